// round 2
// baseline (speedup 1.0000x reference)
#include <cuda_runtime.h>
#include <math.h>

#define BB 8
#define NN 1024
#define DIM 768
#define HEADS 8
#define HD 96
#define HIDDEN 1500
#define ROWS (BB * NN)   // 8192
#define QKVC (3 * DIM)   // 2304

// ---------------- scratch (device globals; no allocs allowed) ----------------
__device__ float g_y[ROWS * DIM];            // LN1 output
__device__ float g_qkv[ROWS * QKVC];         // QKV gemm output
__device__ float g_scores[(size_t)BB * HEADS * NN * NN]; // 256 MB
__device__ float g_att[ROWS * DIM];          // attention output (B,N,H*hd)
__device__ float g_z[ROWS * DIM];            // residual 1
__device__ float g_ln2[ROWS * DIM];          // LN2 output
__device__ float g_h[ROWS * HIDDEN];         // MLP hidden

// ---------------- LayerNorm: one block (256 thr) per row of 768 --------------
__global__ void ln_kernel(const float* __restrict__ in,
                          const float* __restrict__ gamma,
                          const float* __restrict__ beta,
                          float* __restrict__ out) {
    int row = blockIdx.x;
    int t = threadIdx.x;
    const float* px = in + (size_t)row * DIM;
    float v0 = px[t], v1 = px[t + 256], v2 = px[t + 512];
    float s = v0 + v1 + v2;
    float sq = v0 * v0 + v1 * v1 + v2 * v2;

    __shared__ float red0[8], red1[8];
    #pragma unroll
    for (int o = 16; o; o >>= 1) {
        s  += __shfl_xor_sync(0xffffffffu, s, o);
        sq += __shfl_xor_sync(0xffffffffu, sq, o);
    }
    if ((t & 31) == 0) { red0[t >> 5] = s; red1[t >> 5] = sq; }
    __syncthreads();
    if (t < 32) {
        s  = (t < 8) ? red0[t] : 0.f;
        sq = (t < 8) ? red1[t] : 0.f;
        #pragma unroll
        for (int o = 4; o; o >>= 1) {
            s  += __shfl_xor_sync(0xffffffffu, s, o);
            sq += __shfl_xor_sync(0xffffffffu, sq, o);
        }
        if (t == 0) { red0[0] = s; red1[0] = sq; }
    }
    __syncthreads();
    float mean = red0[0] * (1.f / DIM);
    float var  = red1[0] * (1.f / DIM) - mean * mean;
    float rstd = rsqrtf(var + 1e-5f);
    float* po = out + (size_t)row * DIM;
    po[t]       = (v0 - mean) * rstd * gamma[t]       + beta[t];
    po[t + 256] = (v1 - mean) * rstd * gamma[t + 256] + beta[t + 256];
    po[t + 512] = (v2 - mean) * rstd * gamma[t + 512] + beta[t + 512];
}

// ---------------- SGEMM: C = A[MxK] @ B[KxN] + bias (+gelu) (+res) -----------
// 128x128 tile, BK=8, 256 threads, 8x8 per thread.
__global__ __launch_bounds__(256, 2)
void sgemm_kernel(const float* __restrict__ A, const float* __restrict__ Bm,
                  const float* __restrict__ bias, const float* __restrict__ res,
                  float* __restrict__ C, int M, int Nc, int K, int act) {
    __shared__ float As[8][128];
    __shared__ float Bs[8][128];
    int tid = threadIdx.x;
    int row0 = blockIdx.y * 128, col0 = blockIdx.x * 128;
    int aRow = tid >> 1, aK = (tid & 1) * 4;
    int bK = tid >> 5, bC = (tid & 31) * 4;
    int tx = tid & 15, ty = tid >> 4;

    float acc[8][8];
    #pragma unroll
    for (int i = 0; i < 8; i++)
        #pragma unroll
        for (int j = 0; j < 8; j++) acc[i][j] = 0.f;

    for (int k0 = 0; k0 < K; k0 += 8) {
        // A tile -> transposed into As[k][m]
        float4 va;
        const float* pa = A + (size_t)(row0 + aRow) * K + k0 + aK;
        if (k0 + aK + 3 < K) {
            va = *(const float4*)pa;
        } else {
            va.x = (k0 + aK + 0 < K) ? pa[0] : 0.f;
            va.y = (k0 + aK + 1 < K) ? pa[1] : 0.f;
            va.z = (k0 + aK + 2 < K) ? pa[2] : 0.f;
            va.w = (k0 + aK + 3 < K) ? pa[3] : 0.f;
        }
        As[aK + 0][aRow] = va.x; As[aK + 1][aRow] = va.y;
        As[aK + 2][aRow] = va.z; As[aK + 3][aRow] = va.w;

        // B tile
        float4 vb = make_float4(0.f, 0.f, 0.f, 0.f);
        if (k0 + bK < K) {
            const float* pb = Bm + (size_t)(k0 + bK) * Nc + col0 + bC;
            if (col0 + bC + 3 < Nc) {
                vb = *(const float4*)pb;
            } else {
                if (col0 + bC + 0 < Nc) vb.x = pb[0];
                if (col0 + bC + 1 < Nc) vb.y = pb[1];
                if (col0 + bC + 2 < Nc) vb.z = pb[2];
                if (col0 + bC + 3 < Nc) vb.w = pb[3];
            }
        }
        *(float4*)&Bs[bK][bC] = vb;
        __syncthreads();

        #pragma unroll
        for (int kk = 0; kk < 8; kk++) {
            float4 a0 = *(const float4*)&As[kk][ty * 8];
            float4 a1 = *(const float4*)&As[kk][ty * 8 + 4];
            float4 b0 = *(const float4*)&Bs[kk][tx * 8];
            float4 b1 = *(const float4*)&Bs[kk][tx * 8 + 4];
            float ar[8] = {a0.x, a0.y, a0.z, a0.w, a1.x, a1.y, a1.z, a1.w};
            float br[8] = {b0.x, b0.y, b0.z, b0.w, b1.x, b1.y, b1.z, b1.w};
            #pragma unroll
            for (int i = 0; i < 8; i++)
                #pragma unroll
                for (int j = 0; j < 8; j++)
                    acc[i][j] = fmaf(ar[i], br[j], acc[i][j]);
        }
        __syncthreads();
    }

    #pragma unroll
    for (int i = 0; i < 8; i++) {
        int r = row0 + ty * 8 + i;
        #pragma unroll
        for (int j = 0; j < 8; j++) {
            int c = col0 + tx * 8 + j;
            if (c < Nc) {
                float v = acc[i][j] + bias[c];
                if (act == 1) v = 0.5f * v * (1.f + erff(v * 0.70710678118654752f));
                if (res) v += res[(size_t)r * Nc + c];
                C[(size_t)r * Nc + c] = v;
            }
        }
    }
}

// ---------------- Attention scores: S = Q K^T * sqrt(96) ---------------------
// grid (ktile=16, qtile=16, bh=64), 64x64 tile, d chunked 2x48.
__global__ __launch_bounds__(256, 2)
void attn_scores_kernel(const float* __restrict__ qkv, float* __restrict__ scores) {
    __shared__ float Qs[64][48];
    __shared__ float Ks[64][49];
    int bh = blockIdx.z;
    int b = bh >> 3, h = bh & 7;
    int q0 = blockIdx.y * 64, k0 = blockIdx.x * 64;
    int tid = threadIdx.x, tx = tid & 15, ty = tid >> 4;

    float acc[4][4];
    #pragma unroll
    for (int i = 0; i < 4; i++)
        #pragma unroll
        for (int j = 0; j < 4; j++) acc[i][j] = 0.f;

    const size_t base = (size_t)b * NN * QKVC + (size_t)h * HD;
    #pragma unroll
    for (int ch = 0; ch < 2; ch++) {
        int dof = ch * 48;
        for (int idx = tid; idx < 64 * 48; idx += 256) {
            int r = idx / 48, d = idx % 48;
            Qs[r][d] = qkv[base + (size_t)(q0 + r) * QKVC + dof + d];
            Ks[r][d] = qkv[base + 768 + (size_t)(k0 + r) * QKVC + dof + d];
        }
        __syncthreads();
        #pragma unroll 4
        for (int d = 0; d < 48; d++) {
            float qv[4], kv[4];
            #pragma unroll
            for (int i = 0; i < 4; i++) qv[i] = Qs[ty * 4 + i][d];
            #pragma unroll
            for (int j = 0; j < 4; j++) kv[j] = Ks[tx * 4 + j][d];
            #pragma unroll
            for (int i = 0; i < 4; i++)
                #pragma unroll
                for (int j = 0; j < 4; j++)
                    acc[i][j] = fmaf(qv[i], kv[j], acc[i][j]);
        }
        __syncthreads();
    }
    const float scale = 9.7979589711327124f;  // sqrt(96)
    size_t sbase = (size_t)bh * NN * NN;
    #pragma unroll
    for (int i = 0; i < 4; i++)
        #pragma unroll
        for (int j = 0; j < 4; j++)
            scores[sbase + (size_t)(q0 + ty * 4 + i) * NN + k0 + tx * 4 + j] =
                acc[i][j] * scale;
}

// ---------------- Row softmax over 1024 (in place) ---------------------------
__global__ void softmax_kernel(float* __restrict__ s) {
    size_t row = blockIdx.x;
    float* p = s + row * NN;
    int t = threadIdx.x;
    float4 v = *(float4*)(p + t * 4);
    __shared__ float red[8];

    float m = fmaxf(fmaxf(v.x, v.y), fmaxf(v.z, v.w));
    #pragma unroll
    for (int o = 16; o; o >>= 1) m = fmaxf(m, __shfl_xor_sync(0xffffffffu, m, o));
    if ((t & 31) == 0) red[t >> 5] = m;
    __syncthreads();
    m = red[0];
    #pragma unroll
    for (int w = 1; w < 8; w++) m = fmaxf(m, red[w]);

    v.x = expf(v.x - m); v.y = expf(v.y - m);
    v.z = expf(v.z - m); v.w = expf(v.w - m);
    float s4 = v.x + v.y + v.z + v.w;
    #pragma unroll
    for (int o = 16; o; o >>= 1) s4 += __shfl_xor_sync(0xffffffffu, s4, o);
    __syncthreads();
    if ((t & 31) == 0) red[t >> 5] = s4;
    __syncthreads();
    float tot = 0.f;
    #pragma unroll
    for (int w = 0; w < 8; w++) tot += red[w];
    float inv = 1.f / tot;
    v.x *= inv; v.y *= inv; v.z *= inv; v.w *= inv;
    *(float4*)(p + t * 4) = v;
}

// ---------------- O = P @ V,  write to (b,n,h*hd+d) layout -------------------
// grid (qtile=16, bh=64); block computes 64 rows x 96 cols.
__global__ __launch_bounds__(256, 2)
void attn_v_kernel(const float* __restrict__ qkv, const float* __restrict__ scores,
                   float* __restrict__ out) {
    __shared__ float Ps[64][65];
    __shared__ float Vs[64][96];
    int bh = blockIdx.y;
    int b = bh >> 3, h = bh & 7;
    int q0 = blockIdx.x * 64;
    int tid = threadIdx.x, tx = tid & 15, ty = tid >> 4;

    float acc[4][6];
    #pragma unroll
    for (int i = 0; i < 4; i++)
        #pragma unroll
        for (int j = 0; j < 6; j++) acc[i][j] = 0.f;

    size_t sbase = (size_t)bh * NN * NN;
    size_t vbase = (size_t)b * NN * QKVC + 1536 + (size_t)h * HD;

    for (int kc = 0; kc < NN; kc += 64) {
        for (int idx = tid; idx < 64 * 64; idx += 256) {
            int r = idx >> 6, c = idx & 63;
            Ps[r][c] = scores[sbase + (size_t)(q0 + r) * NN + kc + c];
        }
        for (int idx = tid; idx < 64 * 96; idx += 256) {
            int r = idx / 96, d = idx % 96;
            Vs[r][d] = qkv[vbase + (size_t)(kc + r) * QKVC + d];
        }
        __syncthreads();
        #pragma unroll 4
        for (int kk = 0; kk < 64; kk++) {
            float pr[4], vv[6];
            #pragma unroll
            for (int i = 0; i < 4; i++) pr[i] = Ps[ty * 4 + i][kk];
            #pragma unroll
            for (int j = 0; j < 6; j++) vv[j] = Vs[kk][tx * 6 + j];
            #pragma unroll
            for (int i = 0; i < 4; i++)
                #pragma unroll
                for (int j = 0; j < 6; j++)
                    acc[i][j] = fmaf(pr[i], vv[j], acc[i][j]);
        }
        __syncthreads();
    }
    #pragma unroll
    for (int i = 0; i < 4; i++)
        #pragma unroll
        for (int j = 0; j < 6; j++)
            out[(size_t)(b * NN + q0 + ty * 4 + i) * DIM + h * HD + tx * 6 + j] =
                acc[i][j];
}

// ---------------- launch -----------------------------------------------------
extern "C" void kernel_launch(void* const* d_in, const int* in_sizes, int n_in,
                              void* d_out, int out_size) {
    const float* x    = (const float*)d_in[0];
    const float* ln_g = (const float*)d_in[1];
    const float* ln_b = (const float*)d_in[2];
    const float* Wqkv = (const float*)d_in[3];
    const float* bqkv = (const float*)d_in[4];
    const float* W0   = (const float*)d_in[5];
    const float* b0   = (const float*)d_in[6];
    const float* W1   = (const float*)d_in[7];
    const float* b1   = (const float*)d_in[8];
    const float* W2   = (const float*)d_in[9];
    const float* b2   = (const float*)d_in[10];
    float* out = (float*)d_out;

    float *y, *qkv, *scores, *att, *z, *ln2, *hbuf;
    cudaGetSymbolAddress((void**)&y, g_y);
    cudaGetSymbolAddress((void**)&qkv, g_qkv);
    cudaGetSymbolAddress((void**)&scores, g_scores);
    cudaGetSymbolAddress((void**)&att, g_att);
    cudaGetSymbolAddress((void**)&z, g_z);
    cudaGetSymbolAddress((void**)&ln2, g_ln2);
    cudaGetSymbolAddress((void**)&hbuf, g_h);

    // 1. y = LN(x)
    ln_kernel<<<ROWS, 256>>>(x, ln_g, ln_b, y);
    // 2. qkv = y @ Wqkv + bqkv
    sgemm_kernel<<<dim3(QKVC / 128, ROWS / 128), 256>>>(
        y, Wqkv, bqkv, nullptr, qkv, ROWS, QKVC, DIM, 0);
    // 3. S = Q K^T * sqrt(96)
    attn_scores_kernel<<<dim3(16, 16, BB * HEADS), 256>>>(qkv, scores);
    // 4. softmax rows
    softmax_kernel<<<BB * HEADS * NN, 256>>>(scores);
    // 5. O = P V  (written back to (b,n,c) layout)
    attn_v_kernel<<<dim3(16, BB * HEADS), 256>>>(qkv, scores, att);
    // 6. z = att @ W0 + b0 + x
    sgemm_kernel<<<dim3(DIM / 128, ROWS / 128), 256>>>(
        att, W0, b0, x, z, ROWS, DIM, DIM, 0);
    // 7. ln2 = LN(z)
    ln_kernel<<<ROWS, 256>>>(z, ln_g, ln_b, ln2);
    // 8. h = gelu(ln2 @ W1 + b1)
    sgemm_kernel<<<dim3((HIDDEN + 127) / 128, ROWS / 128), 256>>>(
        ln2, W1, b1, nullptr, hbuf, ROWS, HIDDEN, DIM, 1);
    // 9. out = h @ W2 + b2 + z
    sgemm_kernel<<<dim3(DIM / 128, ROWS / 128), 256>>>(
        hbuf, W2, b2, z, out, ROWS, DIM, HIDDEN, 0);
}

// round 3
// speedup vs baseline: 1.0454x; 1.0454x over previous
#include <cuda_runtime.h>
#include <math.h>

#define BB 8
#define NN 1024
#define DIM 768
#define HEADS 8
#define HD 96
#define HIDDEN 1500
#define ROWS (BB * NN)   // 8192
#define QKVC (3 * DIM)   // 2304

// ---------------- scratch (device globals; no allocs allowed) ----------------
__device__ float g_y[ROWS * DIM];            // LN1 output
__device__ float g_qkv[ROWS * QKVC];         // QKV gemm output
__device__ float g_scores[(size_t)BB * HEADS * NN * NN]; // 256 MB
__device__ float g_att[ROWS * DIM];          // attention output (B,N,H*hd)
__device__ float g_z[ROWS * DIM];            // residual 1
__device__ float g_ln2[ROWS * DIM];          // LN2 output
__device__ float g_h[ROWS * HIDDEN];         // MLP hidden

// ---------------- LayerNorm: one block (256 thr) per row of 768 --------------
__global__ void ln_kernel(const float* __restrict__ in,
                          const float* __restrict__ gamma,
                          const float* __restrict__ beta,
                          float* __restrict__ out) {
    int row = blockIdx.x;
    int t = threadIdx.x;
    const float* px = in + (size_t)row * DIM;
    float v0 = px[t], v1 = px[t + 256], v2 = px[t + 512];
    float s = v0 + v1 + v2;
    float sq = v0 * v0 + v1 * v1 + v2 * v2;

    __shared__ float red0[8], red1[8];
    #pragma unroll
    for (int o = 16; o; o >>= 1) {
        s  += __shfl_xor_sync(0xffffffffu, s, o);
        sq += __shfl_xor_sync(0xffffffffu, sq, o);
    }
    if ((t & 31) == 0) { red0[t >> 5] = s; red1[t >> 5] = sq; }
    __syncthreads();
    if (t < 32) {
        s  = (t < 8) ? red0[t] : 0.f;
        sq = (t < 8) ? red1[t] : 0.f;
        #pragma unroll
        for (int o = 4; o; o >>= 1) {
            s  += __shfl_xor_sync(0xffffffffu, s, o);
            sq += __shfl_xor_sync(0xffffffffu, sq, o);
        }
        if (t == 0) { red0[0] = s; red1[0] = sq; }
    }
    __syncthreads();
    float mean = red0[0] * (1.f / DIM);
    float var  = red1[0] * (1.f / DIM) - mean * mean;
    float rstd = rsqrtf(var + 1e-5f);
    float* po = out + (size_t)row * DIM;
    po[t]       = (v0 - mean) * rstd * gamma[t]       + beta[t];
    po[t + 256] = (v1 - mean) * rstd * gamma[t + 256] + beta[t + 256];
    po[t + 512] = (v2 - mean) * rstd * gamma[t + 512] + beta[t + 512];
}

// ---------------- SGEMM: C = A[MxK] @ B[KxN] + bias (+gelu) (+res) -----------
// 128x128 tile, BK=8, 256 threads, 8x8 per thread.
__global__ __launch_bounds__(256, 2)
void sgemm_kernel(const float* __restrict__ A, const float* __restrict__ Bm,
                  const float* __restrict__ bias, const float* __restrict__ res,
                  float* __restrict__ C, int M, int Nc, int K, int act) {
    __shared__ float As[8][128];
    __shared__ float Bs[8][128];
    int tid = threadIdx.x;
    int row0 = blockIdx.y * 128, col0 = blockIdx.x * 128;
    int aRow = tid >> 1, aK = (tid & 1) * 4;
    int bK = tid >> 5, bC = (tid & 31) * 4;
    int tx = tid & 15, ty = tid >> 4;

    float acc[8][8];
    #pragma unroll
    for (int i = 0; i < 8; i++)
        #pragma unroll
        for (int j = 0; j < 8; j++) acc[i][j] = 0.f;

    for (int k0 = 0; k0 < K; k0 += 8) {
        // A tile -> transposed into As[k][m]
        float4 va;
        const float* pa = A + (size_t)(row0 + aRow) * K + k0 + aK;
        if (k0 + aK + 3 < K) {
            va = *(const float4*)pa;
        } else {
            va.x = (k0 + aK + 0 < K) ? pa[0] : 0.f;
            va.y = (k0 + aK + 1 < K) ? pa[1] : 0.f;
            va.z = (k0 + aK + 2 < K) ? pa[2] : 0.f;
            va.w = (k0 + aK + 3 < K) ? pa[3] : 0.f;
        }
        As[aK + 0][aRow] = va.x; As[aK + 1][aRow] = va.y;
        As[aK + 2][aRow] = va.z; As[aK + 3][aRow] = va.w;

        // B tile
        float4 vb = make_float4(0.f, 0.f, 0.f, 0.f);
        if (k0 + bK < K) {
            const float* pb = Bm + (size_t)(k0 + bK) * Nc + col0 + bC;
            if (col0 + bC + 3 < Nc) {
                vb = *(const float4*)pb;
            } else {
                if (col0 + bC + 0 < Nc) vb.x = pb[0];
                if (col0 + bC + 1 < Nc) vb.y = pb[1];
                if (col0 + bC + 2 < Nc) vb.z = pb[2];
                if (col0 + bC + 3 < Nc) vb.w = pb[3];
            }
        }
        *(float4*)&Bs[bK][bC] = vb;
        __syncthreads();

        #pragma unroll
        for (int kk = 0; kk < 8; kk++) {
            float4 a0 = *(const float4*)&As[kk][ty * 8];
            float4 a1 = *(const float4*)&As[kk][ty * 8 + 4];
            float4 b0 = *(const float4*)&Bs[kk][tx * 8];
            float4 b1 = *(const float4*)&Bs[kk][tx * 8 + 4];
            float ar[8] = {a0.x, a0.y, a0.z, a0.w, a1.x, a1.y, a1.z, a1.w};
            float br[8] = {b0.x, b0.y, b0.z, b0.w, b1.x, b1.y, b1.z, b1.w};
            #pragma unroll
            for (int i = 0; i < 8; i++)
                #pragma unroll
                for (int j = 0; j < 8; j++)
                    acc[i][j] = fmaf(ar[i], br[j], acc[i][j]);
        }
        __syncthreads();
    }

    #pragma unroll
    for (int i = 0; i < 8; i++) {
        int r = row0 + ty * 8 + i;
        #pragma unroll
        for (int j = 0; j < 8; j++) {
            int c = col0 + tx * 8 + j;
            if (c < Nc) {
                float v = acc[i][j] + bias[c];
                if (act == 1) v = 0.5f * v * (1.f + erff(v * 0.70710678118654752f));
                if (res) v += res[(size_t)r * Nc + c];
                C[(size_t)r * Nc + c] = v;
            }
        }
    }
}

// ---------------- Attention scores: S = Q K^T * sqrt(96) ---------------------
// grid (ktile=16, qtile=16, bh=64), 64x64 tile, d chunked 2x48.
__global__ __launch_bounds__(256, 2)
void attn_scores_kernel(const float* __restrict__ qkv, float* __restrict__ scores) {
    __shared__ float Qs[64][48];
    __shared__ float Ks[64][49];
    int bh = blockIdx.z;
    int b = bh >> 3, h = bh & 7;
    int q0 = blockIdx.y * 64, k0 = blockIdx.x * 64;
    int tid = threadIdx.x, tx = tid & 15, ty = tid >> 4;

    float acc[4][4];
    #pragma unroll
    for (int i = 0; i < 4; i++)
        #pragma unroll
        for (int j = 0; j < 4; j++) acc[i][j] = 0.f;

    const size_t base = (size_t)b * NN * QKVC + (size_t)h * HD;
    #pragma unroll
    for (int ch = 0; ch < 2; ch++) {
        int dof = ch * 48;
        for (int idx = tid; idx < 64 * 48; idx += 256) {
            int r = idx / 48, d = idx % 48;
            Qs[r][d] = qkv[base + (size_t)(q0 + r) * QKVC + dof + d];
            Ks[r][d] = qkv[base + 768 + (size_t)(k0 + r) * QKVC + dof + d];
        }
        __syncthreads();
        #pragma unroll 4
        for (int d = 0; d < 48; d++) {
            float qv[4], kv[4];
            #pragma unroll
            for (int i = 0; i < 4; i++) qv[i] = Qs[ty * 4 + i][d];
            #pragma unroll
            for (int j = 0; j < 4; j++) kv[j] = Ks[tx * 4 + j][d];
            #pragma unroll
            for (int i = 0; i < 4; i++)
                #pragma unroll
                for (int j = 0; j < 4; j++)
                    acc[i][j] = fmaf(qv[i], kv[j], acc[i][j]);
        }
        __syncthreads();
    }
    const float scale = 9.7979589711327124f;  // sqrt(96)
    size_t sbase = (size_t)bh * NN * NN;
    #pragma unroll
    for (int i = 0; i < 4; i++)
        #pragma unroll
        for (int j = 0; j < 4; j++)
            scores[sbase + (size_t)(q0 + ty * 4 + i) * NN + k0 + tx * 4 + j] =
                acc[i][j] * scale;
}

// ---------------- Row softmax over 1024 (in place) ---------------------------
__global__ void softmax_kernel(float* __restrict__ s) {
    size_t row = blockIdx.x;
    float* p = s + row * NN;
    int t = threadIdx.x;
    float4 v = *(float4*)(p + t * 4);
    __shared__ float red[8];

    float m = fmaxf(fmaxf(v.x, v.y), fmaxf(v.z, v.w));
    #pragma unroll
    for (int o = 16; o; o >>= 1) m = fmaxf(m, __shfl_xor_sync(0xffffffffu, m, o));
    if ((t & 31) == 0) red[t >> 5] = m;
    __syncthreads();
    m = red[0];
    #pragma unroll
    for (int w = 1; w < 8; w++) m = fmaxf(m, red[w]);

    v.x = expf(v.x - m); v.y = expf(v.y - m);
    v.z = expf(v.z - m); v.w = expf(v.w - m);
    float s4 = v.x + v.y + v.z + v.w;
    #pragma unroll
    for (int o = 16; o; o >>= 1) s4 += __shfl_xor_sync(0xffffffffu, s4, o);
    __syncthreads();
    if ((t & 31) == 0) red[t >> 5] = s4;
    __syncthreads();
    float tot = 0.f;
    #pragma unroll
    for (int w = 0; w < 8; w++) tot += red[w];
    float inv = 1.f / tot;
    v.x *= inv; v.y *= inv; v.z *= inv; v.w *= inv;
    *(float4*)(p + t * 4) = v;
}

// ---------------- O = P @ V,  write to (b,n,h*hd+d) layout -------------------
// grid (qtile=16, bh=64); block computes 64 rows x 96 cols.
__global__ __launch_bounds__(256, 2)
void attn_v_kernel(const float* __restrict__ qkv, const float* __restrict__ scores,
                   float* __restrict__ out) {
    __shared__ float Ps[64][65];
    __shared__ float Vs[64][96];
    int bh = blockIdx.y;
    int b = bh >> 3, h = bh & 7;
    int q0 = blockIdx.x * 64;
    int tid = threadIdx.x, tx = tid & 15, ty = tid >> 4;

    float acc[4][6];
    #pragma unroll
    for (int i = 0; i < 4; i++)
        #pragma unroll
        for (int j = 0; j < 6; j++) acc[i][j] = 0.f;

    size_t sbase = (size_t)bh * NN * NN;
    size_t vbase = (size_t)b * NN * QKVC + 1536 + (size_t)h * HD;

    for (int kc = 0; kc < NN; kc += 64) {
        for (int idx = tid; idx < 64 * 64; idx += 256) {
            int r = idx >> 6, c = idx & 63;
            Ps[r][c] = scores[sbase + (size_t)(q0 + r) * NN + kc + c];
        }
        for (int idx = tid; idx < 64 * 96; idx += 256) {
            int r = idx / 96, d = idx % 96;
            Vs[r][d] = qkv[vbase + (size_t)(kc + r) * QKVC + d];
        }
        __syncthreads();
        #pragma unroll 4
        for (int kk = 0; kk < 64; kk++) {
            float pr[4], vv[6];
            #pragma unroll
            for (int i = 0; i < 4; i++) pr[i] = Ps[ty * 4 + i][kk];
            #pragma unroll
            for (int j = 0; j < 6; j++) vv[j] = Vs[kk][tx * 6 + j];
            #pragma unroll
            for (int i = 0; i < 4; i++)
                #pragma unroll
                for (int j = 0; j < 6; j++)
                    acc[i][j] = fmaf(pr[i], vv[j], acc[i][j]);
        }
        __syncthreads();
    }
    #pragma unroll
    for (int i = 0; i < 4; i++)
        #pragma unroll
        for (int j = 0; j < 6; j++)
            out[(size_t)(b * NN + q0 + ty * 4 + i) * DIM + h * HD + tx * 6 + j] =
                acc[i][j];
}

// ---------------- launch -----------------------------------------------------
extern "C" void kernel_launch(void* const* d_in, const int* in_sizes, int n_in,
                              void* d_out, int out_size) {
    const float* x    = (const float*)d_in[0];
    const float* ln_g = (const float*)d_in[1];
    const float* ln_b = (const float*)d_in[2];
    const float* Wqkv = (const float*)d_in[3];
    const float* bqkv = (const float*)d_in[4];
    const float* W0   = (const float*)d_in[5];
    const float* b0   = (const float*)d_in[6];
    const float* W1   = (const float*)d_in[7];
    const float* b1   = (const float*)d_in[8];
    const float* W2   = (const float*)d_in[9];
    const float* b2   = (const float*)d_in[10];
    float* out = (float*)d_out;

    float *y, *qkv, *scores, *att, *z, *ln2, *hbuf;
    cudaGetSymbolAddress((void**)&y, g_y);
    cudaGetSymbolAddress((void**)&qkv, g_qkv);
    cudaGetSymbolAddress((void**)&scores, g_scores);
    cudaGetSymbolAddress((void**)&att, g_att);
    cudaGetSymbolAddress((void**)&z, g_z);
    cudaGetSymbolAddress((void**)&ln2, g_ln2);
    cudaGetSymbolAddress((void**)&hbuf, g_h);

    // 1. y = LN(x)
    ln_kernel<<<ROWS, 256>>>(x, ln_g, ln_b, y);
    // 2. qkv = y @ Wqkv + bqkv
    sgemm_kernel<<<dim3(QKVC / 128, ROWS / 128), 256>>>(
        y, Wqkv, bqkv, nullptr, qkv, ROWS, QKVC, DIM, 0);
    // 3. S = Q K^T * sqrt(96)
    attn_scores_kernel<<<dim3(16, 16, BB * HEADS), 256>>>(qkv, scores);
    // 4. softmax rows
    softmax_kernel<<<BB * HEADS * NN, 256>>>(scores);
    // 5. O = P V  (written back to (b,n,c) layout)
    attn_v_kernel<<<dim3(16, BB * HEADS), 256>>>(qkv, scores, att);
    // 6. z = att @ W0 + b0 + x
    sgemm_kernel<<<dim3(DIM / 128, ROWS / 128), 256>>>(
        att, W0, b0, x, z, ROWS, DIM, DIM, 0);
    // 7. ln2 = LN(z)
    ln_kernel<<<ROWS, 256>>>(z, ln_g, ln_b, ln2);
    // 8. h = gelu(ln2 @ W1 + b1)
    sgemm_kernel<<<dim3((HIDDEN + 127) / 128, ROWS / 128), 256>>>(
        ln2, W1, b1, nullptr, hbuf, ROWS, HIDDEN, DIM, 1);
    // 9. out = h @ W2 + b2 + z
    sgemm_kernel<<<dim3(DIM / 128, ROWS / 128), 256>>>(
        hbuf, W2, b2, z, out, ROWS, DIM, HIDDEN, 0);
}

// round 6
// speedup vs baseline: 2.4047x; 2.3002x over previous
#include <cuda_runtime.h>
#include <cuda_fp16.h>
#include <math.h>
#include <stdint.h>

#define BB 8
#define NN 1024
#define DIM 768
#define HEADS 8
#define HD 96
#define HIDDEN 1500
#define HPAD 1504
#define ROWS (BB * NN)
#define QKVC (3 * DIM)
#define PAD 64

__device__ __forceinline__ uint32_t smem_u32(const void* p) {
    uint32_t r;
    asm("{ .reg .u64 t; cvta.to.shared.u64 t, %1; cvt.u32.u64 %0, t; }" : "=r"(r) : "l"(p));
    return r;
}
#define CPA(dst, src, p) asm volatile("cp.async.cg.shared.global [%0], [%1], 16, %2;" :: "r"(dst), "l"(src), "r"(p) : "memory")
#define CPCOMMIT() asm volatile("cp.async.commit_group;" ::: "memory")
#define CPWAIT1() asm volatile("cp.async.wait_group 1;" ::: "memory")
#define CPWAIT0() asm volatile("cp.async.wait_group 0;" ::: "memory")
#define LDSM4(r, a) asm volatile("ldmatrix.sync.aligned.m8n8.x4.shared.b16 {%0,%1,%2,%3}, [%4];" \
    : "=r"((r)[0]), "=r"((r)[1]), "=r"((r)[2]), "=r"((r)[3]) : "r"(a))
#define LDSM4T(r, a) asm volatile("ldmatrix.sync.aligned.m8n8.x4.trans.shared.b16 {%0,%1,%2,%3}, [%4];" \
    : "=r"((r)[0]), "=r"((r)[1]), "=r"((r)[2]), "=r"((r)[3]) : "r"(a))
#define MMA(c, a, b0, b1) asm volatile( \
    "mma.sync.aligned.m16n8k16.row.col.f32.f16.f16.f32 {%0,%1,%2,%3}, {%4,%5,%6,%7}, {%8,%9}, {%0,%1,%2,%3};" \
    : "+f"((c)[0]), "+f"((c)[1]), "+f"((c)[2]), "+f"((c)[3]) \
    : "r"((a)[0]), "r"((a)[1]), "r"((a)[2]), "r"((a)[3]), "r"(b0), "r"(b1))

// ------------------------------ scratch -------------------------------------
__device__ __half g_yh[ROWS * DIM + PAD], g_yl[ROWS * DIM + PAD];
__device__ __half g_wqh[DIM * QKVC + PAD], g_wql[DIM * QKVC + PAD];
__device__ __half g_qkvh[ROWS * QKVC + PAD], g_qkvl[ROWS * QKVC + PAD];
__device__ float  g_scoresF[(size_t)BB * HEADS * NN * NN + PAD];
__device__ __half g_p[(size_t)BB * HEADS * NN * NN + PAD];
__device__ __half g_att[ROWS * DIM + PAD];
__device__ float  g_z[ROWS * DIM + PAD];
__device__ __half g_l2[ROWS * DIM + PAD];
__device__ __half g_w0[DIM * DIM + PAD];
__device__ __half g_w1[DIM * HPAD + PAD];
__device__ __half g_w2[HPAD * DIM + PAD];
__device__ __half g_h[ROWS * HPAD + PAD];

// fp32 -> fp16 hi (+ optional lo), zero-padded to [outTotal] with ld=ldo
__global__ void split_kernel(const float* __restrict__ in, __half* __restrict__ hi,
                             __half* __restrict__ lo, int inRows, int inCols,
                             int ldo, int total) {
    int i = blockIdx.x * 256 + threadIdx.x;
    if (i >= total) return;
    int r = i / ldo, c = i - r * ldo;
    float v = (r < inRows && c < inCols) ? in[(size_t)r * inCols + c] : 0.f;
    __half h = __float2half_rn(v);
    hi[i] = h;
    if (lo) lo[i] = __float2half_rn(v - __half2float(h));
}

__global__ void ln_split_kernel(const float* __restrict__ in,
                                const float* __restrict__ gamma,
                                const float* __restrict__ beta,
                                __half* __restrict__ oh, __half* __restrict__ ol) {
    int row = blockIdx.x, t = threadIdx.x;
    const float* px = in + (size_t)row * DIM;
    float v0 = px[t], v1 = px[t + 256], v2 = px[t + 512];
    float s = v0 + v1 + v2, sq = v0 * v0 + v1 * v1 + v2 * v2;
    __shared__ float red0[8], red1[8];
    #pragma unroll
    for (int o = 16; o; o >>= 1) {
        s += __shfl_xor_sync(~0u, s, o);
        sq += __shfl_xor_sync(~0u, sq, o);
    }
    if ((t & 31) == 0) { red0[t >> 5] = s; red1[t >> 5] = sq; }
    __syncthreads();
    if (t < 32) {
        s = (t < 8) ? red0[t] : 0.f;
        sq = (t < 8) ? red1[t] : 0.f;
        #pragma unroll
        for (int o = 4; o; o >>= 1) {
            s += __shfl_xor_sync(~0u, s, o);
            sq += __shfl_xor_sync(~0u, sq, o);
        }
        if (t == 0) { red0[0] = s; red1[0] = sq; }
    }
    __syncthreads();
    float mean = red0[0] * (1.f / DIM);
    float var = red1[0] * (1.f / DIM) - mean * mean;
    float rstd = rsqrtf(var + 1e-5f);
    size_t base = (size_t)row * DIM;
    float vv[3] = {v0, v1, v2};
    #pragma unroll
    for (int c = 0; c < 3; c++) {
        int i = t + c * 256;
        float v = (vv[c] - mean) * rstd * gamma[i] + beta[i];
        __half h = __float2half_rn(v);
        oh[base + i] = h;
        if (ol) ol[base + i] = __float2half_rn(v - __half2float(h));
    }
}

__global__ void softmax_kernel(const float* __restrict__ s, __half* __restrict__ ph) {
    size_t row = blockIdx.x;
    const float* p = s + row * NN;
    int t = threadIdx.x;
    float4 v = *(const float4*)(p + t * 4);
    __shared__ float red[8];
    float m = fmaxf(fmaxf(v.x, v.y), fmaxf(v.z, v.w));
    #pragma unroll
    for (int o = 16; o; o >>= 1) m = fmaxf(m, __shfl_xor_sync(~0u, m, o));
    if ((t & 31) == 0) red[t >> 5] = m;
    __syncthreads();
    m = red[0];
    #pragma unroll
    for (int w = 1; w < 8; w++) m = fmaxf(m, red[w]);
    v.x = __expf(v.x - m); v.y = __expf(v.y - m);
    v.z = __expf(v.z - m); v.w = __expf(v.w - m);
    float s4 = v.x + v.y + v.z + v.w;
    #pragma unroll
    for (int o = 16; o; o >>= 1) s4 += __shfl_xor_sync(~0u, s4, o);
    __syncthreads();
    if ((t & 31) == 0) red[t >> 5] = s4;
    __syncthreads();
    float tot = 0.f;
    #pragma unroll
    for (int w = 0; w < 8; w++) tot += red[w];
    float inv = 1.f / tot;
    __half2* o = (__half2*)(ph + row * NN + t * 4);
    o[0] = __halves2half2(__float2half_rn(v.x * inv), __float2half_rn(v.y * inv));
    o[1] = __halves2half2(__float2half_rn(v.z * inv), __float2half_rn(v.w * inv));
}

// ---------------- mma.sync GEMM: 128x128 tile, BK=32, double-buffered --------
// A[m][k] (hi/lo if NP3). BD=1: B stored [n][k]; BD=0: B stored [k][n].
// smem halves layout (elems): A hi@0, A lo@5120; B@10240 (+5120 or +4352 lo)
#define STG_BYTES 40960
#define HG_SMEM (2 * STG_BYTES)

template <int NP3, int BD>
__device__ __forceinline__ void load_stage(uint32_t sb, int tid,
    const __half* __restrict__ Ah, const __half* __restrict__ Al,
    long aRowBase, long lda, int k0,
    const __half* __restrict__ Bh, const __half* __restrict__ Bl,
    long bOff, long ldb, int col0, int Nb) {
    #pragma unroll
    for (int half = 0; half < (NP3 ? 2 : 1); half++) {
        const __half* Ab = half ? Al : Ah;
        #pragma unroll
        for (int i = 0; i < 2; i++) {
            int u = tid + i * 256;
            int row = u >> 2, c = u & 3;
            const __half* src = Ab + aRowBase + (long)row * lda + k0 + c * 8;
            CPA(sb + (half * 5120 + row * 40 + c * 8) * 2, src, 16);
        }
    }
    #pragma unroll
    for (int half = 0; half < (NP3 ? 2 : 1); half++) {
        const __half* Bb = half ? Bl : Bh;
        if (BD) {
            #pragma unroll
            for (int i = 0; i < 2; i++) {
                int u = tid + i * 256;
                int row = u >> 2, c = u & 3;
                const __half* src = Bb + bOff + (long)(col0 + row) * ldb + k0 + c * 8;
                CPA(sb + (10240 + half * 5120 + row * 40 + c * 8) * 2, src,
                    (col0 + row) < Nb ? 16 : 0);
            }
        } else {
            #pragma unroll
            for (int i = 0; i < 2; i++) {
                int u = tid + i * 256;
                int k = u >> 4, c = u & 15;
                const __half* src = Bb + bOff + (long)(k0 + k) * ldb + col0 + c * 8;
                CPA(sb + (10240 + half * 4352 + k * 136 + c * 8) * 2, src,
                    (col0 + c * 8 + 8) <= Nb ? 16 : 0);
            }
        }
    }
    CPCOMMIT();
}

template <int NP3, int BD>
__global__ __launch_bounds__(256, 1)
void hgemm(const __half* __restrict__ Ah, const __half* __restrict__ Al,
           long lda, long a1, long a2,
           const __half* __restrict__ Bh, const __half* __restrict__ Bl,
           long ldb, long b1, long b2,
           float* __restrict__ Cf, __half* __restrict__ Chi, __half* __restrict__ Clo,
           long ldc, long c0, long c1, long c2,
           const float* __restrict__ bias, const float* __restrict__ resid,
           int Nb, int nStore, int nBias, int nkb, float scale, int doGelu) {
    extern __shared__ char smem[];
    uint32_t sbase = smem_u32(smem);
    int tid = threadIdx.x, wid = tid >> 5, lane = tid & 31;
    int wm = wid >> 1, wn = wid & 1;
    int z = blockIdx.z;
    long aOff = (long)(z >> 3) * a1 + (long)(z & 7) * a2;
    long bOff = (long)(z >> 3) * b1 + (long)(z & 7) * b2;
    long cOff = (long)z * c0 + (long)(z >> 3) * c1 + (long)(z & 7) * c2;
    int row0 = blockIdx.y * 128, col0 = blockIdx.x * 128;
    long aRowBase = aOff + (long)row0 * lda;

    float acc[2][8][4];
    #pragma unroll
    for (int a = 0; a < 2; a++)
        #pragma unroll
        for (int b = 0; b < 8; b++)
            #pragma unroll
            for (int c = 0; c < 4; c++) acc[a][b][c] = 0.f;

    load_stage<NP3, BD>(sbase, tid, Ah, Al, aRowBase, lda, 0, Bh, Bl, bOff, ldb, col0, Nb);

    for (int kb = 0; kb < nkb; kb++) {
        if (kb + 1 < nkb) {
            load_stage<NP3, BD>(sbase + ((kb + 1) & 1) * STG_BYTES, tid, Ah, Al,
                                aRowBase, lda, (kb + 1) * 32, Bh, Bl, bOff, ldb, col0, Nb);
            CPWAIT1();
        } else {
            CPWAIT0();
        }
        __syncthreads();
        uint32_t sb = sbase + (kb & 1) * STG_BYTES;
        #pragma unroll
        for (int kk = 0; kk < 32; kk += 16) {
            uint32_t ah[2][4], al[2][4];
            #pragma unroll
            for (int mi = 0; mi < 2; mi++) {
                uint32_t ad = sb + (((wm * 32 + mi * 16 + (lane & 15)) * 40 + kk +
                                     (lane >> 4) * 8) << 1);
                LDSM4(ah[mi], ad);
                if (NP3) LDSM4(al[mi], ad + 10240);
            }
            #pragma unroll
            for (int ni = 0; ni < 4; ni++) {
                uint32_t bh[4], bl[4];
                if (BD) {
                    int nrow = wn * 64 + ni * 16 + (lane & 7) + ((lane >> 4) << 3);
                    uint32_t bd = sb + ((10240 + nrow * 40 + kk +
                                         (((lane >> 3) & 1) << 3)) << 1);
                    LDSM4(bh, bd);
                    if (NP3) LDSM4(bl, bd + 10240);
                } else {
                    int kq = kk + (lane & 15);
                    int nq = wn * 64 + ni * 16 + ((lane >> 4) << 3);
                    uint32_t bd = sb + ((10240 + kq * 136 + nq) << 1);
                    LDSM4T(bh, bd);
                    if (NP3) LDSM4T(bl, bd + 8704);
                }
                #pragma unroll
                for (int mi = 0; mi < 2; mi++) {
                    MMA(acc[mi][2 * ni], ah[mi], bh[0], bh[1]);
                    MMA(acc[mi][2 * ni + 1], ah[mi], bh[2], bh[3]);
                    if (NP3) {
                        MMA(acc[mi][2 * ni], al[mi], bh[0], bh[1]);
                        MMA(acc[mi][2 * ni + 1], al[mi], bh[2], bh[3]);
                        MMA(acc[mi][2 * ni], ah[mi], bl[0], bl[1]);
                        MMA(acc[mi][2 * ni + 1], ah[mi], bl[2], bl[3]);
                    }
                }
            }
        }
        __syncthreads();
    }

    int row_base = row0 + wm * 32, col_base = col0 + wn * 64;
    #pragma unroll
    for (int mi = 0; mi < 2; mi++)
        #pragma unroll
        for (int g = 0; g < 8; g++)
            #pragma unroll
            for (int rh = 0; rh < 2; rh++) {
                int row = row_base + mi * 16 + rh * 8 + (lane >> 2);
                int col = col_base + g * 8 + (lane & 3) * 2;
                if (col >= nStore) continue;
                float v0 = acc[mi][g][rh * 2] * scale;
                float v1 = acc[mi][g][rh * 2 + 1] * scale;
                if (bias) {
                    if (col < nBias) v0 += bias[col];
                    if (col + 1 < nBias) v1 += bias[col + 1];
                }
                if (doGelu) {
                    v0 = 0.5f * v0 * (1.f + erff(v0 * 0.70710678118654752f));
                    v1 = 0.5f * v1 * (1.f + erff(v1 * 0.70710678118654752f));
                }
                long cr = cOff + (long)row * ldc + col;
                if (resid) {
                    float2 rr = *(const float2*)(resid + cr);
                    v0 += rr.x; v1 += rr.y;
                }
                if (Cf) {
                    *(float2*)(Cf + cr) = make_float2(v0, v1);
                } else {
                    __half h0 = __float2half_rn(v0), h1 = __float2half_rn(v1);
                    *(__half2*)(Chi + cr) = __halves2half2(h0, h1);
                    if (Clo)
                        *(__half2*)(Clo + cr) = __halves2half2(
                            __float2half_rn(v0 - __half2float(h0)),
                            __float2half_rn(v1 - __half2float(h1)));
                }
            }
}

// ------------------------------- launch --------------------------------------
extern "C" void kernel_launch(void* const* d_in, const int* in_sizes, int n_in,
                              void* d_out, int out_size) {
    const float* x    = (const float*)d_in[0];
    const float* ln_g = (const float*)d_in[1];
    const float* ln_b = (const float*)d_in[2];
    const float* Wqkv = (const float*)d_in[3];
    const float* bqkv = (const float*)d_in[4];
    const float* W0   = (const float*)d_in[5];
    const float* b0   = (const float*)d_in[6];
    const float* W1   = (const float*)d_in[7];
    const float* b1   = (const float*)d_in[8];
    const float* W2   = (const float*)d_in[9];
    const float* b2   = (const float*)d_in[10];
    float* out = (float*)d_out;

    cudaFuncSetAttribute(hgemm<1, 0>, cudaFuncAttributeMaxDynamicSharedMemorySize, HG_SMEM);
    cudaFuncSetAttribute(hgemm<1, 1>, cudaFuncAttributeMaxDynamicSharedMemorySize, HG_SMEM);
    cudaFuncSetAttribute(hgemm<0, 0>, cudaFuncAttributeMaxDynamicSharedMemorySize, HG_SMEM);

    __half *yh, *yl, *wqh, *wql, *qkvh, *qkvl, *pp, *att, *l2, *w0, *w1, *w2, *hb;
    float *scoresF, *z;
    cudaGetSymbolAddress((void**)&yh, g_yh);   cudaGetSymbolAddress((void**)&yl, g_yl);
    cudaGetSymbolAddress((void**)&wqh, g_wqh); cudaGetSymbolAddress((void**)&wql, g_wql);
    cudaGetSymbolAddress((void**)&qkvh, g_qkvh); cudaGetSymbolAddress((void**)&qkvl, g_qkvl);
    cudaGetSymbolAddress((void**)&scoresF, g_scoresF);
    cudaGetSymbolAddress((void**)&pp, g_p);
    cudaGetSymbolAddress((void**)&att, g_att);
    cudaGetSymbolAddress((void**)&z, g_z);
    cudaGetSymbolAddress((void**)&l2, g_l2);
    cudaGetSymbolAddress((void**)&w0, g_w0);
    cudaGetSymbolAddress((void**)&w1, g_w1);
    cudaGetSymbolAddress((void**)&w2, g_w2);
    cudaGetSymbolAddress((void**)&hb, g_h);

    split_kernel<<<(DIM * QKVC + 255) / 256, 256>>>(Wqkv, wqh, wql, DIM, QKVC, QKVC, DIM * QKVC);
    split_kernel<<<(DIM * DIM + 255) / 256, 256>>>(W0, w0, nullptr, DIM, DIM, DIM, DIM * DIM);
    split_kernel<<<(DIM * HPAD + 255) / 256, 256>>>(W1, w1, nullptr, DIM, HIDDEN, HPAD, DIM * HPAD);
    split_kernel<<<(HPAD * DIM + 255) / 256, 256>>>(W2, w2, nullptr, HIDDEN, DIM, DIM, HPAD * DIM);

    const float SQ96 = 9.79795897113271239f;  // 1 / D_QUIRK
    const long BH_A = (long)NN * QKVC;
    const long SC = (long)NN * NN;
    const long OUT_B = (long)NN * DIM;

    ln_split_kernel<<<ROWS, 256>>>(x, ln_g, ln_b, yh, yl);
    // qkv = y @ Wqkv + bqkv   (split output)
    hgemm<1, 0><<<dim3(18, 64, 1), 256, HG_SMEM>>>(
        yh, yl, DIM, 0, 0, wqh, wql, QKVC, 0, 0,
        nullptr, qkvh, qkvl, QKVC, 0, 0, 0,
        bqkv, nullptr, QKVC, QKVC, QKVC, 24, 1.f, 0);
    // scores = (Q K^T) * sqrt(96)
    hgemm<1, 1><<<dim3(8, 8, 64), 256, HG_SMEM>>>(
        qkvh, qkvl, QKVC, BH_A, HD, qkvh + DIM, qkvl + DIM, QKVC, BH_A, HD,
        scoresF, nullptr, nullptr, NN, SC, 0, 0,
        nullptr, nullptr, NN, NN, 0, 3, SQ96, 0);
    softmax_kernel<<<BB * HEADS * NN, 256>>>(scoresF, pp);
    // att = P @ V  (scatter to (b,n,h*hd+d))
    hgemm<0, 0><<<dim3(1, 8, 64), 256, HG_SMEM>>>(
        pp, nullptr, NN, 8 * SC, SC, qkvh + 2 * DIM, nullptr, QKVC, BH_A, HD,
        nullptr, att, nullptr, DIM, 0, OUT_B, HD,
        nullptr, nullptr, HD, HD, 0, 32, 1.f, 0);
    // z = att @ W0 + b0 + x
    hgemm<0, 0><<<dim3(6, 64, 1), 256, HG_SMEM>>>(
        att, nullptr, DIM, 0, 0, w0, nullptr, DIM, 0, 0,
        z, nullptr, nullptr, DIM, 0, 0, 0,
        b0, x, DIM, DIM, DIM, 24, 1.f, 0);
    ln_split_kernel<<<ROWS, 256>>>(z, ln_g, ln_b, l2, nullptr);
    // h = gelu(l2 @ W1 + b1)
    hgemm<0, 0><<<dim3(12, 64, 1), 256, HG_SMEM>>>(
        l2, nullptr, DIM, 0, 0, w1, nullptr, HPAD, 0, 0,
        nullptr, hb, nullptr, HPAD, 0, 0, 0,
        b1, nullptr, HPAD, HPAD, HIDDEN, 24, 1.f, 1);
    // out = h @ W2 + b2 + z
    hgemm<0, 0><<<dim3(6, 64, 1), 256, HG_SMEM>>>(
        hb, nullptr, HPAD, 0, 0, w2, nullptr, DIM, 0, 0,
        out, nullptr, nullptr, DIM, 0, 0, 0,
        b2, z, DIM, DIM, DIM, 47, 1.f, 0);
}

// round 7
// speedup vs baseline: 4.2703x; 1.7758x over previous
#include <cuda_runtime.h>
#include <cuda_fp16.h>
#include <math.h>
#include <stdint.h>

#define BB 8
#define NN 1024
#define DIM 768
#define HEADS 8
#define HD 96
#define HIDDEN 1500
#define HPAD 1504
#define ROWS (BB * NN)
#define QKVC (3 * DIM)
#define PAD 64

__device__ __forceinline__ uint32_t smem_u32(const void* p) {
    uint32_t r;
    asm("{ .reg .u64 t; cvta.to.shared.u64 t, %1; cvt.u32.u64 %0, t; }" : "=r"(r) : "l"(p));
    return r;
}
#define CPA(dst, src, p) asm volatile("cp.async.cg.shared.global [%0], [%1], 16, %2;" :: "r"(dst), "l"(src), "r"(p) : "memory")
#define CPCOMMIT() asm volatile("cp.async.commit_group;" ::: "memory")
#define CPWAIT1() asm volatile("cp.async.wait_group 1;" ::: "memory")
#define CPWAIT0() asm volatile("cp.async.wait_group 0;" ::: "memory")
#define LDSM4(r, a) asm volatile("ldmatrix.sync.aligned.m8n8.x4.shared.b16 {%0,%1,%2,%3}, [%4];" \
    : "=r"((r)[0]), "=r"((r)[1]), "=r"((r)[2]), "=r"((r)[3]) : "r"(a))
#define LDSM4T(r, a) asm volatile("ldmatrix.sync.aligned.m8n8.x4.trans.shared.b16 {%0,%1,%2,%3}, [%4];" \
    : "=r"((r)[0]), "=r"((r)[1]), "=r"((r)[2]), "=r"((r)[3]) : "r"(a))
#define MMA(c, a, b0, b1) asm volatile( \
    "mma.sync.aligned.m16n8k16.row.col.f32.f16.f16.f32 {%0,%1,%2,%3}, {%4,%5,%6,%7}, {%8,%9}, {%0,%1,%2,%3};" \
    : "+f"((c)[0]), "+f"((c)[1]), "+f"((c)[2]), "+f"((c)[3]) \
    : "r"((a)[0]), "r"((a)[1]), "r"((a)[2]), "r"((a)[3]), "r"(b0), "r"(b1))

// ------------------------------ scratch -------------------------------------
__device__ __half g_yh[ROWS * DIM + PAD], g_yl[ROWS * DIM + PAD];
__device__ __half g_wqh[DIM * QKVC + PAD], g_wql[DIM * QKVC + PAD];
__device__ __half g_qkvh[ROWS * QKVC + PAD], g_qkvl[ROWS * QKVC + PAD];
__device__ __half g_att[ROWS * DIM + PAD];
__device__ float  g_z[ROWS * DIM + PAD];
__device__ __half g_l2[ROWS * DIM + PAD];
__device__ __half g_w0[DIM * DIM + PAD];
__device__ __half g_w1[DIM * HPAD + PAD];
__device__ __half g_w2[HPAD * DIM + PAD];
__device__ __half g_h[ROWS * HPAD + PAD];

__global__ void split_kernel(const float* __restrict__ in, __half* __restrict__ hi,
                             __half* __restrict__ lo, int inRows, int inCols,
                             int ldo, int total) {
    int i = blockIdx.x * 256 + threadIdx.x;
    if (i >= total) return;
    int r = i / ldo, c = i - r * ldo;
    float v = (r < inRows && c < inCols) ? in[(size_t)r * inCols + c] : 0.f;
    __half h = __float2half_rn(v);
    hi[i] = h;
    if (lo) lo[i] = __float2half_rn(v - __half2float(h));
}

__global__ void ln_split_kernel(const float* __restrict__ in,
                                const float* __restrict__ gamma,
                                const float* __restrict__ beta,
                                __half* __restrict__ oh, __half* __restrict__ ol) {
    int row = blockIdx.x, t = threadIdx.x;
    const float* px = in + (size_t)row * DIM;
    float v0 = px[t], v1 = px[t + 256], v2 = px[t + 512];
    float s = v0 + v1 + v2, sq = v0 * v0 + v1 * v1 + v2 * v2;
    __shared__ float red0[8], red1[8];
    #pragma unroll
    for (int o = 16; o; o >>= 1) {
        s += __shfl_xor_sync(~0u, s, o);
        sq += __shfl_xor_sync(~0u, sq, o);
    }
    if ((t & 31) == 0) { red0[t >> 5] = s; red1[t >> 5] = sq; }
    __syncthreads();
    if (t < 32) {
        s = (t < 8) ? red0[t] : 0.f;
        sq = (t < 8) ? red1[t] : 0.f;
        #pragma unroll
        for (int o = 4; o; o >>= 1) {
            s += __shfl_xor_sync(~0u, s, o);
            sq += __shfl_xor_sync(~0u, sq, o);
        }
        if (t == 0) { red0[0] = s; red1[0] = sq; }
    }
    __syncthreads();
    float mean = red0[0] * (1.f / DIM);
    float var = red1[0] * (1.f / DIM) - mean * mean;
    float rstd = rsqrtf(var + 1e-5f);
    size_t base = (size_t)row * DIM;
    float vv[3] = {v0, v1, v2};
    #pragma unroll
    for (int c = 0; c < 3; c++) {
        int i = t + c * 256;
        float v = (vv[c] - mean) * rstd * gamma[i] + beta[i];
        __half h = __float2half_rn(v);
        oh[base + i] = h;
        if (ol) ol[base + i] = __float2half_rn(v - __half2float(h));
    }
}

// ---------------- mma.sync GEMM (unchanged core from R6) ---------------------
#define STG_BYTES 40960
#define HG_SMEM (2 * STG_BYTES)

template <int NP3, int BD>
__device__ __forceinline__ void load_stage(uint32_t sb, int tid,
    const __half* __restrict__ Ah, const __half* __restrict__ Al,
    long aRowBase, long lda, int k0,
    const __half* __restrict__ Bh, const __half* __restrict__ Bl,
    long bOff, long ldb, int col0, int Nb) {
    #pragma unroll
    for (int half = 0; half < (NP3 ? 2 : 1); half++) {
        const __half* Ab = half ? Al : Ah;
        #pragma unroll
        for (int i = 0; i < 2; i++) {
            int u = tid + i * 256;
            int row = u >> 2, c = u & 3;
            const __half* src = Ab + aRowBase + (long)row * lda + k0 + c * 8;
            CPA(sb + (half * 5120 + row * 40 + c * 8) * 2, src, 16);
        }
    }
    #pragma unroll
    for (int half = 0; half < (NP3 ? 2 : 1); half++) {
        const __half* Bb = half ? Bl : Bh;
        if (BD) {
            #pragma unroll
            for (int i = 0; i < 2; i++) {
                int u = tid + i * 256;
                int row = u >> 2, c = u & 3;
                const __half* src = Bb + bOff + (long)(col0 + row) * ldb + k0 + c * 8;
                CPA(sb + (10240 + half * 5120 + row * 40 + c * 8) * 2, src,
                    (col0 + row) < Nb ? 16 : 0);
            }
        } else {
            #pragma unroll
            for (int i = 0; i < 2; i++) {
                int u = tid + i * 256;
                int k = u >> 4, c = u & 15;
                const __half* src = Bb + bOff + (long)(k0 + k) * ldb + col0 + c * 8;
                CPA(sb + (10240 + half * 4352 + k * 136 + c * 8) * 2, src,
                    (col0 + c * 8 + 8) <= Nb ? 16 : 0);
            }
        }
    }
    CPCOMMIT();
}

template <int NP3, int BD>
__global__ __launch_bounds__(256, 1)
void hgemm(const __half* __restrict__ Ah, const __half* __restrict__ Al,
           long lda, long a1, long a2,
           const __half* __restrict__ Bh, const __half* __restrict__ Bl,
           long ldb, long b1, long b2,
           float* __restrict__ Cf, __half* __restrict__ Chi, __half* __restrict__ Clo,
           long ldc, long c0, long c1, long c2,
           const float* __restrict__ bias, const float* __restrict__ resid,
           int Nb, int nStore, int nBias, int nkb, float scale, int doGelu) {
    extern __shared__ char smem[];
    uint32_t sbase = smem_u32(smem);
    int tid = threadIdx.x, wid = tid >> 5, lane = tid & 31;
    int wm = wid >> 1, wn = wid & 1;
    int z = blockIdx.z;
    long aOff = (long)(z >> 3) * a1 + (long)(z & 7) * a2;
    long bOff = (long)(z >> 3) * b1 + (long)(z & 7) * b2;
    long cOff = (long)z * c0 + (long)(z >> 3) * c1 + (long)(z & 7) * c2;
    int row0 = blockIdx.y * 128, col0 = blockIdx.x * 128;
    long aRowBase = aOff + (long)row0 * lda;

    float acc[2][8][4];
    #pragma unroll
    for (int a = 0; a < 2; a++)
        #pragma unroll
        for (int b = 0; b < 8; b++)
            #pragma unroll
            for (int c = 0; c < 4; c++) acc[a][b][c] = 0.f;

    load_stage<NP3, BD>(sbase, tid, Ah, Al, aRowBase, lda, 0, Bh, Bl, bOff, ldb, col0, Nb);

    for (int kb = 0; kb < nkb; kb++) {
        if (kb + 1 < nkb) {
            load_stage<NP3, BD>(sbase + ((kb + 1) & 1) * STG_BYTES, tid, Ah, Al,
                                aRowBase, lda, (kb + 1) * 32, Bh, Bl, bOff, ldb, col0, Nb);
            CPWAIT1();
        } else {
            CPWAIT0();
        }
        __syncthreads();
        uint32_t sb = sbase + (kb & 1) * STG_BYTES;
        #pragma unroll
        for (int kk = 0; kk < 32; kk += 16) {
            uint32_t ah[2][4], al[2][4];
            #pragma unroll
            for (int mi = 0; mi < 2; mi++) {
                uint32_t ad = sb + (((wm * 32 + mi * 16 + (lane & 15)) * 40 + kk +
                                     (lane >> 4) * 8) << 1);
                LDSM4(ah[mi], ad);
                if (NP3) LDSM4(al[mi], ad + 10240);
            }
            #pragma unroll
            for (int ni = 0; ni < 4; ni++) {
                uint32_t bh[4], bl[4];
                if (BD) {
                    int nrow = wn * 64 + ni * 16 + (lane & 7) + ((lane >> 4) << 3);
                    uint32_t bd = sb + ((10240 + nrow * 40 + kk +
                                         (((lane >> 3) & 1) << 3)) << 1);
                    LDSM4(bh, bd);
                    if (NP3) LDSM4(bl, bd + 10240);
                } else {
                    int kq = kk + (lane & 15);
                    int nq = wn * 64 + ni * 16 + ((lane >> 4) << 3);
                    uint32_t bd = sb + ((10240 + kq * 136 + nq) << 1);
                    LDSM4T(bh, bd);
                    if (NP3) LDSM4T(bl, bd + 8704);
                }
                #pragma unroll
                for (int mi = 0; mi < 2; mi++) {
                    MMA(acc[mi][2 * ni], ah[mi], bh[0], bh[1]);
                    MMA(acc[mi][2 * ni + 1], ah[mi], bh[2], bh[3]);
                    if (NP3) {
                        MMA(acc[mi][2 * ni], al[mi], bh[0], bh[1]);
                        MMA(acc[mi][2 * ni + 1], al[mi], bh[2], bh[3]);
                        MMA(acc[mi][2 * ni], ah[mi], bl[0], bl[1]);
                        MMA(acc[mi][2 * ni + 1], ah[mi], bl[2], bl[3]);
                    }
                }
            }
        }
        __syncthreads();
    }

    int row_base = row0 + wm * 32, col_base = col0 + wn * 64;
    #pragma unroll
    for (int mi = 0; mi < 2; mi++)
        #pragma unroll
        for (int g = 0; g < 8; g++)
            #pragma unroll
            for (int rh = 0; rh < 2; rh++) {
                int row = row_base + mi * 16 + rh * 8 + (lane >> 2);
                int col = col_base + g * 8 + (lane & 3) * 2;
                if (col >= nStore) continue;
                float v0 = acc[mi][g][rh * 2] * scale;
                float v1 = acc[mi][g][rh * 2 + 1] * scale;
                if (bias) {
                    if (col < nBias) v0 += bias[col];
                    if (col + 1 < nBias) v1 += bias[col + 1];
                }
                if (doGelu) {
                    v0 = 0.5f * v0 * (1.f + erff(v0 * 0.70710678118654752f));
                    v1 = 0.5f * v1 * (1.f + erff(v1 * 0.70710678118654752f));
                }
                long cr = cOff + (long)row * ldc + col;
                if (resid) {
                    float2 rr = *(const float2*)(resid + cr);
                    v0 += rr.x; v1 += rr.y;
                }
                if (Cf) {
                    *(float2*)(Cf + cr) = make_float2(v0, v1);
                } else {
                    __half h0 = __float2half_rn(v0), h1 = __float2half_rn(v1);
                    *(__half2*)(Chi + cr) = __halves2half2(h0, h1);
                    if (Clo)
                        *(__half2*)(Clo + cr) = __halves2half2(
                            __float2half_rn(v0 - __half2float(h0)),
                            __float2half_rn(v1 - __half2float(h1)));
                }
            }
}

// ---------------- Flash attention: S(3-prod) + online softmax + PV -----------
// smem halves row-stride 104 elems (208B). Q:0/26624, K(st):53248+st*53248 (+26624 lo),
// V(st):159744+st*26624, stats @212992, O-reduce reuses K region.
#define FL_Q 0u
#define FL_KB(st) (53248u + (st) * 53248u)
#define FL_VB(st) (159744u + (st) * 26624u)
#define FL_M 212992
#define FL_L 213504
#define FL_RM 214016
#define FL_RS 215040
#define FL_CR 216064
#define FL_OB 53248
#define FL_SMEM 216576

__device__ __forceinline__ void ldtile(uint32_t dst, const __half* __restrict__ src,
                                       long base, int tid) {
    #pragma unroll
    for (int i = 0; i < 6; i++) {
        int u = tid + i * 256;
        int r = u / 12, c = u - r * 12;
        CPA(dst + r * 208 + c * 16, src + base + (long)r * QKVC + c * 8, 16);
    }
}

__global__ __launch_bounds__(256, 1)
void flash_kernel(const __half* __restrict__ qkvh, const __half* __restrict__ qkvl,
                  __half* __restrict__ att) {
    extern __shared__ char smem[];
    uint32_t sb = smem_u32(smem);
    float* sm_m = (float*)(smem + FL_M);
    float* sm_l = (float*)(smem + FL_L);
    float* sm_rm = (float*)(smem + FL_RM);
    float* sm_rs = (float*)(smem + FL_RS);
    float* sm_c = (float*)(smem + FL_CR);
    int tid = threadIdx.x, wid = tid >> 5, lane = tid & 31;
    int wm = wid >> 1, wn = wid & 1;
    int b = blockIdx.y >> 3, h = blockIdx.y & 7;
    int q0 = blockIdx.x * 128;
    const float SQ = 9.79795897113271239f;

    if (tid < 128) { sm_m[tid] = -1e30f; sm_l[tid] = 0.f; }

    long baseQ = (long)(b * NN + q0) * QKVC + h * HD;
    ldtile(sb + FL_Q, qkvh, baseQ, tid);
    ldtile(sb + FL_Q + 26624, qkvl, baseQ, tid);
    CPCOMMIT();
    long baseK = (long)(b * NN) * QKVC + DIM + h * HD;
    ldtile(sb + FL_KB(0), qkvh, baseK, tid);
    ldtile(sb + FL_KB(0) + 26624, qkvl, baseK, tid);
    ldtile(sb + FL_VB(0), qkvh, baseK + DIM, tid);
    CPCOMMIT();

    float acco[2][12][4];
    #pragma unroll
    for (int a = 0; a < 2; a++)
        #pragma unroll
        for (int g = 0; g < 12; g++)
            #pragma unroll
            for (int c = 0; c < 4; c++) acco[a][g][c] = 0.f;

    for (int kt = 0; kt < 8; kt++) {
        int st = kt & 1;
        if (kt < 7) {
            long bk = (long)(b * NN + (kt + 1) * 128) * QKVC + DIM + h * HD;
            ldtile(sb + FL_KB(st ^ 1), qkvh, bk, tid);
            ldtile(sb + FL_KB(st ^ 1) + 26624, qkvl, bk, tid);
            ldtile(sb + FL_VB(st ^ 1), qkvh, bk + DIM, tid);
            CPCOMMIT();
            CPWAIT1();
        } else {
            CPWAIT0();
        }
        __syncthreads();

        // S = Q K^T (3 products)
        float accs[2][8][4];
        #pragma unroll
        for (int a = 0; a < 2; a++)
            #pragma unroll
            for (int g = 0; g < 8; g++)
                #pragma unroll
                for (int c = 0; c < 4; c++) accs[a][g][c] = 0.f;
        uint32_t qb = sb + FL_Q, kb = sb + FL_KB(st);
        #pragma unroll
        for (int kc = 0; kc < 6; kc++) {
            uint32_t ah[2][4], al[2][4];
            #pragma unroll
            for (int mi = 0; mi < 2; mi++) {
                uint32_t ad = qb + ((wm * 32 + mi * 16 + (lane & 15)) * 104 +
                                    kc * 16 + (lane >> 4) * 8) * 2;
                LDSM4(ah[mi], ad);
                LDSM4(al[mi], ad + 26624);
            }
            #pragma unroll
            for (int ni = 0; ni < 4; ni++) {
                uint32_t bh[4], bl[4];
                uint32_t bd = kb + ((wn * 64 + ni * 16 + (lane & 7) + ((lane >> 4) << 3)) * 104 +
                                    kc * 16 + (((lane >> 3) & 1) << 3)) * 2;
                LDSM4(bh, bd);
                LDSM4(bl, bd + 26624);
                #pragma unroll
                for (int mi = 0; mi < 2; mi++) {
                    MMA(accs[mi][2 * ni], ah[mi], bh[0], bh[1]);
                    MMA(accs[mi][2 * ni + 1], ah[mi], bh[2], bh[3]);
                    MMA(accs[mi][2 * ni], al[mi], bh[0], bh[1]);
                    MMA(accs[mi][2 * ni + 1], al[mi], bh[2], bh[3]);
                    MMA(accs[mi][2 * ni], ah[mi], bl[0], bl[1]);
                    MMA(accs[mi][2 * ni + 1], ah[mi], bl[2], bl[3]);
                }
            }
        }
        // row-local max (x SQ applied at stats level)
        #pragma unroll
        for (int mi = 0; mi < 2; mi++)
            #pragma unroll
            for (int rh = 0; rh < 2; rh++) {
                float mx = -1e30f;
                #pragma unroll
                for (int g = 0; g < 8; g++)
                    mx = fmaxf(mx, fmaxf(accs[mi][g][rh * 2], accs[mi][g][rh * 2 + 1]));
                mx = fmaxf(mx, __shfl_xor_sync(~0u, mx, 1));
                mx = fmaxf(mx, __shfl_xor_sync(~0u, mx, 2));
                if ((lane & 3) == 0)
                    sm_rm[(wm * 32 + mi * 16 + rh * 8 + (lane >> 2)) * 2 + wn] = mx * SQ;
            }
        __syncthreads();
        if (tid < 128) {
            float mo = sm_m[tid];
            float mn = fmaxf(mo, fmaxf(sm_rm[tid * 2], sm_rm[tid * 2 + 1]));
            float cr = __expf(mo - mn);
            sm_m[tid] = mn;
            sm_c[tid] = cr;
            sm_l[tid] *= cr;
        }
        __syncthreads();
        // P = exp(SQ*S - m); rescale O; row sums
        #pragma unroll
        for (int mi = 0; mi < 2; mi++)
            #pragma unroll
            for (int rh = 0; rh < 2; rh++) {
                int row = wm * 32 + mi * 16 + rh * 8 + (lane >> 2);
                float mn = sm_m[row], cr = sm_c[row];
                #pragma unroll
                for (int g = 0; g < 12; g++) {
                    acco[mi][g][rh * 2] *= cr;
                    acco[mi][g][rh * 2 + 1] *= cr;
                }
                float rs = 0.f;
                #pragma unroll
                for (int g = 0; g < 8; g++) {
                    float p0 = __expf(fmaf(SQ, accs[mi][g][rh * 2], -mn));
                    float p1 = __expf(fmaf(SQ, accs[mi][g][rh * 2 + 1], -mn));
                    accs[mi][g][rh * 2] = p0;
                    accs[mi][g][rh * 2 + 1] = p1;
                    rs += p0 + p1;
                }
                rs += __shfl_xor_sync(~0u, rs, 1);
                rs += __shfl_xor_sync(~0u, rs, 2);
                if ((lane & 3) == 0) sm_rs[row * 2 + wn] = rs;
            }
        __syncthreads();
        if (tid < 128) sm_l[tid] += sm_rs[tid * 2] + sm_rs[tid * 2 + 1];
        // O += P V  (partial k: this warp's 64 k-cols)
        uint32_t vb0 = sb + FL_VB(st);
        #pragma unroll
        for (int kc2 = 0; kc2 < 4; kc2++) {
            uint32_t pa[2][4];
            #pragma unroll
            for (int mi = 0; mi < 2; mi++) {
                __half2 t;
                t = __floats2half2_rn(accs[mi][2 * kc2][0], accs[mi][2 * kc2][1]);
                pa[mi][0] = *(uint32_t*)&t;
                t = __floats2half2_rn(accs[mi][2 * kc2][2], accs[mi][2 * kc2][3]);
                pa[mi][1] = *(uint32_t*)&t;
                t = __floats2half2_rn(accs[mi][2 * kc2 + 1][0], accs[mi][2 * kc2 + 1][1]);
                pa[mi][2] = *(uint32_t*)&t;
                t = __floats2half2_rn(accs[mi][2 * kc2 + 1][2], accs[mi][2 * kc2 + 1][3]);
                pa[mi][3] = *(uint32_t*)&t;
            }
            #pragma unroll
            for (int nj = 0; nj < 6; nj++) {
                uint32_t vb[4];
                uint32_t vd = vb0 + ((wn * 64 + kc2 * 16 + (lane & 15)) * 104 +
                                     nj * 16 + ((lane >> 4) << 3)) * 2;
                LDSM4T(vb, vd);
                #pragma unroll
                for (int mi = 0; mi < 2; mi++) {
                    MMA(acco[mi][2 * nj], pa[mi], vb[0], vb[1]);
                    MMA(acco[mi][2 * nj + 1], pa[mi], vb[2], vb[3]);
                }
            }
        }
        __syncthreads();  // protect smem buffers before next prefetch overwrites
    }

    // reduce O across wn pairs in smem, divide by l, store
    float* OB = (float*)(smem + FL_OB);
    if (wn == 0) {
        #pragma unroll
        for (int mi = 0; mi < 2; mi++)
            #pragma unroll
            for (int g = 0; g < 12; g++) {
                int row = wm * 32 + mi * 16 + (lane >> 2);
                int col = g * 8 + (lane & 3) * 2;
                *(float2*)&OB[row * 96 + col] = make_float2(acco[mi][g][0], acco[mi][g][1]);
                *(float2*)&OB[(row + 8) * 96 + col] = make_float2(acco[mi][g][2], acco[mi][g][3]);
            }
    }
    __syncthreads();
    if (wn == 1) {
        #pragma unroll
        for (int mi = 0; mi < 2; mi++)
            #pragma unroll
            for (int g = 0; g < 12; g++) {
                int row = wm * 32 + mi * 16 + (lane >> 2);
                int col = g * 8 + (lane & 3) * 2;
                float2* p0 = (float2*)&OB[row * 96 + col];
                float2* p1 = (float2*)&OB[(row + 8) * 96 + col];
                float2 v0 = *p0, v1 = *p1;
                v0.x += acco[mi][g][0]; v0.y += acco[mi][g][1];
                v1.x += acco[mi][g][2]; v1.y += acco[mi][g][3];
                *p0 = v0; *p1 = v1;
            }
    }
    __syncthreads();
    long outBase = (long)(b * NN + q0) * DIM + h * HD;
    #pragma unroll
    for (int i = 0; i < 24; i++) {
        int u = tid + i * 256;
        int r = u / 48, c = (u - r * 48) * 2;
        float2 v = *(float2*)&OB[r * 96 + c];
        float rl = 1.f / sm_l[r];
        *(__half2*)(att + outBase + (long)r * DIM + c) =
            __floats2half2_rn(v.x * rl, v.y * rl);
    }
}

// ------------------------------- launch --------------------------------------
extern "C" void kernel_launch(void* const* d_in, const int* in_sizes, int n_in,
                              void* d_out, int out_size) {
    const float* x    = (const float*)d_in[0];
    const float* ln_g = (const float*)d_in[1];
    const float* ln_b = (const float*)d_in[2];
    const float* Wqkv = (const float*)d_in[3];
    const float* bqkv = (const float*)d_in[4];
    const float* W0   = (const float*)d_in[5];
    const float* b0   = (const float*)d_in[6];
    const float* W1   = (const float*)d_in[7];
    const float* b1   = (const float*)d_in[8];
    const float* W2   = (const float*)d_in[9];
    const float* b2   = (const float*)d_in[10];
    float* out = (float*)d_out;

    cudaFuncSetAttribute(hgemm<1, 0>, cudaFuncAttributeMaxDynamicSharedMemorySize, HG_SMEM);
    cudaFuncSetAttribute(hgemm<0, 0>, cudaFuncAttributeMaxDynamicSharedMemorySize, HG_SMEM);
    cudaFuncSetAttribute(flash_kernel, cudaFuncAttributeMaxDynamicSharedMemorySize, FL_SMEM);

    __half *yh, *yl, *wqh, *wql, *qkvh, *qkvl, *att, *l2, *w0, *w1, *w2, *hb;
    float *z;
    cudaGetSymbolAddress((void**)&yh, g_yh);   cudaGetSymbolAddress((void**)&yl, g_yl);
    cudaGetSymbolAddress((void**)&wqh, g_wqh); cudaGetSymbolAddress((void**)&wql, g_wql);
    cudaGetSymbolAddress((void**)&qkvh, g_qkvh); cudaGetSymbolAddress((void**)&qkvl, g_qkvl);
    cudaGetSymbolAddress((void**)&att, g_att);
    cudaGetSymbolAddress((void**)&z, g_z);
    cudaGetSymbolAddress((void**)&l2, g_l2);
    cudaGetSymbolAddress((void**)&w0, g_w0);
    cudaGetSymbolAddress((void**)&w1, g_w1);
    cudaGetSymbolAddress((void**)&w2, g_w2);
    cudaGetSymbolAddress((void**)&hb, g_h);

    split_kernel<<<(DIM * QKVC + 255) / 256, 256>>>(Wqkv, wqh, wql, DIM, QKVC, QKVC, DIM * QKVC);
    split_kernel<<<(DIM * DIM + 255) / 256, 256>>>(W0, w0, nullptr, DIM, DIM, DIM, DIM * DIM);
    split_kernel<<<(DIM * HPAD + 255) / 256, 256>>>(W1, w1, nullptr, DIM, HIDDEN, HPAD, DIM * HPAD);
    split_kernel<<<(HPAD * DIM + 255) / 256, 256>>>(W2, w2, nullptr, HIDDEN, DIM, DIM, HPAD * DIM);

    ln_split_kernel<<<ROWS, 256>>>(x, ln_g, ln_b, yh, yl);
    // Q,K = y @ Wqkv[:, :1536] + b  (3-product, split output)
    hgemm<1, 0><<<dim3(12, 64, 1), 256, HG_SMEM>>>(
        yh, yl, DIM, 0, 0, wqh, wql, QKVC, 0, 0,
        nullptr, qkvh, qkvl, QKVC, 0, 0, 0,
        bqkv, nullptr, 1536, 1536, 1536, 24, 1.f, 0);
    // V = y @ Wqkv[:, 1536:] + b  (single product, hi only)
    hgemm<0, 0><<<dim3(6, 64, 1), 256, HG_SMEM>>>(
        yh, nullptr, DIM, 0, 0, wqh + 1536, nullptr, QKVC, 0, 0,
        nullptr, qkvh + 1536, nullptr, QKVC, 0, 0, 0,
        bqkv + 1536, nullptr, 768, 768, 768, 24, 1.f, 0);
    // fused attention
    flash_kernel<<<dim3(8, 64), 256, FL_SMEM>>>(qkvh, qkvl, att);
    // z = att @ W0 + b0 + x
    hgemm<0, 0><<<dim3(6, 64, 1), 256, HG_SMEM>>>(
        att, nullptr, DIM, 0, 0, w0, nullptr, DIM, 0, 0,
        z, nullptr, nullptr, DIM, 0, 0, 0,
        b0, x, DIM, DIM, DIM, 24, 1.f, 0);
    ln_split_kernel<<<ROWS, 256>>>(z, ln_g, ln_b, l2, nullptr);
    // h = gelu(l2 @ W1 + b1)
    hgemm<0, 0><<<dim3(12, 64, 1), 256, HG_SMEM>>>(
        l2, nullptr, DIM, 0, 0, w1, nullptr, HPAD, 0, 0,
        nullptr, hb, nullptr, HPAD, 0, 0, 0,
        b1, nullptr, HPAD, HPAD, HIDDEN, 24, 1.f, 1);
    // out = h @ W2 + b2 + z
    hgemm<0, 0><<<dim3(6, 64, 1), 256, HG_SMEM>>>(
        hb, nullptr, HPAD, 0, 0, w2, nullptr, DIM, 0, 0,
        out, nullptr, nullptr, DIM, 0, 0, 0,
        b2, z, DIM, DIM, DIM, 47, 1.f, 0);
}

// round 9
// speedup vs baseline: 4.4702x; 1.0468x over previous
#include <cuda_runtime.h>
#include <cuda_fp16.h>
#include <math.h>
#include <stdint.h>

#define BB 8
#define NN 1024
#define DIM 768
#define HEADS 8
#define HD 96
#define HIDDEN 1500
#define HPAD 1504
#define ROWS (BB * NN)
#define QKVC (3 * DIM)
#define PAD 64

__device__ __forceinline__ uint32_t smem_u32(const void* p) {
    uint32_t r;
    asm("{ .reg .u64 t; cvta.to.shared.u64 t, %1; cvt.u32.u64 %0, t; }" : "=r"(r) : "l"(p));
    return r;
}
#define CPA(dst, src, p) asm volatile("cp.async.cg.shared.global [%0], [%1], 16, %2;" :: "r"(dst), "l"(src), "r"(p) : "memory")
#define CPCOMMIT() asm volatile("cp.async.commit_group;" ::: "memory")
#define CPWAIT1() asm volatile("cp.async.wait_group 1;" ::: "memory")
#define CPWAIT0() asm volatile("cp.async.wait_group 0;" ::: "memory")
#define LDSM4(r, a) asm volatile("ldmatrix.sync.aligned.m8n8.x4.shared.b16 {%0,%1,%2,%3}, [%4];" \
    : "=r"((r)[0]), "=r"((r)[1]), "=r"((r)[2]), "=r"((r)[3]) : "r"(a))
#define LDSM4T(r, a) asm volatile("ldmatrix.sync.aligned.m8n8.x4.trans.shared.b16 {%0,%1,%2,%3}, [%4];" \
    : "=r"((r)[0]), "=r"((r)[1]), "=r"((r)[2]), "=r"((r)[3]) : "r"(a))
#define MMA(c, a, b0, b1) asm volatile( \
    "mma.sync.aligned.m16n8k16.row.col.f32.f16.f16.f32 {%0,%1,%2,%3}, {%4,%5,%6,%7}, {%8,%9}, {%0,%1,%2,%3};" \
    : "+f"((c)[0]), "+f"((c)[1]), "+f"((c)[2]), "+f"((c)[3]) \
    : "r"((a)[0]), "r"((a)[1]), "r"((a)[2]), "r"((a)[3]), "r"(b0), "r"(b1))

// ------------------------------ scratch -------------------------------------
__device__ __half g_yh[ROWS * DIM + PAD], g_yl[ROWS * DIM + PAD];
__device__ __half g_wqh[DIM * QKVC + PAD], g_wql[DIM * QKVC + PAD];
__device__ __half g_qkvh[ROWS * QKVC + PAD], g_qkvl[ROWS * QKVC + PAD];
__device__ __half g_att[ROWS * DIM + PAD];
__device__ float  g_z[ROWS * DIM + PAD];
__device__ __half g_l2[ROWS * DIM + PAD];
__device__ __half g_w0[DIM * DIM + PAD];
__device__ __half g_w1[DIM * HPAD + PAD];
__device__ __half g_w2[HPAD * DIM + PAD];
__device__ __half g_h[ROWS * HPAD + PAD];

// ---- one kernel splitting all 4 weights (wq gets lo; w1/w2 padded) ----------
#define SEG0 6912   // wq: 768*2304
#define SEG1 2304   // w0: 768*768
#define SEG2 4512   // w1: 768*1504 (pad from 1500)
#define SEG3 4512   // w2: 1504*768 (pad rows from 1500)
__global__ void split4_kernel(const float* __restrict__ wq, __half* __restrict__ wqh,
                              __half* __restrict__ wql,
                              const float* __restrict__ w0, __half* __restrict__ w0h,
                              const float* __restrict__ w1, __half* __restrict__ w1h,
                              const float* __restrict__ w2, __half* __restrict__ w2h) {
    int blk = blockIdx.x;
    int t = threadIdx.x;
    if (blk < SEG0) {
        int i = blk * 256 + t;
        float v = wq[i];
        __half hh = __float2half_rn(v);
        wqh[i] = hh;
        wql[i] = __float2half_rn(v - __half2float(hh));
    } else if (blk < SEG0 + SEG1) {
        int i = (blk - SEG0) * 256 + t;
        w0h[i] = __float2half_rn(w0[i]);
    } else if (blk < SEG0 + SEG1 + SEG2) {
        int i = (blk - SEG0 - SEG1) * 256 + t;
        int r = i / HPAD, c = i - r * HPAD;
        w1h[i] = __float2half_rn(c < HIDDEN ? w1[(size_t)r * HIDDEN + c] : 0.f);
    } else {
        int i = (blk - SEG0 - SEG1 - SEG2) * 256 + t;
        int r = i / DIM, c = i - r * DIM;
        w2h[i] = __float2half_rn(r < HIDDEN ? w2[(size_t)r * DIM + c] : 0.f);
    }
}

__global__ void ln_split_kernel(const float* __restrict__ in,
                                const float* __restrict__ gamma,
                                const float* __restrict__ beta,
                                __half* __restrict__ oh, __half* __restrict__ ol) {
    int row = blockIdx.x, t = threadIdx.x;
    const float* px = in + (size_t)row * DIM;
    float v0 = px[t], v1 = px[t + 256], v2 = px[t + 512];
    float s = v0 + v1 + v2, sq = v0 * v0 + v1 * v1 + v2 * v2;
    __shared__ float red0[8], red1[8];
    #pragma unroll
    for (int o = 16; o; o >>= 1) {
        s += __shfl_xor_sync(~0u, s, o);
        sq += __shfl_xor_sync(~0u, sq, o);
    }
    if ((t & 31) == 0) { red0[t >> 5] = s; red1[t >> 5] = sq; }
    __syncthreads();
    if (t < 32) {
        s = (t < 8) ? red0[t] : 0.f;
        sq = (t < 8) ? red1[t] : 0.f;
        #pragma unroll
        for (int o = 4; o; o >>= 1) {
            s += __shfl_xor_sync(~0u, s, o);
            sq += __shfl_xor_sync(~0u, sq, o);
        }
        if (t == 0) { red0[0] = s; red1[0] = sq; }
    }
    __syncthreads();
    float mean = red0[0] * (1.f / DIM);
    float var = red1[0] * (1.f / DIM) - mean * mean;
    float rstd = rsqrtf(var + 1e-5f);
    size_t base = (size_t)row * DIM;
    float vv[3] = {v0, v1, v2};
    #pragma unroll
    for (int c = 0; c < 3; c++) {
        int i = t + c * 256;
        float v = (vv[c] - mean) * rstd * gamma[i] + beta[i];
        __half h = __float2half_rn(v);
        oh[base + i] = h;
        if (ol) ol[base + i] = __float2half_rn(v - __half2float(h));
    }
}

// ---------------- mma.sync GEMM (unchanged core) -----------------------------
#define STG_BYTES 40960
#define HG_SMEM (2 * STG_BYTES)

template <int NP3, int BD>
__device__ __forceinline__ void load_stage(uint32_t sb, int tid,
    const __half* __restrict__ Ah, const __half* __restrict__ Al,
    long aRowBase, long lda, int k0,
    const __half* __restrict__ Bh, const __half* __restrict__ Bl,
    long bOff, long ldb, int col0, int Nb) {
    #pragma unroll
    for (int half = 0; half < (NP3 ? 2 : 1); half++) {
        const __half* Ab = half ? Al : Ah;
        #pragma unroll
        for (int i = 0; i < 2; i++) {
            int u = tid + i * 256;
            int row = u >> 2, c = u & 3;
            const __half* src = Ab + aRowBase + (long)row * lda + k0 + c * 8;
            CPA(sb + (half * 5120 + row * 40 + c * 8) * 2, src, 16);
        }
    }
    #pragma unroll
    for (int half = 0; half < (NP3 ? 2 : 1); half++) {
        const __half* Bb = half ? Bl : Bh;
        if (BD) {
            #pragma unroll
            for (int i = 0; i < 2; i++) {
                int u = tid + i * 256;
                int row = u >> 2, c = u & 3;
                const __half* src = Bb + bOff + (long)(col0 + row) * ldb + k0 + c * 8;
                CPA(sb + (10240 + half * 5120 + row * 40 + c * 8) * 2, src,
                    (col0 + row) < Nb ? 16 : 0);
            }
        } else {
            #pragma unroll
            for (int i = 0; i < 2; i++) {
                int u = tid + i * 256;
                int k = u >> 4, c = u & 15;
                const __half* src = Bb + bOff + (long)(k0 + k) * ldb + col0 + c * 8;
                CPA(sb + (10240 + half * 4352 + k * 136 + c * 8) * 2, src,
                    (col0 + c * 8 + 8) <= Nb ? 16 : 0);
            }
        }
    }
    CPCOMMIT();
}

template <int NP3, int BD>
__global__ __launch_bounds__(256, 1)
void hgemm(const __half* __restrict__ Ah, const __half* __restrict__ Al,
           long lda, long a1, long a2,
           const __half* __restrict__ Bh, const __half* __restrict__ Bl,
           long ldb, long b1, long b2,
           float* __restrict__ Cf, __half* __restrict__ Chi, __half* __restrict__ Clo,
           long ldc, long c0, long c1, long c2,
           const float* __restrict__ bias, const float* __restrict__ resid,
           int Nb, int nStore, int nBias, int nkb, float scale, int doGelu) {
    extern __shared__ char smem[];
    uint32_t sbase = smem_u32(smem);
    int tid = threadIdx.x, wid = tid >> 5, lane = tid & 31;
    int wm = wid >> 1, wn = wid & 1;
    int z = blockIdx.z;
    long aOff = (long)(z >> 3) * a1 + (long)(z & 7) * a2;
    long bOff = (long)(z >> 3) * b1 + (long)(z & 7) * b2;
    long cOff = (long)z * c0 + (long)(z >> 3) * c1 + (long)(z & 7) * c2;
    int row0 = blockIdx.y * 128, col0 = blockIdx.x * 128;
    long aRowBase = aOff + (long)row0 * lda;

    float acc[2][8][4];
    #pragma unroll
    for (int a = 0; a < 2; a++)
        #pragma unroll
        for (int b = 0; b < 8; b++)
            #pragma unroll
            for (int c = 0; c < 4; c++) acc[a][b][c] = 0.f;

    load_stage<NP3, BD>(sbase, tid, Ah, Al, aRowBase, lda, 0, Bh, Bl, bOff, ldb, col0, Nb);

    for (int kb = 0; kb < nkb; kb++) {
        if (kb + 1 < nkb) {
            load_stage<NP3, BD>(sbase + ((kb + 1) & 1) * STG_BYTES, tid, Ah, Al,
                                aRowBase, lda, (kb + 1) * 32, Bh, Bl, bOff, ldb, col0, Nb);
            CPWAIT1();
        } else {
            CPWAIT0();
        }
        __syncthreads();
        uint32_t sb = sbase + (kb & 1) * STG_BYTES;
        #pragma unroll
        for (int kk = 0; kk < 32; kk += 16) {
            uint32_t ah[2][4], al[2][4];
            #pragma unroll
            for (int mi = 0; mi < 2; mi++) {
                uint32_t ad = sb + (((wm * 32 + mi * 16 + (lane & 15)) * 40 + kk +
                                     (lane >> 4) * 8) << 1);
                LDSM4(ah[mi], ad);
                if (NP3) LDSM4(al[mi], ad + 10240);
            }
            #pragma unroll
            for (int ni = 0; ni < 4; ni++) {
                uint32_t bh[4], bl[4];
                if (BD) {
                    int nrow = wn * 64 + ni * 16 + (lane & 7) + ((lane >> 4) << 3);
                    uint32_t bd = sb + ((10240 + nrow * 40 + kk +
                                         (((lane >> 3) & 1) << 3)) << 1);
                    LDSM4(bh, bd);
                    if (NP3) LDSM4(bl, bd + 10240);
                } else {
                    int kq = kk + (lane & 15);
                    int nq = wn * 64 + ni * 16 + ((lane >> 4) << 3);
                    uint32_t bd = sb + ((10240 + kq * 136 + nq) << 1);
                    LDSM4T(bh, bd);
                    if (NP3) LDSM4T(bl, bd + 8704);
                }
                #pragma unroll
                for (int mi = 0; mi < 2; mi++) {
                    MMA(acc[mi][2 * ni], ah[mi], bh[0], bh[1]);
                    MMA(acc[mi][2 * ni + 1], ah[mi], bh[2], bh[3]);
                    if (NP3) {
                        MMA(acc[mi][2 * ni], al[mi], bh[0], bh[1]);
                        MMA(acc[mi][2 * ni + 1], al[mi], bh[2], bh[3]);
                        MMA(acc[mi][2 * ni], ah[mi], bl[0], bl[1]);
                        MMA(acc[mi][2 * ni + 1], ah[mi], bl[2], bl[3]);
                    }
                }
            }
        }
        __syncthreads();
    }

    int row_base = row0 + wm * 32, col_base = col0 + wn * 64;
    #pragma unroll
    for (int mi = 0; mi < 2; mi++)
        #pragma unroll
        for (int g = 0; g < 8; g++)
            #pragma unroll
            for (int rh = 0; rh < 2; rh++) {
                int row = row_base + mi * 16 + rh * 8 + (lane >> 2);
                int col = col_base + g * 8 + (lane & 3) * 2;
                if (col >= nStore) continue;
                float v0 = acc[mi][g][rh * 2] * scale;
                float v1 = acc[mi][g][rh * 2 + 1] * scale;
                if (bias) {
                    if (col < nBias) v0 += bias[col];
                    if (col + 1 < nBias) v1 += bias[col + 1];
                }
                if (doGelu) {
                    v0 = 0.5f * v0 * (1.f + erff(v0 * 0.70710678118654752f));
                    v1 = 0.5f * v1 * (1.f + erff(v1 * 0.70710678118654752f));
                }
                long cr = cOff + (long)row * ldc + col;
                if (resid) {
                    float2 rr = *(const float2*)(resid + cr);
                    v0 += rr.x; v1 += rr.y;
                }
                if (Cf) {
                    *(float2*)(Cf + cr) = make_float2(v0, v1);
                } else {
                    __half h0 = __float2half_rn(v0), h1 = __float2half_rn(v1);
                    *(__half2*)(Chi + cr) = __halves2half2(h0, h1);
                    if (Clo)
                        *(__half2*)(Clo + cr) = __halves2half2(
                            __float2half_rn(v0 - __half2float(h0)),
                            __float2half_rn(v1 - __half2float(h1)));
                }
            }
}

// ---------------- Flash attention v2: warp-owns-rows, register softmax -------
// Q hi/lo @0/26624; stage st: K hi @FST, K lo @+26624, V @+53248. stride 104 halves.
#define FQ 0u
#define FST(st) (53248u + (st) * 79872u)
#define FL_SMEM 212992

__device__ __forceinline__ void ldtile(uint32_t dst, const __half* __restrict__ src,
                                       long base, int tid) {
    #pragma unroll
    for (int i = 0; i < 6; i++) {
        int u = tid + i * 256;
        int r = u / 12, c = u - r * 12;
        CPA(dst + r * 208 + c * 16, src + base + (long)r * QKVC + c * 8, 16);
    }
}

__global__ __launch_bounds__(256, 1)
void flash_kernel(const __half* __restrict__ qkvh, const __half* __restrict__ qkvl,
                  __half* __restrict__ att) {
    extern __shared__ char smem[];
    uint32_t sb = smem_u32(smem);
    int tid = threadIdx.x, wid = tid >> 5, lane = tid & 31;
    int b = blockIdx.y >> 3, h = blockIdx.y & 7;
    int q0 = blockIdx.x * 128;
    int qr = wid * 16;
    const float SQ = 9.79795897113271239f;

    long baseQ = (long)(b * NN + q0) * QKVC + h * HD;
    ldtile(sb + FQ, qkvh, baseQ, tid);
    ldtile(sb + FQ + 26624, qkvl, baseQ, tid);
    CPCOMMIT();
    long baseK = (long)(b * NN) * QKVC + DIM + h * HD;
    ldtile(sb + FST(0), qkvh, baseK, tid);
    ldtile(sb + FST(0) + 26624, qkvl, baseK, tid);
    ldtile(sb + FST(0) + 53248, qkvh, baseK + DIM, tid);
    CPCOMMIT();

    float acco[12][4];
    #pragma unroll
    for (int g = 0; g < 12; g++)
        #pragma unroll
        for (int c = 0; c < 4; c++) acco[g][c] = 0.f;
    float m0 = -1e30f, m1 = -1e30f, l0 = 0.f, l1 = 0.f;

    for (int kt = 0; kt < 8; kt++) {
        int st = kt & 1;
        if (kt < 7) {
            long bk = (long)(b * NN + (kt + 1) * 128) * QKVC + DIM + h * HD;
            ldtile(sb + FST(st ^ 1), qkvh, bk, tid);
            ldtile(sb + FST(st ^ 1) + 26624, qkvl, bk, tid);
            ldtile(sb + FST(st ^ 1) + 53248, qkvh, bk + DIM, tid);
            CPCOMMIT();
            CPWAIT1();
        } else {
            CPWAIT0();
        }
        __syncthreads();

        // ---- S = Q K^T (3 products), warp rows qr..qr+15, cols 0..127 ----
        float accs[16][4];
        #pragma unroll
        for (int g = 0; g < 16; g++)
            #pragma unroll
            for (int c = 0; c < 4; c++) accs[g][c] = 0.f;
        uint32_t qb = sb + FQ, kbase = sb + FST(st);
        #pragma unroll
        for (int kc = 0; kc < 6; kc++) {
            uint32_t ah[4], al[4];
            uint32_t ad = qb + ((qr + (lane & 15)) * 104 + kc * 16 + (lane >> 4) * 8) * 2;
            LDSM4(ah, ad);
            LDSM4(al, ad + 26624);
            #pragma unroll
            for (int ni = 0; ni < 8; ni++) {
                uint32_t bh[4], bl[4];
                uint32_t bd = kbase + ((ni * 16 + (lane & 7) + ((lane >> 4) << 3)) * 104 +
                                       kc * 16 + (((lane >> 3) & 1) << 3)) * 2;
                LDSM4(bh, bd);
                LDSM4(bl, bd + 26624);
                MMA(accs[2 * ni], ah, bh[0], bh[1]);
                MMA(accs[2 * ni + 1], ah, bh[2], bh[3]);
                MMA(accs[2 * ni], al, bh[0], bh[1]);
                MMA(accs[2 * ni + 1], al, bh[2], bh[3]);
                MMA(accs[2 * ni], ah, bl[0], bl[1]);
                MMA(accs[2 * ni + 1], ah, bl[2], bl[3]);
            }
        }
        // ---- online softmax entirely in registers (quad shfl) ----
        float mx0 = -1e30f, mx1 = -1e30f;
        #pragma unroll
        for (int g = 0; g < 16; g++) {
            mx0 = fmaxf(mx0, fmaxf(accs[g][0], accs[g][1]));
            mx1 = fmaxf(mx1, fmaxf(accs[g][2], accs[g][3]));
        }
        mx0 = fmaxf(mx0, __shfl_xor_sync(~0u, mx0, 1));
        mx0 = fmaxf(mx0, __shfl_xor_sync(~0u, mx0, 2));
        mx1 = fmaxf(mx1, __shfl_xor_sync(~0u, mx1, 1));
        mx1 = fmaxf(mx1, __shfl_xor_sync(~0u, mx1, 2));
        float mn0 = fmaxf(m0, mx0 * SQ), mn1 = fmaxf(m1, mx1 * SQ);
        float cr0 = __expf(m0 - mn0), cr1 = __expf(m1 - mn1);
        m0 = mn0; m1 = mn1;
        float rs0 = 0.f, rs1 = 0.f;
        #pragma unroll
        for (int g = 0; g < 16; g++) {
            float p0 = __expf(fmaf(SQ, accs[g][0], -mn0));
            float p1 = __expf(fmaf(SQ, accs[g][1], -mn0));
            float p2 = __expf(fmaf(SQ, accs[g][2], -mn1));
            float p3 = __expf(fmaf(SQ, accs[g][3], -mn1));
            accs[g][0] = p0; accs[g][1] = p1; accs[g][2] = p2; accs[g][3] = p3;
            rs0 += p0 + p1; rs1 += p2 + p3;
        }
        rs0 += __shfl_xor_sync(~0u, rs0, 1);
        rs0 += __shfl_xor_sync(~0u, rs0, 2);
        rs1 += __shfl_xor_sync(~0u, rs1, 1);
        rs1 += __shfl_xor_sync(~0u, rs1, 2);
        l0 = l0 * cr0 + rs0;
        l1 = l1 * cr1 + rs1;
        #pragma unroll
        for (int g = 0; g < 12; g++) {
            acco[g][0] *= cr0; acco[g][1] *= cr0;
            acco[g][2] *= cr1; acco[g][3] *= cr1;
        }
        // ---- O += P V ----
        uint32_t vb0 = sb + FST(st) + 53248;
        #pragma unroll
        for (int kb2 = 0; kb2 < 8; kb2++) {
            uint32_t pa[4];
            __half2 t;
            t = __floats2half2_rn(accs[2 * kb2][0], accs[2 * kb2][1]);
            pa[0] = *(uint32_t*)&t;
            t = __floats2half2_rn(accs[2 * kb2][2], accs[2 * kb2][3]);
            pa[1] = *(uint32_t*)&t;
            t = __floats2half2_rn(accs[2 * kb2 + 1][0], accs[2 * kb2 + 1][1]);
            pa[2] = *(uint32_t*)&t;
            t = __floats2half2_rn(accs[2 * kb2 + 1][2], accs[2 * kb2 + 1][3]);
            pa[3] = *(uint32_t*)&t;
            #pragma unroll
            for (int nj = 0; nj < 6; nj++) {
                uint32_t vb[4];
                uint32_t vd = vb0 + ((kb2 * 16 + (lane & 15)) * 104 +
                                     nj * 16 + ((lane >> 4) << 3)) * 2;
                LDSM4T(vb, vd);
                MMA(acco[2 * nj], pa, vb[0], vb[1]);
                MMA(acco[2 * nj + 1], pa, vb[2], vb[3]);
            }
        }
        __syncthreads();  // all warps done reading stage st before it is refilled
    }

    float rl0 = 1.f / l0, rl1 = 1.f / l1;
    long ob = (long)(b * NN + q0 + qr + (lane >> 2)) * DIM + h * HD + (lane & 3) * 2;
    #pragma unroll
    for (int g = 0; g < 12; g++) {
        *(__half2*)(att + ob + g * 8) =
            __floats2half2_rn(acco[g][0] * rl0, acco[g][1] * rl0);
        *(__half2*)(att + ob + 8 * DIM + g * 8) =
            __floats2half2_rn(acco[g][2] * rl1, acco[g][3] * rl1);
    }
}

// ------------------------------- launch --------------------------------------
extern "C" void kernel_launch(void* const* d_in, const int* in_sizes, int n_in,
                              void* d_out, int out_size) {
    const float* x    = (const float*)d_in[0];
    const float* ln_g = (const float*)d_in[1];
    const float* ln_b = (const float*)d_in[2];
    const float* Wqkv = (const float*)d_in[3];
    const float* bqkv = (const float*)d_in[4];
    const float* W0   = (const float*)d_in[5];
    const float* b0   = (const float*)d_in[6];
    const float* W1   = (const float*)d_in[7];
    const float* b1   = (const float*)d_in[8];
    const float* W2   = (const float*)d_in[9];
    const float* b2   = (const float*)d_in[10];
    float* out = (float*)d_out;

    cudaFuncSetAttribute(hgemm<1, 0>, cudaFuncAttributeMaxDynamicSharedMemorySize, HG_SMEM);
    cudaFuncSetAttribute(hgemm<0, 0>, cudaFuncAttributeMaxDynamicSharedMemorySize, HG_SMEM);
    cudaFuncSetAttribute(flash_kernel, cudaFuncAttributeMaxDynamicSharedMemorySize, FL_SMEM);

    __half *yh, *yl, *wqh, *wql, *qkvh, *qkvl, *att, *l2, *w0, *w1, *w2, *hb;
    float *z;
    cudaGetSymbolAddress((void**)&yh, g_yh);   cudaGetSymbolAddress((void**)&yl, g_yl);
    cudaGetSymbolAddress((void**)&wqh, g_wqh); cudaGetSymbolAddress((void**)&wql, g_wql);
    cudaGetSymbolAddress((void**)&qkvh, g_qkvh); cudaGetSymbolAddress((void**)&qkvl, g_qkvl);
    cudaGetSymbolAddress((void**)&att, g_att);
    cudaGetSymbolAddress((void**)&z, g_z);
    cudaGetSymbolAddress((void**)&l2, g_l2);
    cudaGetSymbolAddress((void**)&w0, g_w0);
    cudaGetSymbolAddress((void**)&w1, g_w1);
    cudaGetSymbolAddress((void**)&w2, g_w2);
    cudaGetSymbolAddress((void**)&hb, g_h);

    split4_kernel<<<SEG0 + SEG1 + SEG2 + SEG3, 256>>>(Wqkv, wqh, wql, W0, w0, W1, w1, W2, w2);
    ln_split_kernel<<<ROWS, 256>>>(x, ln_g, ln_b, yh, yl);
    // Q,K = y @ Wqkv[:, :1536] + b  (3-product, split output)
    hgemm<1, 0><<<dim3(12, 64, 1), 256, HG_SMEM>>>(
        yh, yl, DIM, 0, 0, wqh, wql, QKVC, 0, 0,
        nullptr, qkvh, qkvl, QKVC, 0, 0, 0,
        bqkv, nullptr, 1536, 1536, 1536, 24, 1.f, 0);
    // V = y @ Wqkv[:, 1536:] + b  (single product)
    hgemm<0, 0><<<dim3(6, 64, 1), 256, HG_SMEM>>>(
        yh, nullptr, DIM, 0, 0, wqh + 1536, nullptr, QKVC, 0, 0,
        nullptr, qkvh + 1536, nullptr, QKVC, 0, 0, 0,
        bqkv + 1536, nullptr, 768, 768, 768, 24, 1.f, 0);
    flash_kernel<<<dim3(8, 64), 256, FL_SMEM>>>(qkvh, qkvl, att);
    // z = att @ W0 + b0 + x
    hgemm<0, 0><<<dim3(6, 64, 1), 256, HG_SMEM>>>(
        att, nullptr, DIM, 0, 0, w0, nullptr, DIM, 0, 0,
        z, nullptr, nullptr, DIM, 0, 0, 0,
        b0, x, DIM, DIM, DIM, 24, 1.f, 0);
    ln_split_kernel<<<ROWS, 256>>>(z, ln_g, ln_b, l2, nullptr);
    // h = gelu(l2 @ W1 + b1)
    hgemm<0, 0><<<dim3(12, 64, 1), 256, HG_SMEM>>>(
        l2, nullptr, DIM, 0, 0, w1, nullptr, HPAD, 0, 0,
        nullptr, hb, nullptr, HPAD, 0, 0, 0,
        b1, nullptr, HPAD, HPAD, HIDDEN, 24, 1.f, 1);
    // out = h @ W2 + b2 + z
    hgemm<0, 0><<<dim3(6, 64, 1), 256, HG_SMEM>>>(
        hb, nullptr, HPAD, 0, 0, w2, nullptr, DIM, 0, 0,
        out, nullptr, nullptr, DIM, 0, 0, 0,
        b2, z, DIM, DIM, DIM, 47, 1.f, 0);
}

// round 10
// speedup vs baseline: 5.4589x; 1.2212x over previous
#include <cuda_runtime.h>
#include <cuda_fp16.h>
#include <math.h>
#include <stdint.h>

#define BB 8
#define NN 1024
#define DIM 768
#define HEADS 8
#define HD 96
#define HIDDEN 1500
#define HPAD 1504
#define ROWS (BB * NN)
#define QKVC (3 * DIM)
#define PAD 64

__device__ __forceinline__ uint32_t smem_u32(const void* p) {
    uint32_t r;
    asm("{ .reg .u64 t; cvta.to.shared.u64 t, %1; cvt.u32.u64 %0, t; }" : "=r"(r) : "l"(p));
    return r;
}
#define CPA(dst, src, p) asm volatile("cp.async.cg.shared.global [%0], [%1], 16, %2;" :: "r"(dst), "l"(src), "r"(p) : "memory")
#define CPCOMMIT() asm volatile("cp.async.commit_group;" ::: "memory")
#define CPWAIT1() asm volatile("cp.async.wait_group 1;" ::: "memory")
#define CPWAIT0() asm volatile("cp.async.wait_group 0;" ::: "memory")
#define LDSM4(r, a) asm volatile("ldmatrix.sync.aligned.m8n8.x4.shared.b16 {%0,%1,%2,%3}, [%4];" \
    : "=r"((r)[0]), "=r"((r)[1]), "=r"((r)[2]), "=r"((r)[3]) : "r"(a))
#define LDSM4T(r, a) asm volatile("ldmatrix.sync.aligned.m8n8.x4.trans.shared.b16 {%0,%1,%2,%3}, [%4];" \
    : "=r"((r)[0]), "=r"((r)[1]), "=r"((r)[2]), "=r"((r)[3]) : "r"(a))
#define MMA(c, a, b0, b1) asm volatile( \
    "mma.sync.aligned.m16n8k16.row.col.f32.f16.f16.f32 {%0,%1,%2,%3}, {%4,%5,%6,%7}, {%8,%9}, {%0,%1,%2,%3};" \
    : "+f"((c)[0]), "+f"((c)[1]), "+f"((c)[2]), "+f"((c)[3]) \
    : "r"((a)[0]), "r"((a)[1]), "r"((a)[2]), "r"((a)[3]), "r"(b0), "r"(b1))

// ------------------------------ scratch -------------------------------------
__device__ __half g_yh[ROWS * DIM + PAD], g_yl[ROWS * DIM + PAD];
__device__ __half g_wqh[DIM * QKVC + PAD], g_wql[DIM * QKVC + PAD];
__device__ __half g_qkvh[ROWS * QKVC + PAD], g_qkvl[ROWS * QKVC + PAD];
__device__ __half g_att[ROWS * DIM + PAD];
__device__ float  g_z[ROWS * DIM + PAD];
__device__ __half g_l2[ROWS * DIM + PAD];
__device__ __half g_w0[DIM * DIM + PAD];
__device__ __half g_w1[DIM * HPAD + PAD];
__device__ __half g_w2[HPAD * DIM + PAD];
__device__ __half g_h[ROWS * HPAD + PAD];

// ---- one kernel splitting all 4 weights ------------------------------------
#define SEG0 6912
#define SEG1 2304
#define SEG2 4512
#define SEG3 4512
__global__ void split4_kernel(const float* __restrict__ wq, __half* __restrict__ wqh,
                              __half* __restrict__ wql,
                              const float* __restrict__ w0, __half* __restrict__ w0h,
                              const float* __restrict__ w1, __half* __restrict__ w1h,
                              const float* __restrict__ w2, __half* __restrict__ w2h) {
    int blk = blockIdx.x;
    int t = threadIdx.x;
    if (blk < SEG0) {
        int i = blk * 256 + t;
        float v = wq[i];
        __half hh = __float2half_rn(v);
        wqh[i] = hh;
        wql[i] = __float2half_rn(v - __half2float(hh));
    } else if (blk < SEG0 + SEG1) {
        int i = (blk - SEG0) * 256 + t;
        w0h[i] = __float2half_rn(w0[i]);
    } else if (blk < SEG0 + SEG1 + SEG2) {
        int i = (blk - SEG0 - SEG1) * 256 + t;
        int r = i / HPAD, c = i - r * HPAD;
        w1h[i] = __float2half_rn(c < HIDDEN ? w1[(size_t)r * HIDDEN + c] : 0.f);
    } else {
        int i = (blk - SEG0 - SEG1 - SEG2) * 256 + t;
        int r = i / DIM, c = i - r * DIM;
        w2h[i] = __float2half_rn(r < HIDDEN ? w2[(size_t)r * DIM + c] : 0.f);
    }
}

__global__ void ln_split_kernel(const float* __restrict__ in,
                                const float* __restrict__ gamma,
                                const float* __restrict__ beta,
                                __half* __restrict__ oh, __half* __restrict__ ol) {
    int row = blockIdx.x, t = threadIdx.x;
    const float* px = in + (size_t)row * DIM;
    float v0 = px[t], v1 = px[t + 256], v2 = px[t + 512];
    float s = v0 + v1 + v2, sq = v0 * v0 + v1 * v1 + v2 * v2;
    __shared__ float red0[8], red1[8];
    #pragma unroll
    for (int o = 16; o; o >>= 1) {
        s += __shfl_xor_sync(~0u, s, o);
        sq += __shfl_xor_sync(~0u, sq, o);
    }
    if ((t & 31) == 0) { red0[t >> 5] = s; red1[t >> 5] = sq; }
    __syncthreads();
    if (t < 32) {
        s = (t < 8) ? red0[t] : 0.f;
        sq = (t < 8) ? red1[t] : 0.f;
        #pragma unroll
        for (int o = 4; o; o >>= 1) {
            s += __shfl_xor_sync(~0u, s, o);
            sq += __shfl_xor_sync(~0u, sq, o);
        }
        if (t == 0) { red0[0] = s; red1[0] = sq; }
    }
    __syncthreads();
    float mean = red0[0] * (1.f / DIM);
    float var = red1[0] * (1.f / DIM) - mean * mean;
    float rstd = rsqrtf(var + 1e-5f);
    size_t base = (size_t)row * DIM;
    float vv[3] = {v0, v1, v2};
    #pragma unroll
    for (int c = 0; c < 3; c++) {
        int i = t + c * 256;
        float v = (vv[c] - mean) * rstd * gamma[i] + beta[i];
        __half h = __float2half_rn(v);
        oh[base + i] = h;
        if (ol) ol[base + i] = __float2half_rn(v - __half2float(h));
    }
}

// ---------------- mma.sync GEMM, sized stages + 2 CTA/SM ---------------------
// Stage elems: A = NP3?10240:5120 ; B starts at BOFFE = A-size; stage =
// NP3 ? 20480 : 10240 elems.
template <int NP3> struct Geom {
    static const int BOFFE = NP3 ? 10240 : 5120;          // elems
    static const int STGB = (NP3 ? 20480 : 10240) * 2;    // bytes per stage
};

template <int NP3, int BD>
__device__ __forceinline__ void load_stage(uint32_t sb, int tid,
    const __half* __restrict__ Ah, const __half* __restrict__ Al,
    long aRowBase, long lda, int k0,
    const __half* __restrict__ Bh, const __half* __restrict__ Bl,
    long bOff, long ldb, int col0, int Nb) {
    const int BOFFE = Geom<NP3>::BOFFE;
    #pragma unroll
    for (int half = 0; half < (NP3 ? 2 : 1); half++) {
        const __half* Ab = half ? Al : Ah;
        #pragma unroll
        for (int i = 0; i < 2; i++) {
            int u = tid + i * 256;
            int row = u >> 2, c = u & 3;
            const __half* src = Ab + aRowBase + (long)row * lda + k0 + c * 8;
            CPA(sb + (half * 5120 + row * 40 + c * 8) * 2, src, 16);
        }
    }
    #pragma unroll
    for (int half = 0; half < (NP3 ? 2 : 1); half++) {
        const __half* Bb = half ? Bl : Bh;
        if (BD) {
            #pragma unroll
            for (int i = 0; i < 2; i++) {
                int u = tid + i * 256;
                int row = u >> 2, c = u & 3;
                const __half* src = Bb + bOff + (long)(col0 + row) * ldb + k0 + c * 8;
                CPA(sb + (BOFFE + half * 5120 + row * 40 + c * 8) * 2, src,
                    (col0 + row) < Nb ? 16 : 0);
            }
        } else {
            #pragma unroll
            for (int i = 0; i < 2; i++) {
                int u = tid + i * 256;
                int k = u >> 4, c = u & 15;
                const __half* src = Bb + bOff + (long)(k0 + k) * ldb + col0 + c * 8;
                CPA(sb + (BOFFE + half * 4352 + k * 136 + c * 8) * 2, src,
                    (col0 + c * 8 + 8) <= Nb ? 16 : 0);
            }
        }
    }
    CPCOMMIT();
}

template <int NP3, int BD>
__global__ __launch_bounds__(256, 2)
void hgemm(const __half* __restrict__ Ah, const __half* __restrict__ Al,
           long lda, long a1, long a2,
           const __half* __restrict__ Bh, const __half* __restrict__ Bl,
           long ldb, long b1, long b2,
           float* __restrict__ Cf, __half* __restrict__ Chi, __half* __restrict__ Clo,
           long ldc, long c0, long c1, long c2,
           const float* __restrict__ bias, const float* __restrict__ resid,
           int Nb, int nStore, int nBias, int nkb, float scale, int doGelu) {
    extern __shared__ char smem[];
    uint32_t sbase = smem_u32(smem);
    const int BOFFB = Geom<NP3>::BOFFE * 2;   // byte offset of B region
    const int STGB = Geom<NP3>::STGB;
    int tid = threadIdx.x, wid = tid >> 5, lane = tid & 31;
    int wm = wid >> 1, wn = wid & 1;
    int z = blockIdx.z;
    long aOff = (long)(z >> 3) * a1 + (long)(z & 7) * a2;
    long bOff = (long)(z >> 3) * b1 + (long)(z & 7) * b2;
    long cOff = (long)z * c0 + (long)(z >> 3) * c1 + (long)(z & 7) * c2;
    int row0 = blockIdx.y * 128, col0 = blockIdx.x * 128;
    long aRowBase = aOff + (long)row0 * lda;

    float acc[2][8][4];
    #pragma unroll
    for (int a = 0; a < 2; a++)
        #pragma unroll
        for (int b = 0; b < 8; b++)
            #pragma unroll
            for (int c = 0; c < 4; c++) acc[a][b][c] = 0.f;

    load_stage<NP3, BD>(sbase, tid, Ah, Al, aRowBase, lda, 0, Bh, Bl, bOff, ldb, col0, Nb);

    for (int kb = 0; kb < nkb; kb++) {
        if (kb + 1 < nkb) {
            load_stage<NP3, BD>(sbase + ((kb + 1) & 1) * STGB, tid, Ah, Al,
                                aRowBase, lda, (kb + 1) * 32, Bh, Bl, bOff, ldb, col0, Nb);
            CPWAIT1();
        } else {
            CPWAIT0();
        }
        __syncthreads();
        uint32_t sb = sbase + (kb & 1) * STGB;
        #pragma unroll
        for (int kk = 0; kk < 32; kk += 16) {
            uint32_t ah[2][4], al[2][4];
            #pragma unroll
            for (int mi = 0; mi < 2; mi++) {
                uint32_t ad = sb + (((wm * 32 + mi * 16 + (lane & 15)) * 40 + kk +
                                     (lane >> 4) * 8) << 1);
                LDSM4(ah[mi], ad);
                if (NP3) LDSM4(al[mi], ad + 10240);
            }
            #pragma unroll
            for (int ni = 0; ni < 4; ni++) {
                uint32_t bh[4], bl[4];
                if (BD) {
                    int nrow = wn * 64 + ni * 16 + (lane & 7) + ((lane >> 4) << 3);
                    uint32_t bd = sb + BOFFB + ((nrow * 40 + kk +
                                                 (((lane >> 3) & 1) << 3)) << 1);
                    LDSM4(bh, bd);
                    if (NP3) LDSM4(bl, bd + 10240);
                } else {
                    int kq = kk + (lane & 15);
                    int nq = wn * 64 + ni * 16 + ((lane >> 4) << 3);
                    uint32_t bd = sb + BOFFB + ((kq * 136 + nq) << 1);
                    LDSM4T(bh, bd);
                    if (NP3) LDSM4T(bl, bd + 8704);
                }
                #pragma unroll
                for (int mi = 0; mi < 2; mi++) {
                    MMA(acc[mi][2 * ni], ah[mi], bh[0], bh[1]);
                    MMA(acc[mi][2 * ni + 1], ah[mi], bh[2], bh[3]);
                    if (NP3) {
                        MMA(acc[mi][2 * ni], al[mi], bh[0], bh[1]);
                        MMA(acc[mi][2 * ni + 1], al[mi], bh[2], bh[3]);
                        MMA(acc[mi][2 * ni], ah[mi], bl[0], bl[1]);
                        MMA(acc[mi][2 * ni + 1], ah[mi], bl[2], bl[3]);
                    }
                }
            }
        }
        __syncthreads();
    }

    int row_base = row0 + wm * 32, col_base = col0 + wn * 64;
    #pragma unroll
    for (int mi = 0; mi < 2; mi++)
        #pragma unroll
        for (int g = 0; g < 8; g++)
            #pragma unroll
            for (int rh = 0; rh < 2; rh++) {
                int row = row_base + mi * 16 + rh * 8 + (lane >> 2);
                int col = col_base + g * 8 + (lane & 3) * 2;
                if (col >= nStore) continue;
                float v0 = acc[mi][g][rh * 2] * scale;
                float v1 = acc[mi][g][rh * 2 + 1] * scale;
                if (bias) {
                    if (col < nBias) v0 += bias[col];
                    if (col + 1 < nBias) v1 += bias[col + 1];
                }
                if (doGelu) {
                    v0 = 0.5f * v0 * (1.f + erff(v0 * 0.70710678118654752f));
                    v1 = 0.5f * v1 * (1.f + erff(v1 * 0.70710678118654752f));
                }
                long cr = cOff + (long)row * ldc + col;
                if (resid) {
                    float2 rr = *(const float2*)(resid + cr);
                    v0 += rr.x; v1 += rr.y;
                }
                if (Cf) {
                    *(float2*)(Cf + cr) = make_float2(v0, v1);
                } else {
                    __half h0 = __float2half_rn(v0), h1 = __float2half_rn(v1);
                    *(__half2*)(Chi + cr) = __halves2half2(h0, h1);
                    if (Clo)
                        *(__half2*)(Clo + cr) = __halves2half2(
                            __float2half_rn(v0 - __half2float(h0)),
                            __float2half_rn(v1 - __half2float(h1)));
                }
            }
}

// ---------------- Flash attention (unchanged from R8) ------------------------
#define FQ 0u
#define FST(st) (53248u + (st) * 79872u)
#define FL_SMEM 212992

__device__ __forceinline__ void ldtile(uint32_t dst, const __half* __restrict__ src,
                                       long base, int tid) {
    #pragma unroll
    for (int i = 0; i < 6; i++) {
        int u = tid + i * 256;
        int r = u / 12, c = u - r * 12;
        CPA(dst + r * 208 + c * 16, src + base + (long)r * QKVC + c * 8, 16);
    }
}

__global__ __launch_bounds__(256, 1)
void flash_kernel(const __half* __restrict__ qkvh, const __half* __restrict__ qkvl,
                  __half* __restrict__ att) {
    extern __shared__ char smem[];
    uint32_t sb = smem_u32(smem);
    int tid = threadIdx.x, wid = tid >> 5, lane = tid & 31;
    int b = blockIdx.y >> 3, h = blockIdx.y & 7;
    int q0 = blockIdx.x * 128;
    int qr = wid * 16;
    const float SQ = 9.79795897113271239f;

    long baseQ = (long)(b * NN + q0) * QKVC + h * HD;
    ldtile(sb + FQ, qkvh, baseQ, tid);
    ldtile(sb + FQ + 26624, qkvl, baseQ, tid);
    CPCOMMIT();
    long baseK = (long)(b * NN) * QKVC + DIM + h * HD;
    ldtile(sb + FST(0), qkvh, baseK, tid);
    ldtile(sb + FST(0) + 26624, qkvl, baseK, tid);
    ldtile(sb + FST(0) + 53248, qkvh, baseK + DIM, tid);
    CPCOMMIT();

    float acco[12][4];
    #pragma unroll
    for (int g = 0; g < 12; g++)
        #pragma unroll
        for (int c = 0; c < 4; c++) acco[g][c] = 0.f;
    float m0 = -1e30f, m1 = -1e30f, l0 = 0.f, l1 = 0.f;

    for (int kt = 0; kt < 8; kt++) {
        int st = kt & 1;
        if (kt < 7) {
            long bk = (long)(b * NN + (kt + 1) * 128) * QKVC + DIM + h * HD;
            ldtile(sb + FST(st ^ 1), qkvh, bk, tid);
            ldtile(sb + FST(st ^ 1) + 26624, qkvl, bk, tid);
            ldtile(sb + FST(st ^ 1) + 53248, qkvh, bk + DIM, tid);
            CPCOMMIT();
            CPWAIT1();
        } else {
            CPWAIT0();
        }
        __syncthreads();

        float accs[16][4];
        #pragma unroll
        for (int g = 0; g < 16; g++)
            #pragma unroll
            for (int c = 0; c < 4; c++) accs[g][c] = 0.f;
        uint32_t qb = sb + FQ, kbase = sb + FST(st);
        #pragma unroll
        for (int kc = 0; kc < 6; kc++) {
            uint32_t ah[4], al[4];
            uint32_t ad = qb + ((qr + (lane & 15)) * 104 + kc * 16 + (lane >> 4) * 8) * 2;
            LDSM4(ah, ad);
            LDSM4(al, ad + 26624);
            #pragma unroll
            for (int ni = 0; ni < 8; ni++) {
                uint32_t bh[4], bl[4];
                uint32_t bd = kbase + ((ni * 16 + (lane & 7) + ((lane >> 4) << 3)) * 104 +
                                       kc * 16 + (((lane >> 3) & 1) << 3)) * 2;
                LDSM4(bh, bd);
                LDSM4(bl, bd + 26624);
                MMA(accs[2 * ni], ah, bh[0], bh[1]);
                MMA(accs[2 * ni + 1], ah, bh[2], bh[3]);
                MMA(accs[2 * ni], al, bh[0], bh[1]);
                MMA(accs[2 * ni + 1], al, bh[2], bh[3]);
                MMA(accs[2 * ni], ah, bl[0], bl[1]);
                MMA(accs[2 * ni + 1], ah, bl[2], bl[3]);
            }
        }
        float mx0 = -1e30f, mx1 = -1e30f;
        #pragma unroll
        for (int g = 0; g < 16; g++) {
            mx0 = fmaxf(mx0, fmaxf(accs[g][0], accs[g][1]));
            mx1 = fmaxf(mx1, fmaxf(accs[g][2], accs[g][3]));
        }
        mx0 = fmaxf(mx0, __shfl_xor_sync(~0u, mx0, 1));
        mx0 = fmaxf(mx0, __shfl_xor_sync(~0u, mx0, 2));
        mx1 = fmaxf(mx1, __shfl_xor_sync(~0u, mx1, 1));
        mx1 = fmaxf(mx1, __shfl_xor_sync(~0u, mx1, 2));
        float mn0 = fmaxf(m0, mx0 * SQ), mn1 = fmaxf(m1, mx1 * SQ);
        float cr0 = __expf(m0 - mn0), cr1 = __expf(m1 - mn1);
        m0 = mn0; m1 = mn1;
        float rs0 = 0.f, rs1 = 0.f;
        #pragma unroll
        for (int g = 0; g < 16; g++) {
            float p0 = __expf(fmaf(SQ, accs[g][0], -mn0));
            float p1 = __expf(fmaf(SQ, accs[g][1], -mn0));
            float p2 = __expf(fmaf(SQ, accs[g][2], -mn1));
            float p3 = __expf(fmaf(SQ, accs[g][3], -mn1));
            accs[g][0] = p0; accs[g][1] = p1; accs[g][2] = p2; accs[g][3] = p3;
            rs0 += p0 + p1; rs1 += p2 + p3;
        }
        rs0 += __shfl_xor_sync(~0u, rs0, 1);
        rs0 += __shfl_xor_sync(~0u, rs0, 2);
        rs1 += __shfl_xor_sync(~0u, rs1, 1);
        rs1 += __shfl_xor_sync(~0u, rs1, 2);
        l0 = l0 * cr0 + rs0;
        l1 = l1 * cr1 + rs1;
        #pragma unroll
        for (int g = 0; g < 12; g++) {
            acco[g][0] *= cr0; acco[g][1] *= cr0;
            acco[g][2] *= cr1; acco[g][3] *= cr1;
        }
        uint32_t vb0 = sb + FST(st) + 53248;
        #pragma unroll
        for (int kb2 = 0; kb2 < 8; kb2++) {
            uint32_t pa[4];
            __half2 t;
            t = __floats2half2_rn(accs[2 * kb2][0], accs[2 * kb2][1]);
            pa[0] = *(uint32_t*)&t;
            t = __floats2half2_rn(accs[2 * kb2][2], accs[2 * kb2][3]);
            pa[1] = *(uint32_t*)&t;
            t = __floats2half2_rn(accs[2 * kb2 + 1][0], accs[2 * kb2 + 1][1]);
            pa[2] = *(uint32_t*)&t;
            t = __floats2half2_rn(accs[2 * kb2 + 1][2], accs[2 * kb2 + 1][3]);
            pa[3] = *(uint32_t*)&t;
            #pragma unroll
            for (int nj = 0; nj < 6; nj++) {
                uint32_t vb[4];
                uint32_t vd = vb0 + ((kb2 * 16 + (lane & 15)) * 104 +
                                     nj * 16 + ((lane >> 4) << 3)) * 2;
                LDSM4T(vb, vd);
                MMA(acco[2 * nj], pa, vb[0], vb[1]);
                MMA(acco[2 * nj + 1], pa, vb[2], vb[3]);
            }
        }
        __syncthreads();
    }

    float rl0 = 1.f / l0, rl1 = 1.f / l1;
    long ob = (long)(b * NN + q0 + qr + (lane >> 2)) * DIM + h * HD + (lane & 3) * 2;
    #pragma unroll
    for (int g = 0; g < 12; g++) {
        *(__half2*)(att + ob + g * 8) =
            __floats2half2_rn(acco[g][0] * rl0, acco[g][1] * rl0);
        *(__half2*)(att + ob + 8 * DIM + g * 8) =
            __floats2half2_rn(acco[g][2] * rl1, acco[g][3] * rl1);
    }
}

// ------------------------------- launch --------------------------------------
extern "C" void kernel_launch(void* const* d_in, const int* in_sizes, int n_in,
                              void* d_out, int out_size) {
    const float* x    = (const float*)d_in[0];
    const float* ln_g = (const float*)d_in[1];
    const float* ln_b = (const float*)d_in[2];
    const float* Wqkv = (const float*)d_in[3];
    const float* bqkv = (const float*)d_in[4];
    const float* W0   = (const float*)d_in[5];
    const float* b0   = (const float*)d_in[6];
    const float* W1   = (const float*)d_in[7];
    const float* b1   = (const float*)d_in[8];
    const float* W2   = (const float*)d_in[9];
    const float* b2   = (const float*)d_in[10];
    float* out = (float*)d_out;

    const int SM3 = 2 * Geom<1>::STGB;   // 81920
    const int SM1 = 2 * Geom<0>::STGB;   // 40960
    cudaFuncSetAttribute(hgemm<1, 0>, cudaFuncAttributeMaxDynamicSharedMemorySize, SM3);
    cudaFuncSetAttribute(hgemm<0, 0>, cudaFuncAttributeMaxDynamicSharedMemorySize, SM1);
    cudaFuncSetAttribute(flash_kernel, cudaFuncAttributeMaxDynamicSharedMemorySize, FL_SMEM);

    __half *yh, *yl, *wqh, *wql, *qkvh, *qkvl, *att, *l2, *w0, *w1, *w2, *hb;
    float *z;
    cudaGetSymbolAddress((void**)&yh, g_yh);   cudaGetSymbolAddress((void**)&yl, g_yl);
    cudaGetSymbolAddress((void**)&wqh, g_wqh); cudaGetSymbolAddress((void**)&wql, g_wql);
    cudaGetSymbolAddress((void**)&qkvh, g_qkvh); cudaGetSymbolAddress((void**)&qkvl, g_qkvl);
    cudaGetSymbolAddress((void**)&att, g_att);
    cudaGetSymbolAddress((void**)&z, g_z);
    cudaGetSymbolAddress((void**)&l2, g_l2);
    cudaGetSymbolAddress((void**)&w0, g_w0);
    cudaGetSymbolAddress((void**)&w1, g_w1);
    cudaGetSymbolAddress((void**)&w2, g_w2);
    cudaGetSymbolAddress((void**)&hb, g_h);

    split4_kernel<<<SEG0 + SEG1 + SEG2 + SEG3, 256>>>(Wqkv, wqh, wql, W0, w0, W1, w1, W2, w2);
    ln_split_kernel<<<ROWS, 256>>>(x, ln_g, ln_b, yh, yl);
    hgemm<1, 0><<<dim3(12, 64, 1), 256, SM3>>>(
        yh, yl, DIM, 0, 0, wqh, wql, QKVC, 0, 0,
        nullptr, qkvh, qkvl, QKVC, 0, 0, 0,
        bqkv, nullptr, 1536, 1536, 1536, 24, 1.f, 0);
    hgemm<0, 0><<<dim3(6, 64, 1), 256, SM1>>>(
        yh, nullptr, DIM, 0, 0, wqh + 1536, nullptr, QKVC, 0, 0,
        nullptr, qkvh + 1536, nullptr, QKVC, 0, 0, 0,
        bqkv + 1536, nullptr, 768, 768, 768, 24, 1.f, 0);
    flash_kernel<<<dim3(8, 64), 256, FL_SMEM>>>(qkvh, qkvl, att);
    hgemm<0, 0><<<dim3(6, 64, 1), 256, SM1>>>(
        att, nullptr, DIM, 0, 0, w0, nullptr, DIM, 0, 0,
        z, nullptr, nullptr, DIM, 0, 0, 0,
        b0, x, DIM, DIM, DIM, 24, 1.f, 0);
    ln_split_kernel<<<ROWS, 256>>>(z, ln_g, ln_b, l2, nullptr);
    hgemm<0, 0><<<dim3(12, 64, 1), 256, SM1>>>(
        l2, nullptr, DIM, 0, 0, w1, nullptr, HPAD, 0, 0,
        nullptr, hb, nullptr, HPAD, 0, 0, 0,
        b1, nullptr, HPAD, HPAD, HIDDEN, 24, 1.f, 1);
    hgemm<0, 0><<<dim3(6, 64, 1), 256, SM1>>>(
        hb, nullptr, HPAD, 0, 0, w2, nullptr, DIM, 0, 0,
        out, nullptr, nullptr, DIM, 0, 0, 0,
        b2, z, DIM, DIM, DIM, 47, 1.f, 0);
}

// round 12
// speedup vs baseline: 5.7079x; 1.0456x over previous
#include <cuda_runtime.h>
#include <cuda_fp16.h>
#include <math.h>
#include <stdint.h>

#define BB 8
#define NN 1024
#define DIM 768
#define HEADS 8
#define HD 96
#define HIDDEN 1500
#define HPAD 1536
#define ROWS (BB * NN)
#define QKVC (3 * DIM)
#define PAD 64

__device__ __forceinline__ uint32_t smem_u32(const void* p) {
    uint32_t r;
    asm("{ .reg .u64 t; cvta.to.shared.u64 t, %1; cvt.u32.u64 %0, t; }" : "=r"(r) : "l"(p));
    return r;
}
#define CPA(dst, src, p) asm volatile("cp.async.cg.shared.global [%0], [%1], 16, %2;" :: "r"(dst), "l"(src), "r"(p) : "memory")
#define CPCOMMIT() asm volatile("cp.async.commit_group;" ::: "memory")
#define CPWAIT2() asm volatile("cp.async.wait_group 2;" ::: "memory")
#define CPWAIT1() asm volatile("cp.async.wait_group 1;" ::: "memory")
#define CPWAIT0() asm volatile("cp.async.wait_group 0;" ::: "memory")
#define LDSM4(r, a) asm volatile("ldmatrix.sync.aligned.m8n8.x4.shared.b16 {%0,%1,%2,%3}, [%4];" \
    : "=r"((r)[0]), "=r"((r)[1]), "=r"((r)[2]), "=r"((r)[3]) : "r"(a))
#define LDSM4T(r, a) asm volatile("ldmatrix.sync.aligned.m8n8.x4.trans.shared.b16 {%0,%1,%2,%3}, [%4];" \
    : "=r"((r)[0]), "=r"((r)[1]), "=r"((r)[2]), "=r"((r)[3]) : "r"(a))
#define MMA(c, a, b0, b1) asm volatile( \
    "mma.sync.aligned.m16n8k16.row.col.f32.f16.f16.f32 {%0,%1,%2,%3}, {%4,%5,%6,%7}, {%8,%9}, {%0,%1,%2,%3};" \
    : "+f"((c)[0]), "+f"((c)[1]), "+f"((c)[2]), "+f"((c)[3]) \
    : "r"((a)[0]), "r"((a)[1]), "r"((a)[2]), "r"((a)[3]), "r"(b0), "r"(b1))

// ------------------------------ scratch -------------------------------------
__device__ __half g_yh[ROWS * DIM + PAD], g_yl[ROWS * DIM + PAD];
__device__ __half g_wqh[DIM * QKVC + PAD], g_wql[DIM * QKVC + PAD];
__device__ __half g_qkvh[ROWS * QKVC + PAD], g_qkvl[ROWS * QKVC + PAD];
__device__ __half g_att[ROWS * DIM + PAD];
__device__ float  g_z[ROWS * DIM + PAD];
__device__ __half g_l2[ROWS * DIM + PAD];
__device__ __half g_w0[DIM * DIM + PAD];
__device__ __half g_w1[DIM * HPAD + PAD];
__device__ __half g_w2[HPAD * DIM + PAD];
__device__ __half g_h[ROWS * HPAD + PAD];

// ---- one kernel splitting all 4 weights ------------------------------------
#define SEG0 6912                    // wq 768*2304 /256
#define SEG1 2304                    // w0 768*768 /256
#define SEG2 4608                    // w1 768*1536 /256
#define SEG3 4608                    // w2 1536*768 /256
__global__ void split4_kernel(const float* __restrict__ wq, __half* __restrict__ wqh,
                              __half* __restrict__ wql,
                              const float* __restrict__ w0, __half* __restrict__ w0h,
                              const float* __restrict__ w1, __half* __restrict__ w1h,
                              const float* __restrict__ w2, __half* __restrict__ w2h) {
    int blk = blockIdx.x;
    int t = threadIdx.x;
    if (blk < SEG0) {
        int i = blk * 256 + t;
        float v = wq[i];
        __half hh = __float2half_rn(v);
        wqh[i] = hh;
        wql[i] = __float2half_rn(v - __half2float(hh));
    } else if (blk < SEG0 + SEG1) {
        int i = (blk - SEG0) * 256 + t;
        w0h[i] = __float2half_rn(w0[i]);
    } else if (blk < SEG0 + SEG1 + SEG2) {
        int i = (blk - SEG0 - SEG1) * 256 + t;
        int r = i / HPAD, c = i - r * HPAD;
        w1h[i] = __float2half_rn(c < HIDDEN ? w1[(size_t)r * HIDDEN + c] : 0.f);
    } else {
        int i = (blk - SEG0 - SEG1 - SEG2) * 256 + t;
        int r = i / DIM, c = i - r * DIM;
        w2h[i] = __float2half_rn(r < HIDDEN ? w2[(size_t)r * DIM + c] : 0.f);
    }
}

__global__ void ln_split_kernel(const float* __restrict__ in,
                                const float* __restrict__ gamma,
                                const float* __restrict__ beta,
                                __half* __restrict__ oh, __half* __restrict__ ol) {
    int row = blockIdx.x, t = threadIdx.x;
    const float* px = in + (size_t)row * DIM;
    float v0 = px[t], v1 = px[t + 256], v2 = px[t + 512];
    float s = v0 + v1 + v2, sq = v0 * v0 + v1 * v1 + v2 * v2;
    __shared__ float red0[8], red1[8];
    #pragma unroll
    for (int o = 16; o; o >>= 1) {
        s += __shfl_xor_sync(~0u, s, o);
        sq += __shfl_xor_sync(~0u, sq, o);
    }
    if ((t & 31) == 0) { red0[t >> 5] = s; red1[t >> 5] = sq; }
    __syncthreads();
    if (t < 32) {
        s = (t < 8) ? red0[t] : 0.f;
        sq = (t < 8) ? red1[t] : 0.f;
        #pragma unroll
        for (int o = 4; o; o >>= 1) {
            s += __shfl_xor_sync(~0u, s, o);
            sq += __shfl_xor_sync(~0u, sq, o);
        }
        if (t == 0) { red0[0] = s; red1[0] = sq; }
    }
    __syncthreads();
    float mean = red0[0] * (1.f / DIM);
    float var = red1[0] * (1.f / DIM) - mean * mean;
    float rstd = rsqrtf(var + 1e-5f);
    size_t base = (size_t)row * DIM;
    float vv[3] = {v0, v1, v2};
    #pragma unroll
    for (int c = 0; c < 3; c++) {
        int i = t + c * 256;
        float v = (vv[c] - mean) * rstd * gamma[i] + beta[i];
        __half h = __float2half_rn(v);
        oh[base + i] = h;
        if (ol) ol[base + i] = __float2half_rn(v - __half2float(h));
    }
}

// ======== NP3 GEMM (QKV only): BK=32, 2-stage (unchanged mainloop) ===========
#define STG3B (20480 * 2)
__device__ __forceinline__ void load_stage3(uint32_t sb, int tid,
    const __half* __restrict__ Ah, const __half* __restrict__ Al,
    long aRowBase, long lda, int k0,
    const __half* __restrict__ Bh, const __half* __restrict__ Bl,
    long ldb, int col0) {
    #pragma unroll
    for (int half = 0; half < 2; half++) {
        const __half* Ab = half ? Al : Ah;
        #pragma unroll
        for (int i = 0; i < 2; i++) {
            int u = tid + i * 256;
            int row = u >> 2, c = u & 3;
            CPA(sb + (half * 5120 + row * 40 + c * 8) * 2,
                Ab + aRowBase + (long)row * lda + k0 + c * 8, 16);
        }
    }
    #pragma unroll
    for (int half = 0; half < 2; half++) {
        const __half* Bb = half ? Bl : Bh;
        #pragma unroll
        for (int i = 0; i < 2; i++) {
            int u = tid + i * 256;
            int k = u >> 4, c = u & 15;
            CPA(sb + (10240 + half * 4352 + k * 136 + c * 8) * 2,
                Bb + (long)(k0 + k) * ldb + col0 + c * 8, 16);
        }
    }
    CPCOMMIT();
}

__global__ __launch_bounds__(256, 2)
void hgemm3(const __half* __restrict__ Ah, const __half* __restrict__ Al, long lda,
            const __half* __restrict__ Bh, const __half* __restrict__ Bl, long ldb,
            __half* __restrict__ Chi, __half* __restrict__ Clo, long ldc,
            const float* __restrict__ bias, int nkb) {
    extern __shared__ char smem[];
    uint32_t sbase = smem_u32(smem);
    int tid = threadIdx.x, wid = tid >> 5, lane = tid & 31;
    int wm = wid >> 1, wn = wid & 1;
    int row0 = blockIdx.y * 128, col0 = blockIdx.x * 128;
    long aRowBase = (long)row0 * lda;

    float acc[2][8][4];
    #pragma unroll
    for (int a = 0; a < 2; a++)
        #pragma unroll
        for (int b = 0; b < 8; b++)
            #pragma unroll
            for (int c = 0; c < 4; c++) acc[a][b][c] = 0.f;

    load_stage3(sbase, tid, Ah, Al, aRowBase, lda, 0, Bh, Bl, ldb, col0);
    for (int kb = 0; kb < nkb; kb++) {
        if (kb + 1 < nkb) {
            load_stage3(sbase + ((kb + 1) & 1) * STG3B, tid, Ah, Al, aRowBase, lda,
                        (kb + 1) * 32, Bh, Bl, ldb, col0);
            CPWAIT1();
        } else {
            CPWAIT0();
        }
        __syncthreads();
        uint32_t sb = sbase + (kb & 1) * STG3B;
        #pragma unroll
        for (int kk = 0; kk < 32; kk += 16) {
            uint32_t ah[2][4], al[2][4];
            #pragma unroll
            for (int mi = 0; mi < 2; mi++) {
                uint32_t ad = sb + (((wm * 32 + mi * 16 + (lane & 15)) * 40 + kk +
                                     (lane >> 4) * 8) << 1);
                LDSM4(ah[mi], ad);
                LDSM4(al[mi], ad + 10240);
            }
            #pragma unroll
            for (int ni = 0; ni < 4; ni++) {
                uint32_t bh[4], bl[4];
                int kq = kk + (lane & 15);
                int nq = wn * 64 + ni * 16 + ((lane >> 4) << 3);
                uint32_t bd = sb + 20480 + ((kq * 136 + nq) << 1);
                LDSM4T(bh, bd);
                LDSM4T(bl, bd + 8704);
                #pragma unroll
                for (int mi = 0; mi < 2; mi++) {
                    MMA(acc[mi][2 * ni], ah[mi], bh[0], bh[1]);
                    MMA(acc[mi][2 * ni + 1], ah[mi], bh[2], bh[3]);
                    MMA(acc[mi][2 * ni], al[mi], bh[0], bh[1]);
                    MMA(acc[mi][2 * ni + 1], al[mi], bh[2], bh[3]);
                    MMA(acc[mi][2 * ni], ah[mi], bl[0], bl[1]);
                    MMA(acc[mi][2 * ni + 1], ah[mi], bl[2], bl[3]);
                }
            }
        }
        __syncthreads();
    }
    int row_base = row0 + wm * 32, col_base = col0 + wn * 64;
    #pragma unroll
    for (int mi = 0; mi < 2; mi++)
        #pragma unroll
        for (int g = 0; g < 8; g++)
            #pragma unroll
            for (int rh = 0; rh < 2; rh++) {
                int row = row_base + mi * 16 + rh * 8 + (lane >> 2);
                int col = col_base + g * 8 + (lane & 3) * 2;
                float v0 = acc[mi][g][rh * 2] + bias[col];
                float v1 = acc[mi][g][rh * 2 + 1] + bias[col + 1];
                long cr = (long)row * ldc + col;
                __half h0 = __float2half_rn(v0), h1 = __float2half_rn(v1);
                *(__half2*)(Chi + cr) = __halves2half2(h0, h1);
                *(__half2*)(Clo + cr) = __halves2half2(
                    __float2half_rn(v0 - __half2float(h0)),
                    __float2half_rn(v1 - __half2float(h1)));
            }
}

// ======== NP1 GEMM: BK=64, 3-stage ring, prefetch-before-wait ================
// stage elems: A 128x72=9216 ; B 64x136=8704 -> 17920 elems = 35840 B
#define STG1B 35840
#define SM1 (3 * STG1B)
__device__ __forceinline__ void load_stage1(uint32_t sb, int tid,
    const __half* __restrict__ A, long aRowBase, long lda, int k0,
    const __half* __restrict__ B, long ldb, int col0) {
    #pragma unroll
    for (int i = 0; i < 4; i++) {
        int u = tid + i * 256;
        int row = u >> 3, c = u & 7;
        CPA(sb + (row * 72 + c * 8) * 2, A + aRowBase + (long)row * lda + k0 + c * 8, 16);
    }
    #pragma unroll
    for (int i = 0; i < 4; i++) {
        int u = tid + i * 256;
        int k = u >> 4, c = u & 15;
        CPA(sb + (9216 + k * 136 + c * 8) * 2, B + (long)(k0 + k) * ldb + col0 + c * 8, 16);
    }
    CPCOMMIT();
}

__global__ __launch_bounds__(256, 2)
void hgemm1(const __half* __restrict__ A, long lda,
            const __half* __restrict__ B, long ldb,
            float* __restrict__ Cf, __half* __restrict__ Ch, long ldc,
            const float* __restrict__ bias, const float* __restrict__ resid,
            int nBias, int nkb, int doGelu) {
    extern __shared__ char smem[];
    uint32_t sbase = smem_u32(smem);
    int tid = threadIdx.x, wid = tid >> 5, lane = tid & 31;
    int wm = wid >> 1, wn = wid & 1;
    int row0 = blockIdx.y * 128, col0 = blockIdx.x * 128;
    long aRowBase = (long)row0 * lda;

    float acc[2][8][4];
    #pragma unroll
    for (int a = 0; a < 2; a++)
        #pragma unroll
        for (int b = 0; b < 8; b++)
            #pragma unroll
            for (int c = 0; c < 4; c++) acc[a][b][c] = 0.f;

    load_stage1(sbase, tid, A, aRowBase, lda, 0, B, ldb, col0);
    if (nkb > 1) load_stage1(sbase + STG1B, tid, A, aRowBase, lda, 64, B, ldb, col0);

    int st = 0;
    for (int kb = 0; kb < nkb; kb++) {
        // prefetch stage kb+2 (buffer freed at kb-1, protected by bottom barrier)
        if (kb + 2 < nkb) {
            int ps = (st + 2) % 3;
            load_stage1(sbase + ps * STG1B, tid, A, aRowBase, lda, (kb + 2) * 64,
                        B, ldb, col0);
        }
        int rem = nkb - kb;
        if (rem >= 3) { CPWAIT2(); } else if (rem == 2) { CPWAIT1(); } else { CPWAIT0(); }
        __syncthreads();
        uint32_t sb = sbase + st * STG1B;
        #pragma unroll
        for (int kk = 0; kk < 64; kk += 16) {
            uint32_t ah[2][4];
            #pragma unroll
            for (int mi = 0; mi < 2; mi++) {
                uint32_t ad = sb + (((wm * 32 + mi * 16 + (lane & 15)) * 72 + kk +
                                     (lane >> 4) * 8) << 1);
                LDSM4(ah[mi], ad);
            }
            #pragma unroll
            for (int ni = 0; ni < 4; ni++) {
                uint32_t bh[4];
                int kq = kk + (lane & 15);
                int nq = wn * 64 + ni * 16 + ((lane >> 4) << 3);
                uint32_t bd = sb + ((9216 + kq * 136 + nq) << 1);
                LDSM4T(bh, bd);
                #pragma unroll
                for (int mi = 0; mi < 2; mi++) {
                    MMA(acc[mi][2 * ni], ah[mi], bh[0], bh[1]);
                    MMA(acc[mi][2 * ni + 1], ah[mi], bh[2], bh[3]);
                }
            }
        }
        __syncthreads();
        st++; if (st == 3) st = 0;
    }

    int row_base = row0 + wm * 32, col_base = col0 + wn * 64;
    #pragma unroll
    for (int mi = 0; mi < 2; mi++)
        #pragma unroll
        for (int g = 0; g < 8; g++)
            #pragma unroll
            for (int rh = 0; rh < 2; rh++) {
                int row = row_base + mi * 16 + rh * 8 + (lane >> 2);
                int col = col_base + g * 8 + (lane & 3) * 2;
                float v0 = acc[mi][g][rh * 2];
                float v1 = acc[mi][g][rh * 2 + 1];
                if (col < nBias) v0 += bias[col];
                if (col + 1 < nBias) v1 += bias[col + 1];
                if (doGelu) {
                    v0 = 0.5f * v0 * (1.f + erff(v0 * 0.70710678118654752f));
                    v1 = 0.5f * v1 * (1.f + erff(v1 * 0.70710678118654752f));
                }
                long cr = (long)row * ldc + col;
                if (resid) {
                    float2 rr = *(const float2*)(resid + cr);
                    v0 += rr.x; v1 += rr.y;
                }
                if (Cf) *(float2*)(Cf + cr) = make_float2(v0, v1);
                else *(__half2*)(Ch + cr) = __floats2half2_rn(v0, v1);
            }
}

// ---------------- Flash attention (unchanged from R8) ------------------------
#define FQ 0u
#define FST(st) (53248u + (st) * 79872u)
#define FL_SMEM 212992

__device__ __forceinline__ void ldtile(uint32_t dst, const __half* __restrict__ src,
                                       long base, int tid) {
    #pragma unroll
    for (int i = 0; i < 6; i++) {
        int u = tid + i * 256;
        int r = u / 12, c = u - r * 12;
        CPA(dst + r * 208 + c * 16, src + base + (long)r * QKVC + c * 8, 16);
    }
}

__global__ __launch_bounds__(256, 1)
void flash_kernel(const __half* __restrict__ qkvh, const __half* __restrict__ qkvl,
                  __half* __restrict__ att) {
    extern __shared__ char smem[];
    uint32_t sb = smem_u32(smem);
    int tid = threadIdx.x, wid = tid >> 5, lane = tid & 31;
    int b = blockIdx.y >> 3, h = blockIdx.y & 7;
    int q0 = blockIdx.x * 128;
    int qr = wid * 16;
    const float SQ = 9.79795897113271239f;

    long baseQ = (long)(b * NN + q0) * QKVC + h * HD;
    ldtile(sb + FQ, qkvh, baseQ, tid);
    ldtile(sb + FQ + 26624, qkvl, baseQ, tid);
    CPCOMMIT();
    long baseK = (long)(b * NN) * QKVC + DIM + h * HD;
    ldtile(sb + FST(0), qkvh, baseK, tid);
    ldtile(sb + FST(0) + 26624, qkvl, baseK, tid);
    ldtile(sb + FST(0) + 53248, qkvh, baseK + DIM, tid);
    CPCOMMIT();

    float acco[12][4];
    #pragma unroll
    for (int g = 0; g < 12; g++)
        #pragma unroll
        for (int c = 0; c < 4; c++) acco[g][c] = 0.f;
    float m0 = -1e30f, m1 = -1e30f, l0 = 0.f, l1 = 0.f;

    for (int kt = 0; kt < 8; kt++) {
        int st = kt & 1;
        if (kt < 7) {
            long bk = (long)(b * NN + (kt + 1) * 128) * QKVC + DIM + h * HD;
            ldtile(sb + FST(st ^ 1), qkvh, bk, tid);
            ldtile(sb + FST(st ^ 1) + 26624, qkvl, bk, tid);
            ldtile(sb + FST(st ^ 1) + 53248, qkvh, bk + DIM, tid);
            CPCOMMIT();
            CPWAIT1();
        } else {
            CPWAIT0();
        }
        __syncthreads();

        float accs[16][4];
        #pragma unroll
        for (int g = 0; g < 16; g++)
            #pragma unroll
            for (int c = 0; c < 4; c++) accs[g][c] = 0.f;
        uint32_t qb = sb + FQ, kbase = sb + FST(st);
        #pragma unroll
        for (int kc = 0; kc < 6; kc++) {
            uint32_t ah[4], al[4];
            uint32_t ad = qb + ((qr + (lane & 15)) * 104 + kc * 16 + (lane >> 4) * 8) * 2;
            LDSM4(ah, ad);
            LDSM4(al, ad + 26624);
            #pragma unroll
            for (int ni = 0; ni < 8; ni++) {
                uint32_t bh[4], bl[4];
                uint32_t bd = kbase + ((ni * 16 + (lane & 7) + ((lane >> 4) << 3)) * 104 +
                                       kc * 16 + (((lane >> 3) & 1) << 3)) * 2;
                LDSM4(bh, bd);
                LDSM4(bl, bd + 26624);
                MMA(accs[2 * ni], ah, bh[0], bh[1]);
                MMA(accs[2 * ni + 1], ah, bh[2], bh[3]);
                MMA(accs[2 * ni], al, bh[0], bh[1]);
                MMA(accs[2 * ni + 1], al, bh[2], bh[3]);
                MMA(accs[2 * ni], ah, bl[0], bl[1]);
                MMA(accs[2 * ni + 1], ah, bl[2], bl[3]);
            }
        }
        float mx0 = -1e30f, mx1 = -1e30f;
        #pragma unroll
        for (int g = 0; g < 16; g++) {
            mx0 = fmaxf(mx0, fmaxf(accs[g][0], accs[g][1]));
            mx1 = fmaxf(mx1, fmaxf(accs[g][2], accs[g][3]));
        }
        mx0 = fmaxf(mx0, __shfl_xor_sync(~0u, mx0, 1));
        mx0 = fmaxf(mx0, __shfl_xor_sync(~0u, mx0, 2));
        mx1 = fmaxf(mx1, __shfl_xor_sync(~0u, mx1, 1));
        mx1 = fmaxf(mx1, __shfl_xor_sync(~0u, mx1, 2));
        float mn0 = fmaxf(m0, mx0 * SQ), mn1 = fmaxf(m1, mx1 * SQ);
        float cr0 = __expf(m0 - mn0), cr1 = __expf(m1 - mn1);
        m0 = mn0; m1 = mn1;
        float rs0 = 0.f, rs1 = 0.f;
        #pragma unroll
        for (int g = 0; g < 16; g++) {
            float p0 = __expf(fmaf(SQ, accs[g][0], -mn0));
            float p1 = __expf(fmaf(SQ, accs[g][1], -mn0));
            float p2 = __expf(fmaf(SQ, accs[g][2], -mn1));
            float p3 = __expf(fmaf(SQ, accs[g][3], -mn1));
            accs[g][0] = p0; accs[g][1] = p1; accs[g][2] = p2; accs[g][3] = p3;
            rs0 += p0 + p1; rs1 += p2 + p3;
        }
        rs0 += __shfl_xor_sync(~0u, rs0, 1);
        rs0 += __shfl_xor_sync(~0u, rs0, 2);
        rs1 += __shfl_xor_sync(~0u, rs1, 1);
        rs1 += __shfl_xor_sync(~0u, rs1, 2);
        l0 = l0 * cr0 + rs0;
        l1 = l1 * cr1 + rs1;
        #pragma unroll
        for (int g = 0; g < 12; g++) {
            acco[g][0] *= cr0; acco[g][1] *= cr0;
            acco[g][2] *= cr1; acco[g][3] *= cr1;
        }
        uint32_t vb0 = sb + FST(st) + 53248;
        #pragma unroll
        for (int kb2 = 0; kb2 < 8; kb2++) {
            uint32_t pa[4];
            __half2 t;
            t = __floats2half2_rn(accs[2 * kb2][0], accs[2 * kb2][1]);
            pa[0] = *(uint32_t*)&t;
            t = __floats2half2_rn(accs[2 * kb2][2], accs[2 * kb2][3]);
            pa[1] = *(uint32_t*)&t;
            t = __floats2half2_rn(accs[2 * kb2 + 1][0], accs[2 * kb2 + 1][1]);
            pa[2] = *(uint32_t*)&t;
            t = __floats2half2_rn(accs[2 * kb2 + 1][2], accs[2 * kb2 + 1][3]);
            pa[3] = *(uint32_t*)&t;
            #pragma unroll
            for (int nj = 0; nj < 6; nj++) {
                uint32_t vb[4];
                uint32_t vd = vb0 + ((kb2 * 16 + (lane & 15)) * 104 +
                                     nj * 16 + ((lane >> 4) << 3)) * 2;
                LDSM4T(vb, vd);
                MMA(acco[2 * nj], pa, vb[0], vb[1]);
                MMA(acco[2 * nj + 1], pa, vb[2], vb[3]);
            }
        }
        __syncthreads();
    }

    float rl0 = 1.f / l0, rl1 = 1.f / l1;
    long ob = (long)(b * NN + q0 + qr + (lane >> 2)) * DIM + h * HD + (lane & 3) * 2;
    #pragma unroll
    for (int g = 0; g < 12; g++) {
        *(__half2*)(att + ob + g * 8) =
            __floats2half2_rn(acco[g][0] * rl0, acco[g][1] * rl0);
        *(__half2*)(att + ob + 8 * DIM + g * 8) =
            __floats2half2_rn(acco[g][2] * rl1, acco[g][3] * rl1);
    }
}

// ------------------------------- launch --------------------------------------
extern "C" void kernel_launch(void* const* d_in, const int* in_sizes, int n_in,
                              void* d_out, int out_size) {
    const float* x    = (const float*)d_in[0];
    const float* ln_g = (const float*)d_in[1];
    const float* ln_b = (const float*)d_in[2];
    const float* Wqkv = (const float*)d_in[3];
    const float* bqkv = (const float*)d_in[4];
    const float* W0   = (const float*)d_in[5];
    const float* b0   = (const float*)d_in[6];
    const float* W1   = (const float*)d_in[7];
    const float* b1   = (const float*)d_in[8];
    const float* W2   = (const float*)d_in[9];
    const float* b2   = (const float*)d_in[10];
    float* out = (float*)d_out;

    cudaFuncSetAttribute(hgemm3, cudaFuncAttributeMaxDynamicSharedMemorySize, 2 * STG3B);
    cudaFuncSetAttribute(hgemm1, cudaFuncAttributeMaxDynamicSharedMemorySize, SM1);
    cudaFuncSetAttribute(flash_kernel, cudaFuncAttributeMaxDynamicSharedMemorySize, FL_SMEM);

    __half *yh, *yl, *wqh, *wql, *qkvh, *qkvl, *att, *l2, *w0, *w1, *w2, *hb;
    float *z;
    cudaGetSymbolAddress((void**)&yh, g_yh);   cudaGetSymbolAddress((void**)&yl, g_yl);
    cudaGetSymbolAddress((void**)&wqh, g_wqh); cudaGetSymbolAddress((void**)&wql, g_wql);
    cudaGetSymbolAddress((void**)&qkvh, g_qkvh); cudaGetSymbolAddress((void**)&qkvl, g_qkvl);
    cudaGetSymbolAddress((void**)&att, g_att);
    cudaGetSymbolAddress((void**)&z, g_z);
    cudaGetSymbolAddress((void**)&l2, g_l2);
    cudaGetSymbolAddress((void**)&w0, g_w0);
    cudaGetSymbolAddress((void**)&w1, g_w1);
    cudaGetSymbolAddress((void**)&w2, g_w2);
    cudaGetSymbolAddress((void**)&hb, g_h);

    split4_kernel<<<SEG0 + SEG1 + SEG2 + SEG3, 256>>>(Wqkv, wqh, wql, W0, w0, W1, w1, W2, w2);
    ln_split_kernel<<<ROWS, 256>>>(x, ln_g, ln_b, yh, yl);
    // Q,K = y @ Wqkv[:, :1536] + b  (3-product split output)
    hgemm3<<<dim3(12, 64), 256, 2 * STG3B>>>(
        yh, yl, DIM, wqh, wql, QKVC, qkvh, qkvl, QKVC, bqkv, 24);
    // V = y @ Wqkv[:, 1536:] + b
    hgemm1<<<dim3(6, 64), 256, SM1>>>(
        yh, DIM, wqh + 1536, QKVC, nullptr, qkvh + 1536, QKVC, bqkv + 1536, nullptr,
        768, 12, 0);
    flash_kernel<<<dim3(8, 64), 256, FL_SMEM>>>(qkvh, qkvl, att);
    // z = att @ W0 + b0 + x
    hgemm1<<<dim3(6, 64), 256, SM1>>>(
        att, DIM, w0, DIM, z, nullptr, DIM, b0, x, DIM, 12, 0);
    ln_split_kernel<<<ROWS, 256>>>(z, ln_g, ln_b, l2, nullptr);
    // h = gelu(l2 @ W1 + b1)   (N padded to 1536, zero cols -> gelu(0)=0)
    hgemm1<<<dim3(12, 64), 256, SM1>>>(
        l2, DIM, w1, HPAD, nullptr, hb, HPAD, b1, nullptr, HIDDEN, 12, 1);
    // out = h @ W2 + b2 + z    (K padded to 1536 with zero rows)
    hgemm1<<<dim3(6, 64), 256, SM1>>>(
        hb, HPAD, w2, DIM, out, nullptr, DIM, b2, z, DIM, 24, 0);
}

// round 13
// speedup vs baseline: 5.7634x; 1.0097x over previous
#include <cuda_runtime.h>
#include <cuda_fp16.h>
#include <math.h>
#include <stdint.h>

#define BB 8
#define NN 1024
#define DIM 768
#define HEADS 8
#define HD 96
#define HIDDEN 1500
#define HPAD 1536
#define ROWS (BB * NN)
#define QKVC (3 * DIM)
#define PAD 64

__device__ __forceinline__ uint32_t smem_u32(const void* p) {
    uint32_t r;
    asm("{ .reg .u64 t; cvta.to.shared.u64 t, %1; cvt.u32.u64 %0, t; }" : "=r"(r) : "l"(p));
    return r;
}
#define CPA(dst, src, p) asm volatile("cp.async.cg.shared.global [%0], [%1], 16, %2;" :: "r"(dst), "l"(src), "r"(p) : "memory")
#define CPCOMMIT() asm volatile("cp.async.commit_group;" ::: "memory")
#define CPWAIT2() asm volatile("cp.async.wait_group 2;" ::: "memory")
#define CPWAIT1() asm volatile("cp.async.wait_group 1;" ::: "memory")
#define CPWAIT0() asm volatile("cp.async.wait_group 0;" ::: "memory")
#define LDSM4(r, a) asm volatile("ldmatrix.sync.aligned.m8n8.x4.shared.b16 {%0,%1,%2,%3}, [%4];" \
    : "=r"((r)[0]), "=r"((r)[1]), "=r"((r)[2]), "=r"((r)[3]) : "r"(a))
#define LDSM4T(r, a) asm volatile("ldmatrix.sync.aligned.m8n8.x4.trans.shared.b16 {%0,%1,%2,%3}, [%4];" \
    : "=r"((r)[0]), "=r"((r)[1]), "=r"((r)[2]), "=r"((r)[3]) : "r"(a))
#define MMA(c, a, b0, b1) asm volatile( \
    "mma.sync.aligned.m16n8k16.row.col.f32.f16.f16.f32 {%0,%1,%2,%3}, {%4,%5,%6,%7}, {%8,%9}, {%0,%1,%2,%3};" \
    : "+f"((c)[0]), "+f"((c)[1]), "+f"((c)[2]), "+f"((c)[3]) \
    : "r"((a)[0]), "r"((a)[1]), "r"((a)[2]), "r"((a)[3]), "r"(b0), "r"(b1))
#define CP4(d, s) { (d)[0] = (s)[0]; (d)[1] = (s)[1]; (d)[2] = (s)[2]; (d)[3] = (s)[3]; }

// ------------------------------ scratch -------------------------------------
__device__ __half g_yh[ROWS * DIM + PAD], g_yl[ROWS * DIM + PAD];
__device__ __half g_wqh[DIM * QKVC + PAD], g_wql[DIM * QKVC + PAD];
__device__ __half g_qkvh[ROWS * QKVC + PAD], g_qkvl[ROWS * QKVC + PAD];
__device__ __half g_att[ROWS * DIM + PAD];
__device__ float  g_z[ROWS * DIM + PAD];
__device__ __half g_l2[ROWS * DIM + PAD];
__device__ __half g_w0[DIM * DIM + PAD];
__device__ __half g_w1[DIM * HPAD + PAD];
__device__ __half g_w2[HPAD * DIM + PAD];
__device__ __half g_h[ROWS * HPAD + PAD];
__device__ float  g_b1p[HPAD];

// ---- one kernel splitting all 4 weights + padded b1 -------------------------
#define SEG0 6912
#define SEG1 2304
#define SEG2 4608
#define SEG3 4608
#define SEG4 6
__global__ void split4_kernel(const float* __restrict__ wq, __half* __restrict__ wqh,
                              __half* __restrict__ wql,
                              const float* __restrict__ w0, __half* __restrict__ w0h,
                              const float* __restrict__ w1, __half* __restrict__ w1h,
                              const float* __restrict__ w2, __half* __restrict__ w2h,
                              const float* __restrict__ b1, float* __restrict__ b1p) {
    int blk = blockIdx.x;
    int t = threadIdx.x;
    if (blk < SEG0) {
        int i = blk * 256 + t;
        float v = wq[i];
        __half hh = __float2half_rn(v);
        wqh[i] = hh;
        wql[i] = __float2half_rn(v - __half2float(hh));
    } else if (blk < SEG0 + SEG1) {
        int i = (blk - SEG0) * 256 + t;
        w0h[i] = __float2half_rn(w0[i]);
    } else if (blk < SEG0 + SEG1 + SEG2) {
        int i = (blk - SEG0 - SEG1) * 256 + t;
        int r = i / HPAD, c = i - r * HPAD;
        w1h[i] = __float2half_rn(c < HIDDEN ? w1[(size_t)r * HIDDEN + c] : 0.f);
    } else if (blk < SEG0 + SEG1 + SEG2 + SEG3) {
        int i = (blk - SEG0 - SEG1 - SEG2) * 256 + t;
        int r = i / DIM, c = i - r * DIM;
        w2h[i] = __float2half_rn(r < HIDDEN ? w2[(size_t)r * DIM + c] : 0.f);
    } else {
        int i = (blk - SEG0 - SEG1 - SEG2 - SEG3) * 256 + t;
        b1p[i] = (i < HIDDEN) ? b1[i] : 0.f;
    }
}

__global__ void ln_split_kernel(const float* __restrict__ in,
                                const float* __restrict__ gamma,
                                const float* __restrict__ beta,
                                __half* __restrict__ oh, __half* __restrict__ ol) {
    int row = blockIdx.x, t = threadIdx.x;
    const float* px = in + (size_t)row * DIM;
    float v0 = px[t], v1 = px[t + 256], v2 = px[t + 512];
    float s = v0 + v1 + v2, sq = v0 * v0 + v1 * v1 + v2 * v2;
    __shared__ float red0[8], red1[8];
    #pragma unroll
    for (int o = 16; o; o >>= 1) {
        s += __shfl_xor_sync(~0u, s, o);
        sq += __shfl_xor_sync(~0u, sq, o);
    }
    if ((t & 31) == 0) { red0[t >> 5] = s; red1[t >> 5] = sq; }
    __syncthreads();
    if (t < 32) {
        s = (t < 8) ? red0[t] : 0.f;
        sq = (t < 8) ? red1[t] : 0.f;
        #pragma unroll
        for (int o = 4; o; o >>= 1) {
            s += __shfl_xor_sync(~0u, s, o);
            sq += __shfl_xor_sync(~0u, sq, o);
        }
        if (t == 0) { red0[0] = s; red1[0] = sq; }
    }
    __syncthreads();
    float mean = red0[0] * (1.f / DIM);
    float var = red1[0] * (1.f / DIM) - mean * mean;
    float rstd = rsqrtf(var + 1e-5f);
    size_t base = (size_t)row * DIM;
    float vv[3] = {v0, v1, v2};
    #pragma unroll
    for (int c = 0; c < 3; c++) {
        int i = t + c * 256;
        float v = (vv[c] - mean) * rstd * gamma[i] + beta[i];
        __half h = __float2half_rn(v);
        oh[base + i] = h;
        if (ol) ol[base + i] = __float2half_rn(v - __half2float(h));
    }
}

// ======== NP3 GEMM (QKV only): BK=32, 2-stage (unchanged) ====================
#define STG3B (20480 * 2)
__device__ __forceinline__ void load_stage3(uint32_t sb, int tid,
    const __half* __restrict__ Ah, const __half* __restrict__ Al,
    long aRowBase, long lda, int k0,
    const __half* __restrict__ Bh, const __half* __restrict__ Bl,
    long ldb, int col0) {
    #pragma unroll
    for (int half = 0; half < 2; half++) {
        const __half* Ab = half ? Al : Ah;
        #pragma unroll
        for (int i = 0; i < 2; i++) {
            int u = tid + i * 256;
            int row = u >> 2, c = u & 3;
            CPA(sb + (half * 5120 + row * 40 + c * 8) * 2,
                Ab + aRowBase + (long)row * lda + k0 + c * 8, 16);
        }
    }
    #pragma unroll
    for (int half = 0; half < 2; half++) {
        const __half* Bb = half ? Bl : Bh;
        #pragma unroll
        for (int i = 0; i < 2; i++) {
            int u = tid + i * 256;
            int k = u >> 4, c = u & 15;
            CPA(sb + (10240 + half * 4352 + k * 136 + c * 8) * 2,
                Bb + (long)(k0 + k) * ldb + col0 + c * 8, 16);
        }
    }
    CPCOMMIT();
}

__global__ __launch_bounds__(256, 2)
void hgemm3(const __half* __restrict__ Ah, const __half* __restrict__ Al, long lda,
            const __half* __restrict__ Bh, const __half* __restrict__ Bl, long ldb,
            __half* __restrict__ Chi, __half* __restrict__ Clo, long ldc,
            const float* __restrict__ bias, int nkb) {
    extern __shared__ char smem[];
    uint32_t sbase = smem_u32(smem);
    int tid = threadIdx.x, wid = tid >> 5, lane = tid & 31;
    int wm = wid >> 1, wn = wid & 1;
    int row0 = blockIdx.y * 128, col0 = blockIdx.x * 128;
    long aRowBase = (long)row0 * lda;

    float acc[2][8][4];
    #pragma unroll
    for (int a = 0; a < 2; a++)
        #pragma unroll
        for (int b = 0; b < 8; b++)
            #pragma unroll
            for (int c = 0; c < 4; c++) acc[a][b][c] = 0.f;

    load_stage3(sbase, tid, Ah, Al, aRowBase, lda, 0, Bh, Bl, ldb, col0);
    for (int kb = 0; kb < nkb; kb++) {
        if (kb + 1 < nkb) {
            load_stage3(sbase + ((kb + 1) & 1) * STG3B, tid, Ah, Al, aRowBase, lda,
                        (kb + 1) * 32, Bh, Bl, ldb, col0);
            CPWAIT1();
        } else {
            CPWAIT0();
        }
        __syncthreads();
        uint32_t sb = sbase + (kb & 1) * STG3B;
        #pragma unroll
        for (int kk = 0; kk < 32; kk += 16) {
            uint32_t ah[2][4], al[2][4];
            #pragma unroll
            for (int mi = 0; mi < 2; mi++) {
                uint32_t ad = sb + (((wm * 32 + mi * 16 + (lane & 15)) * 40 + kk +
                                     (lane >> 4) * 8) << 1);
                LDSM4(ah[mi], ad);
                LDSM4(al[mi], ad + 10240);
            }
            #pragma unroll
            for (int ni = 0; ni < 4; ni++) {
                uint32_t bh[4], bl[4];
                int kq = kk + (lane & 15);
                int nq = wn * 64 + ni * 16 + ((lane >> 4) << 3);
                uint32_t bd = sb + 20480 + ((kq * 136 + nq) << 1);
                LDSM4T(bh, bd);
                LDSM4T(bl, bd + 8704);
                #pragma unroll
                for (int mi = 0; mi < 2; mi++) {
                    MMA(acc[mi][2 * ni], ah[mi], bh[0], bh[1]);
                    MMA(acc[mi][2 * ni + 1], ah[mi], bh[2], bh[3]);
                    MMA(acc[mi][2 * ni], al[mi], bh[0], bh[1]);
                    MMA(acc[mi][2 * ni + 1], al[mi], bh[2], bh[3]);
                    MMA(acc[mi][2 * ni], ah[mi], bl[0], bl[1]);
                    MMA(acc[mi][2 * ni + 1], ah[mi], bl[2], bl[3]);
                }
            }
        }
        __syncthreads();
    }
    int row_base = row0 + wm * 32, col_base = col0 + wn * 64;
    #pragma unroll
    for (int mi = 0; mi < 2; mi++)
        #pragma unroll
        for (int g = 0; g < 8; g++)
            #pragma unroll
            for (int rh = 0; rh < 2; rh++) {
                int row = row_base + mi * 16 + rh * 8 + (lane >> 2);
                int col = col_base + g * 8 + (lane & 3) * 2;
                float v0 = acc[mi][g][rh * 2] + bias[col];
                float v1 = acc[mi][g][rh * 2 + 1] + bias[col + 1];
                long cr = (long)row * ldc + col;
                __half h0 = __float2half_rn(v0), h1 = __float2half_rn(v1);
                *(__half2*)(Chi + cr) = __halves2half2(h0, h1);
                *(__half2*)(Clo + cr) = __halves2half2(
                    __float2half_rn(v0 - __half2float(h0)),
                    __float2half_rn(v1 - __half2float(h1)));
            }
}

// ======== NP1 GEMM: BK=64, 3-stage ring, fragment double-buffering ===========
#define STG1B 35840
#define SM1 (3 * STG1B)
__device__ __forceinline__ void load_stage1(uint32_t sb, int tid,
    const __half* __restrict__ A, long aRowBase, long lda, int k0,
    const __half* __restrict__ B, long ldb, int col0) {
    #pragma unroll
    for (int i = 0; i < 4; i++) {
        int u = tid + i * 256;
        int row = u >> 3, c = u & 7;
        CPA(sb + (row * 72 + c * 8) * 2, A + aRowBase + (long)row * lda + k0 + c * 8, 16);
    }
    #pragma unroll
    for (int i = 0; i < 4; i++) {
        int u = tid + i * 256;
        int k = u >> 4, c = u & 15;
        CPA(sb + (9216 + k * 136 + c * 8) * 2, B + (long)(k0 + k) * ldb + col0 + c * 8, 16);
    }
    CPCOMMIT();
}

#define G1_LDA(buf, kkv) { \
    uint32_t ad = sb + (((wm * 32 + (lane & 15)) * 72 + (kkv) + (lane >> 4) * 8) << 1); \
    LDSM4((buf)[0], ad); \
    LDSM4((buf)[1], ad + (16 * 72 * 2)); }
#define G1_LDB(buf, kkv, niv) { \
    int kq = (kkv) + (lane & 15); \
    int nq = wn * 64 + (niv) * 16 + ((lane >> 4) << 3); \
    LDSM4T(buf, sb + ((9216 + kq * 136 + nq) << 1)); }

__global__ __launch_bounds__(256, 2)
void hgemm1(const __half* __restrict__ A, long lda,
            const __half* __restrict__ B, long ldb,
            float* __restrict__ Cf, __half* __restrict__ Ch, long ldc,
            const float* __restrict__ bias, const float* __restrict__ resid,
            int nkb, int doGelu) {
    extern __shared__ char smem[];
    uint32_t sbase = smem_u32(smem);
    int tid = threadIdx.x, wid = tid >> 5, lane = tid & 31;
    int wm = wid >> 1, wn = wid & 1;
    int row0 = blockIdx.y * 128, col0 = blockIdx.x * 128;
    long aRowBase = (long)row0 * lda;

    float acc[2][8][4];
    #pragma unroll
    for (int a = 0; a < 2; a++)
        #pragma unroll
        for (int b = 0; b < 8; b++)
            #pragma unroll
            for (int c = 0; c < 4; c++) acc[a][b][c] = 0.f;

    load_stage1(sbase, tid, A, aRowBase, lda, 0, B, ldb, col0);
    if (nkb > 1) load_stage1(sbase + STG1B, tid, A, aRowBase, lda, 64, B, ldb, col0);

    int st = 0;
    for (int kb = 0; kb < nkb; kb++) {
        if (kb + 2 < nkb) {
            int ps = (st + 2) % 3;
            load_stage1(sbase + ps * STG1B, tid, A, aRowBase, lda, (kb + 2) * 64,
                        B, ldb, col0);
        }
        int rem = nkb - kb;
        if (rem >= 3) { CPWAIT2(); } else if (rem == 2) { CPWAIT1(); } else { CPWAIT0(); }
        __syncthreads();
        uint32_t sb = sbase + st * STG1B;

        uint32_t a_cur[2][4], a_nxt[2][4], b_cur[4], b_nxt[4];
        G1_LDA(a_cur, 0);
        G1_LDB(b_cur, 0, 0);
        #pragma unroll
        for (int j = 0; j < 4; j++) {
            int kk = j * 16;
            if (j < 3) G1_LDA(a_nxt, kk + 16);
            #pragma unroll
            for (int ni = 0; ni < 4; ni++) {
                if (ni < 3) { G1_LDB(b_nxt, kk, ni + 1); }
                else if (j < 3) { G1_LDB(b_nxt, kk + 16, 0); }
                MMA(acc[0][2 * ni], a_cur[0], b_cur[0], b_cur[1]);
                MMA(acc[0][2 * ni + 1], a_cur[0], b_cur[2], b_cur[3]);
                MMA(acc[1][2 * ni], a_cur[1], b_cur[0], b_cur[1]);
                MMA(acc[1][2 * ni + 1], a_cur[1], b_cur[2], b_cur[3]);
                CP4(b_cur, b_nxt);
            }
            CP4(a_cur[0], a_nxt[0]);
            CP4(a_cur[1], a_nxt[1]);
        }
        __syncthreads();
        st++; if (st == 3) st = 0;
    }

    int row_base = row0 + wm * 32, col_base = col0 + wn * 64;
    #pragma unroll
    for (int mi = 0; mi < 2; mi++)
        #pragma unroll
        for (int g = 0; g < 8; g++)
            #pragma unroll
            for (int rh = 0; rh < 2; rh++) {
                int row = row_base + mi * 16 + rh * 8 + (lane >> 2);
                int col = col_base + g * 8 + (lane & 3) * 2;
                float v0 = acc[mi][g][rh * 2] + bias[col];
                float v1 = acc[mi][g][rh * 2 + 1] + bias[col + 1];
                if (doGelu) {
                    v0 = 0.5f * v0 * (1.f + erff(v0 * 0.70710678118654752f));
                    v1 = 0.5f * v1 * (1.f + erff(v1 * 0.70710678118654752f));
                }
                long cr = (long)row * ldc + col;
                if (resid) {
                    float2 rr = *(const float2*)(resid + cr);
                    v0 += rr.x; v1 += rr.y;
                }
                if (Cf) *(float2*)(Cf + cr) = make_float2(v0, v1);
                else *(__half2*)(Ch + cr) = __floats2half2_rn(v0, v1);
            }
}

// ---------------- Flash attention: fragment-pipelined ------------------------
#define FQ 0u
#define FST(st) (53248u + (st) * 79872u)
#define FL_SMEM 212992

__device__ __forceinline__ void ldtile(uint32_t dst, const __half* __restrict__ src,
                                       long base, int tid) {
    #pragma unroll
    for (int i = 0; i < 6; i++) {
        int u = tid + i * 256;
        int r = u / 12, c = u - r * 12;
        CPA(dst + r * 208 + c * 16, src + base + (long)r * QKVC + c * 8, 16);
    }
}

#define FL_LDA(bh_, bl_, kcv) { \
    uint32_t ad = qb + ((qr + (lane & 15)) * 104 + (kcv) * 16 + (lane >> 4) * 8) * 2; \
    LDSM4(bh_, ad); \
    LDSM4(bl_, ad + 26624); }
#define FL_LDB(bh_, bl_, kcv, niv) { \
    uint32_t bd = kbase + (((niv) * 16 + (lane & 7) + ((lane >> 4) << 3)) * 104 + \
                           (kcv) * 16 + (((lane >> 3) & 1) << 3)) * 2; \
    LDSM4(bh_, bd); \
    LDSM4(bl_, bd + 26624); }
#define FL_LDV(buf, kb2v, njv) { \
    uint32_t vd = vb0 + (((kb2v) * 16 + (lane & 15)) * 104 + \
                         (njv) * 16 + ((lane >> 4) << 3)) * 2; \
    LDSM4T(buf, vd); }

__global__ __launch_bounds__(256, 1)
void flash_kernel(const __half* __restrict__ qkvh, const __half* __restrict__ qkvl,
                  __half* __restrict__ att) {
    extern __shared__ char smem[];
    uint32_t sb = smem_u32(smem);
    int tid = threadIdx.x, wid = tid >> 5, lane = tid & 31;
    int b = blockIdx.y >> 3, h = blockIdx.y & 7;
    int q0 = blockIdx.x * 128;
    int qr = wid * 16;
    const float SQ = 9.79795897113271239f;

    long baseQ = (long)(b * NN + q0) * QKVC + h * HD;
    ldtile(sb + FQ, qkvh, baseQ, tid);
    ldtile(sb + FQ + 26624, qkvl, baseQ, tid);
    CPCOMMIT();
    long baseK = (long)(b * NN) * QKVC + DIM + h * HD;
    ldtile(sb + FST(0), qkvh, baseK, tid);
    ldtile(sb + FST(0) + 26624, qkvl, baseK, tid);
    ldtile(sb + FST(0) + 53248, qkvh, baseK + DIM, tid);
    CPCOMMIT();

    float acco[12][4];
    #pragma unroll
    for (int g = 0; g < 12; g++)
        #pragma unroll
        for (int c = 0; c < 4; c++) acco[g][c] = 0.f;
    float m0 = -1e30f, m1 = -1e30f, l0 = 0.f, l1 = 0.f;

    for (int kt = 0; kt < 8; kt++) {
        int st = kt & 1;
        if (kt < 7) {
            long bk = (long)(b * NN + (kt + 1) * 128) * QKVC + DIM + h * HD;
            ldtile(sb + FST(st ^ 1), qkvh, bk, tid);
            ldtile(sb + FST(st ^ 1) + 26624, qkvl, bk, tid);
            ldtile(sb + FST(st ^ 1) + 53248, qkvh, bk + DIM, tid);
            CPCOMMIT();
            CPWAIT1();
        } else {
            CPWAIT0();
        }
        __syncthreads();

        float accs[16][4];
        #pragma unroll
        for (int g = 0; g < 16; g++)
            #pragma unroll
            for (int c = 0; c < 4; c++) accs[g][c] = 0.f;
        uint32_t qb = sb + FQ, kbase = sb + FST(st);

        uint32_t ah_c[4], al_c[4], ah_n[4], al_n[4];
        uint32_t bh_c[4], bl_c[4], bh_n[4], bl_n[4];
        FL_LDA(ah_c, al_c, 0);
        FL_LDB(bh_c, bl_c, 0, 0);
        #pragma unroll
        for (int kc = 0; kc < 6; kc++) {
            if (kc < 5) FL_LDA(ah_n, al_n, kc + 1);
            #pragma unroll
            for (int ni = 0; ni < 8; ni++) {
                if (ni < 7) { FL_LDB(bh_n, bl_n, kc, ni + 1); }
                else if (kc < 5) { FL_LDB(bh_n, bl_n, kc + 1, 0); }
                MMA(accs[2 * ni], ah_c, bh_c[0], bh_c[1]);
                MMA(accs[2 * ni + 1], ah_c, bh_c[2], bh_c[3]);
                MMA(accs[2 * ni], al_c, bh_c[0], bh_c[1]);
                MMA(accs[2 * ni + 1], al_c, bh_c[2], bh_c[3]);
                MMA(accs[2 * ni], ah_c, bl_c[0], bl_c[1]);
                MMA(accs[2 * ni + 1], ah_c, bl_c[2], bl_c[3]);
                CP4(bh_c, bh_n);
                CP4(bl_c, bl_n);
            }
            CP4(ah_c, ah_n);
            CP4(al_c, al_n);
        }

        float mx0 = -1e30f, mx1 = -1e30f;
        #pragma unroll
        for (int g = 0; g < 16; g++) {
            mx0 = fmaxf(mx0, fmaxf(accs[g][0], accs[g][1]));
            mx1 = fmaxf(mx1, fmaxf(accs[g][2], accs[g][3]));
        }
        mx0 = fmaxf(mx0, __shfl_xor_sync(~0u, mx0, 1));
        mx0 = fmaxf(mx0, __shfl_xor_sync(~0u, mx0, 2));
        mx1 = fmaxf(mx1, __shfl_xor_sync(~0u, mx1, 1));
        mx1 = fmaxf(mx1, __shfl_xor_sync(~0u, mx1, 2));
        float mn0 = fmaxf(m0, mx0 * SQ), mn1 = fmaxf(m1, mx1 * SQ);
        float cr0 = __expf(m0 - mn0), cr1 = __expf(m1 - mn1);
        m0 = mn0; m1 = mn1;
        float rs0 = 0.f, rs1 = 0.f;
        #pragma unroll
        for (int g = 0; g < 16; g++) {
            float p0 = __expf(fmaf(SQ, accs[g][0], -mn0));
            float p1 = __expf(fmaf(SQ, accs[g][1], -mn0));
            float p2 = __expf(fmaf(SQ, accs[g][2], -mn1));
            float p3 = __expf(fmaf(SQ, accs[g][3], -mn1));
            accs[g][0] = p0; accs[g][1] = p1; accs[g][2] = p2; accs[g][3] = p3;
            rs0 += p0 + p1; rs1 += p2 + p3;
        }
        rs0 += __shfl_xor_sync(~0u, rs0, 1);
        rs0 += __shfl_xor_sync(~0u, rs0, 2);
        rs1 += __shfl_xor_sync(~0u, rs1, 1);
        rs1 += __shfl_xor_sync(~0u, rs1, 2);
        l0 = l0 * cr0 + rs0;
        l1 = l1 * cr1 + rs1;
        #pragma unroll
        for (int g = 0; g < 12; g++) {
            acco[g][0] *= cr0; acco[g][1] *= cr0;
            acco[g][2] *= cr1; acco[g][3] *= cr1;
        }

        uint32_t vb0 = sb + FST(st) + 53248;
        uint32_t v_c[4], v_n[4];
        FL_LDV(v_c, 0, 0);
        #pragma unroll
        for (int kb2 = 0; kb2 < 8; kb2++) {
            uint32_t pa[4];
            __half2 t;
            t = __floats2half2_rn(accs[2 * kb2][0], accs[2 * kb2][1]);
            pa[0] = *(uint32_t*)&t;
            t = __floats2half2_rn(accs[2 * kb2][2], accs[2 * kb2][3]);
            pa[1] = *(uint32_t*)&t;
            t = __floats2half2_rn(accs[2 * kb2 + 1][0], accs[2 * kb2 + 1][1]);
            pa[2] = *(uint32_t*)&t;
            t = __floats2half2_rn(accs[2 * kb2 + 1][2], accs[2 * kb2 + 1][3]);
            pa[3] = *(uint32_t*)&t;
            #pragma unroll
            for (int nj = 0; nj < 6; nj++) {
                if (nj < 5) { FL_LDV(v_n, kb2, nj + 1); }
                else if (kb2 < 7) { FL_LDV(v_n, kb2 + 1, 0); }
                MMA(acco[2 * nj], pa, v_c[0], v_c[1]);
                MMA(acco[2 * nj + 1], pa, v_c[2], v_c[3]);
                CP4(v_c, v_n);
            }
        }
        __syncthreads();
    }

    float rl0 = 1.f / l0, rl1 = 1.f / l1;
    long ob = (long)(b * NN + q0 + qr + (lane >> 2)) * DIM + h * HD + (lane & 3) * 2;
    #pragma unroll
    for (int g = 0; g < 12; g++) {
        *(__half2*)(att + ob + g * 8) =
            __floats2half2_rn(acco[g][0] * rl0, acco[g][1] * rl0);
        *(__half2*)(att + ob + 8 * DIM + g * 8) =
            __floats2half2_rn(acco[g][2] * rl1, acco[g][3] * rl1);
    }
}

// ------------------------------- launch --------------------------------------
extern "C" void kernel_launch(void* const* d_in, const int* in_sizes, int n_in,
                              void* d_out, int out_size) {
    const float* x    = (const float*)d_in[0];
    const float* ln_g = (const float*)d_in[1];
    const float* ln_b = (const float*)d_in[2];
    const float* Wqkv = (const float*)d_in[3];
    const float* bqkv = (const float*)d_in[4];
    const float* W0   = (const float*)d_in[5];
    const float* b0   = (const float*)d_in[6];
    const float* W1   = (const float*)d_in[7];
    const float* b1   = (const float*)d_in[8];
    const float* W2   = (const float*)d_in[9];
    const float* b2   = (const float*)d_in[10];
    float* out = (float*)d_out;

    cudaFuncSetAttribute(hgemm3, cudaFuncAttributeMaxDynamicSharedMemorySize, 2 * STG3B);
    cudaFuncSetAttribute(hgemm1, cudaFuncAttributeMaxDynamicSharedMemorySize, SM1);
    cudaFuncSetAttribute(flash_kernel, cudaFuncAttributeMaxDynamicSharedMemorySize, FL_SMEM);

    __half *yh, *yl, *wqh, *wql, *qkvh, *qkvl, *att, *l2, *w0, *w1, *w2, *hb;
    float *z, *b1p;
    cudaGetSymbolAddress((void**)&yh, g_yh);   cudaGetSymbolAddress((void**)&yl, g_yl);
    cudaGetSymbolAddress((void**)&wqh, g_wqh); cudaGetSymbolAddress((void**)&wql, g_wql);
    cudaGetSymbolAddress((void**)&qkvh, g_qkvh); cudaGetSymbolAddress((void**)&qkvl, g_qkvl);
    cudaGetSymbolAddress((void**)&att, g_att);
    cudaGetSymbolAddress((void**)&z, g_z);
    cudaGetSymbolAddress((void**)&l2, g_l2);
    cudaGetSymbolAddress((void**)&w0, g_w0);
    cudaGetSymbolAddress((void**)&w1, g_w1);
    cudaGetSymbolAddress((void**)&w2, g_w2);
    cudaGetSymbolAddress((void**)&hb, g_h);
    cudaGetSymbolAddress((void**)&b1p, g_b1p);

    split4_kernel<<<SEG0 + SEG1 + SEG2 + SEG3 + SEG4, 256>>>(
        Wqkv, wqh, wql, W0, w0, W1, w1, W2, w2, b1, b1p);
    ln_split_kernel<<<ROWS, 256>>>(x, ln_g, ln_b, yh, yl);
    // Q,K = y @ Wqkv[:, :1536] + b  (3-product split output)
    hgemm3<<<dim3(12, 64), 256, 2 * STG3B>>>(
        yh, yl, DIM, wqh, wql, QKVC, qkvh, qkvl, QKVC, bqkv, 24);
    // V = y @ Wqkv[:, 1536:] + b
    hgemm1<<<dim3(6, 64), 256, SM1>>>(
        yh, DIM, wqh + 1536, QKVC, nullptr, qkvh + 1536, QKVC, bqkv + 1536, nullptr,
        12, 0);
    flash_kernel<<<dim3(8, 64), 256, FL_SMEM>>>(qkvh, qkvl, att);
    // z = att @ W0 + b0 + x
    hgemm1<<<dim3(6, 64), 256, SM1>>>(
        att, DIM, w0, DIM, z, nullptr, DIM, b0, x, 12, 0);
    ln_split_kernel<<<ROWS, 256>>>(z, ln_g, ln_b, l2, nullptr);
    // h = gelu(l2 @ W1 + b1)   (N padded to 1536; padded bias = 0)
    hgemm1<<<dim3(12, 64), 256, SM1>>>(
        l2, DIM, w1, HPAD, nullptr, hb, HPAD, b1p, nullptr, 12, 1);
    // out = h @ W2 + b2 + z    (K padded to 1536 with zero rows)
    hgemm1<<<dim3(6, 64), 256, SM1>>>(
        hb, HPAD, w2, DIM, out, nullptr, DIM, b2, z, 24, 0);
}

// round 14
// speedup vs baseline: 6.7005x; 1.1626x over previous
#include <cuda_runtime.h>
#include <cuda_fp16.h>
#include <math.h>
#include <stdint.h>

#define BB 8
#define NN 1024
#define DIM 768
#define HEADS 8
#define HD 96
#define HIDDEN 1500
#define HPAD 1536
#define ROWS (BB * NN)
#define QKVC (3 * DIM)
#define PAD 64

__device__ __forceinline__ uint32_t smem_u32(const void* p) {
    uint32_t r;
    asm("{ .reg .u64 t; cvta.to.shared.u64 t, %1; cvt.u32.u64 %0, t; }" : "=r"(r) : "l"(p));
    return r;
}
#define CPA(dst, src, p) asm volatile("cp.async.cg.shared.global [%0], [%1], 16, %2;" :: "r"(dst), "l"(src), "r"(p) : "memory")
#define CPCOMMIT() asm volatile("cp.async.commit_group;" ::: "memory")
#define CPWAIT2() asm volatile("cp.async.wait_group 2;" ::: "memory")
#define CPWAIT1() asm volatile("cp.async.wait_group 1;" ::: "memory")
#define CPWAIT0() asm volatile("cp.async.wait_group 0;" ::: "memory")
#define LDSM4(r, a) asm volatile("ldmatrix.sync.aligned.m8n8.x4.shared.b16 {%0,%1,%2,%3}, [%4];" \
    : "=r"((r)[0]), "=r"((r)[1]), "=r"((r)[2]), "=r"((r)[3]) : "r"(a))
#define LDSM4T(r, a) asm volatile("ldmatrix.sync.aligned.m8n8.x4.trans.shared.b16 {%0,%1,%2,%3}, [%4];" \
    : "=r"((r)[0]), "=r"((r)[1]), "=r"((r)[2]), "=r"((r)[3]) : "r"(a))
#define MMA(c, a, b0, b1) asm volatile( \
    "mma.sync.aligned.m16n8k16.row.col.f32.f16.f16.f32 {%0,%1,%2,%3}, {%4,%5,%6,%7}, {%8,%9}, {%0,%1,%2,%3};" \
    : "+f"((c)[0]), "+f"((c)[1]), "+f"((c)[2]), "+f"((c)[3]) \
    : "r"((a)[0]), "r"((a)[1]), "r"((a)[2]), "r"((a)[3]), "r"(b0), "r"(b1))
#define CP4(d, s) { (d)[0] = (s)[0]; (d)[1] = (s)[1]; (d)[2] = (s)[2]; (d)[3] = (s)[3]; }

// ------------------------------ scratch -------------------------------------
__device__ __half g_yh[ROWS * DIM + PAD], g_yl[ROWS * DIM + PAD];
__device__ __half g_wqh[DIM * QKVC + PAD];
__device__ __half g_qkvh[ROWS * QKVC + PAD], g_qkvl[ROWS * QKVC + PAD];
__device__ __half g_att[ROWS * DIM + PAD];
__device__ float  g_z[ROWS * DIM + PAD];
__device__ __half g_l2[ROWS * DIM + PAD];
__device__ __half g_w0[DIM * DIM + PAD];
__device__ __half g_w1[DIM * HPAD + PAD];
__device__ __half g_w2[HPAD * DIM + PAD];
__device__ __half g_h[ROWS * HPAD + PAD];
__device__ float  g_b1p[HPAD];

// ---- one kernel converting all 4 weights (hi only) + padded b1 --------------
#define SEG0 6912
#define SEG1 2304
#define SEG2 4608
#define SEG3 4608
#define SEG4 6
__global__ void split4_kernel(const float* __restrict__ wq, __half* __restrict__ wqh,
                              const float* __restrict__ w0, __half* __restrict__ w0h,
                              const float* __restrict__ w1, __half* __restrict__ w1h,
                              const float* __restrict__ w2, __half* __restrict__ w2h,
                              const float* __restrict__ b1, float* __restrict__ b1p) {
    int blk = blockIdx.x;
    int t = threadIdx.x;
    if (blk < SEG0) {
        int i = blk * 256 + t;
        wqh[i] = __float2half_rn(wq[i]);
    } else if (blk < SEG0 + SEG1) {
        int i = (blk - SEG0) * 256 + t;
        w0h[i] = __float2half_rn(w0[i]);
    } else if (blk < SEG0 + SEG1 + SEG2) {
        int i = (blk - SEG0 - SEG1) * 256 + t;
        int r = i / HPAD, c = i - r * HPAD;
        w1h[i] = __float2half_rn(c < HIDDEN ? w1[(size_t)r * HIDDEN + c] : 0.f);
    } else if (blk < SEG0 + SEG1 + SEG2 + SEG3) {
        int i = (blk - SEG0 - SEG1 - SEG2) * 256 + t;
        int r = i / DIM, c = i - r * DIM;
        w2h[i] = __float2half_rn(r < HIDDEN ? w2[(size_t)r * DIM + c] : 0.f);
    } else {
        int i = (blk - SEG0 - SEG1 - SEG2 - SEG3) * 256 + t;
        b1p[i] = (i < HIDDEN) ? b1[i] : 0.f;
    }
}

__global__ void ln_split_kernel(const float* __restrict__ in,
                                const float* __restrict__ gamma,
                                const float* __restrict__ beta,
                                __half* __restrict__ oh, __half* __restrict__ ol) {
    int row = blockIdx.x, t = threadIdx.x;
    const float* px = in + (size_t)row * DIM;
    float v0 = px[t], v1 = px[t + 256], v2 = px[t + 512];
    float s = v0 + v1 + v2, sq = v0 * v0 + v1 * v1 + v2 * v2;
    __shared__ float red0[8], red1[8];
    #pragma unroll
    for (int o = 16; o; o >>= 1) {
        s += __shfl_xor_sync(~0u, s, o);
        sq += __shfl_xor_sync(~0u, sq, o);
    }
    if ((t & 31) == 0) { red0[t >> 5] = s; red1[t >> 5] = sq; }
    __syncthreads();
    if (t < 32) {
        s = (t < 8) ? red0[t] : 0.f;
        sq = (t < 8) ? red1[t] : 0.f;
        #pragma unroll
        for (int o = 4; o; o >>= 1) {
            s += __shfl_xor_sync(~0u, s, o);
            sq += __shfl_xor_sync(~0u, sq, o);
        }
        if (t == 0) { red0[0] = s; red1[0] = sq; }
    }
    __syncthreads();
    float mean = red0[0] * (1.f / DIM);
    float var = red1[0] * (1.f / DIM) - mean * mean;
    float rstd = rsqrtf(var + 1e-5f);
    size_t base = (size_t)row * DIM;
    float vv[3] = {v0, v1, v2};
    #pragma unroll
    for (int c = 0; c < 3; c++) {
        int i = t + c * 256;
        float v = (vv[c] - mean) * rstd * gamma[i] + beta[i];
        __half h = __float2half_rn(v);
        oh[base + i] = h;
        if (ol) ol[base + i] = __float2half_rn(v - __half2float(h));
    }
}

// ======== NP2 GEMM (QKV): BK=32, 2-stage; A hi+lo x B hi =====================
// stage elems: A hi 5120, A lo 5120, B hi 4352 -> 14592 elems = 29184 B
#define STG3B 29184
__device__ __forceinline__ void load_stage3(uint32_t sb, int tid,
    const __half* __restrict__ Ah, const __half* __restrict__ Al,
    long aRowBase, long lda, int k0,
    const __half* __restrict__ Bh, long ldb, int col0) {
    #pragma unroll
    for (int half = 0; half < 2; half++) {
        const __half* Ab = half ? Al : Ah;
        #pragma unroll
        for (int i = 0; i < 2; i++) {
            int u = tid + i * 256;
            int row = u >> 2, c = u & 3;
            CPA(sb + (half * 5120 + row * 40 + c * 8) * 2,
                Ab + aRowBase + (long)row * lda + k0 + c * 8, 16);
        }
    }
    #pragma unroll
    for (int i = 0; i < 2; i++) {
        int u = tid + i * 256;
        int k = u >> 4, c = u & 15;
        CPA(sb + (10240 + k * 136 + c * 8) * 2,
            Bh + (long)(k0 + k) * ldb + col0 + c * 8, 16);
    }
    CPCOMMIT();
}

__global__ __launch_bounds__(256, 2)
void hgemm3(const __half* __restrict__ Ah, const __half* __restrict__ Al, long lda,
            const __half* __restrict__ Bh, long ldb,
            __half* __restrict__ Chi, __half* __restrict__ Clo, long ldc,
            const float* __restrict__ bias, int nkb) {
    extern __shared__ char smem[];
    uint32_t sbase = smem_u32(smem);
    int tid = threadIdx.x, wid = tid >> 5, lane = tid & 31;
    int wm = wid >> 1, wn = wid & 1;
    int row0 = blockIdx.y * 128, col0 = blockIdx.x * 128;
    long aRowBase = (long)row0 * lda;

    float acc[2][8][4];
    #pragma unroll
    for (int a = 0; a < 2; a++)
        #pragma unroll
        for (int b = 0; b < 8; b++)
            #pragma unroll
            for (int c = 0; c < 4; c++) acc[a][b][c] = 0.f;

    load_stage3(sbase, tid, Ah, Al, aRowBase, lda, 0, Bh, ldb, col0);
    for (int kb = 0; kb < nkb; kb++) {
        if (kb + 1 < nkb) {
            load_stage3(sbase + ((kb + 1) & 1) * STG3B, tid, Ah, Al, aRowBase, lda,
                        (kb + 1) * 32, Bh, ldb, col0);
            CPWAIT1();
        } else {
            CPWAIT0();
        }
        __syncthreads();
        uint32_t sb = sbase + (kb & 1) * STG3B;
        #pragma unroll
        for (int kk = 0; kk < 32; kk += 16) {
            uint32_t ah[2][4], al[2][4];
            #pragma unroll
            for (int mi = 0; mi < 2; mi++) {
                uint32_t ad = sb + (((wm * 32 + mi * 16 + (lane & 15)) * 40 + kk +
                                     (lane >> 4) * 8) << 1);
                LDSM4(ah[mi], ad);
                LDSM4(al[mi], ad + 10240);
            }
            #pragma unroll
            for (int ni = 0; ni < 4; ni++) {
                uint32_t bh[4];
                int kq = kk + (lane & 15);
                int nq = wn * 64 + ni * 16 + ((lane >> 4) << 3);
                uint32_t bd = sb + 20480 + ((kq * 136 + nq) << 1);
                LDSM4T(bh, bd);
                #pragma unroll
                for (int mi = 0; mi < 2; mi++) {
                    MMA(acc[mi][2 * ni], ah[mi], bh[0], bh[1]);
                    MMA(acc[mi][2 * ni + 1], ah[mi], bh[2], bh[3]);
                    MMA(acc[mi][2 * ni], al[mi], bh[0], bh[1]);
                    MMA(acc[mi][2 * ni + 1], al[mi], bh[2], bh[3]);
                }
            }
        }
        __syncthreads();
    }
    int row_base = row0 + wm * 32, col_base = col0 + wn * 64;
    #pragma unroll
    for (int mi = 0; mi < 2; mi++)
        #pragma unroll
        for (int g = 0; g < 8; g++)
            #pragma unroll
            for (int rh = 0; rh < 2; rh++) {
                int row = row_base + mi * 16 + rh * 8 + (lane >> 2);
                int col = col_base + g * 8 + (lane & 3) * 2;
                float v0 = acc[mi][g][rh * 2] + bias[col];
                float v1 = acc[mi][g][rh * 2 + 1] + bias[col + 1];
                long cr = (long)row * ldc + col;
                __half h0 = __float2half_rn(v0), h1 = __float2half_rn(v1);
                *(__half2*)(Chi + cr) = __halves2half2(h0, h1);
                *(__half2*)(Clo + cr) = __halves2half2(
                    __float2half_rn(v0 - __half2float(h0)),
                    __float2half_rn(v1 - __half2float(h1)));
            }
}

// ======== NP1 GEMM: BK=64, 3-stage ring, fragment double-buffering ===========
#define STG1B 35840
#define SM1 (3 * STG1B)
__device__ __forceinline__ void load_stage1(uint32_t sb, int tid,
    const __half* __restrict__ A, long aRowBase, long lda, int k0,
    const __half* __restrict__ B, long ldb, int col0) {
    #pragma unroll
    for (int i = 0; i < 4; i++) {
        int u = tid + i * 256;
        int row = u >> 3, c = u & 7;
        CPA(sb + (row * 72 + c * 8) * 2, A + aRowBase + (long)row * lda + k0 + c * 8, 16);
    }
    #pragma unroll
    for (int i = 0; i < 4; i++) {
        int u = tid + i * 256;
        int k = u >> 4, c = u & 15;
        CPA(sb + (9216 + k * 136 + c * 8) * 2, B + (long)(k0 + k) * ldb + col0 + c * 8, 16);
    }
    CPCOMMIT();
}

#define G1_LDA(buf, kkv) { \
    uint32_t ad = sb + (((wm * 32 + (lane & 15)) * 72 + (kkv) + (lane >> 4) * 8) << 1); \
    LDSM4((buf)[0], ad); \
    LDSM4((buf)[1], ad + (16 * 72 * 2)); }
#define G1_LDB(buf, kkv, niv) { \
    int kq = (kkv) + (lane & 15); \
    int nq = wn * 64 + (niv) * 16 + ((lane >> 4) << 3); \
    LDSM4T(buf, sb + ((9216 + kq * 136 + nq) << 1)); }

__global__ __launch_bounds__(256, 2)
void hgemm1(const __half* __restrict__ A, long lda,
            const __half* __restrict__ B, long ldb,
            float* __restrict__ Cf, __half* __restrict__ Ch, long ldc,
            const float* __restrict__ bias, const float* __restrict__ resid,
            int nkb, int doGelu) {
    extern __shared__ char smem[];
    uint32_t sbase = smem_u32(smem);
    int tid = threadIdx.x, wid = tid >> 5, lane = tid & 31;
    int wm = wid >> 1, wn = wid & 1;
    int row0 = blockIdx.y * 128, col0 = blockIdx.x * 128;
    long aRowBase = (long)row0 * lda;

    float acc[2][8][4];
    #pragma unroll
    for (int a = 0; a < 2; a++)
        #pragma unroll
        for (int b = 0; b < 8; b++)
            #pragma unroll
            for (int c = 0; c < 4; c++) acc[a][b][c] = 0.f;

    load_stage1(sbase, tid, A, aRowBase, lda, 0, B, ldb, col0);
    if (nkb > 1) load_stage1(sbase + STG1B, tid, A, aRowBase, lda, 64, B, ldb, col0);

    int st = 0;
    for (int kb = 0; kb < nkb; kb++) {
        if (kb + 2 < nkb) {
            int ps = (st + 2) % 3;
            load_stage1(sbase + ps * STG1B, tid, A, aRowBase, lda, (kb + 2) * 64,
                        B, ldb, col0);
        }
        int rem = nkb - kb;
        if (rem >= 3) { CPWAIT2(); } else if (rem == 2) { CPWAIT1(); } else { CPWAIT0(); }
        __syncthreads();
        uint32_t sb = sbase + st * STG1B;

        uint32_t a_cur[2][4], a_nxt[2][4], b_cur[4], b_nxt[4];
        G1_LDA(a_cur, 0);
        G1_LDB(b_cur, 0, 0);
        #pragma unroll
        for (int j = 0; j < 4; j++) {
            int kk = j * 16;
            if (j < 3) G1_LDA(a_nxt, kk + 16);
            #pragma unroll
            for (int ni = 0; ni < 4; ni++) {
                if (ni < 3) { G1_LDB(b_nxt, kk, ni + 1); }
                else if (j < 3) { G1_LDB(b_nxt, kk + 16, 0); }
                MMA(acc[0][2 * ni], a_cur[0], b_cur[0], b_cur[1]);
                MMA(acc[0][2 * ni + 1], a_cur[0], b_cur[2], b_cur[3]);
                MMA(acc[1][2 * ni], a_cur[1], b_cur[0], b_cur[1]);
                MMA(acc[1][2 * ni + 1], a_cur[1], b_cur[2], b_cur[3]);
                CP4(b_cur, b_nxt);
            }
            CP4(a_cur[0], a_nxt[0]);
            CP4(a_cur[1], a_nxt[1]);
        }
        __syncthreads();
        st++; if (st == 3) st = 0;
    }

    int row_base = row0 + wm * 32, col_base = col0 + wn * 64;
    #pragma unroll
    for (int mi = 0; mi < 2; mi++)
        #pragma unroll
        for (int g = 0; g < 8; g++)
            #pragma unroll
            for (int rh = 0; rh < 2; rh++) {
                int row = row_base + mi * 16 + rh * 8 + (lane >> 2);
                int col = col_base + g * 8 + (lane & 3) * 2;
                float v0 = acc[mi][g][rh * 2] + bias[col];
                float v1 = acc[mi][g][rh * 2 + 1] + bias[col + 1];
                if (doGelu) {
                    v0 = 0.5f * v0 * (1.f + erff(v0 * 0.70710678118654752f));
                    v1 = 0.5f * v1 * (1.f + erff(v1 * 0.70710678118654752f));
                }
                long cr = (long)row * ldc + col;
                if (resid) {
                    float2 rr = *(const float2*)(resid + cr);
                    v0 += rr.x; v1 += rr.y;
                }
                if (Cf) *(float2*)(Cf + cr) = make_float2(v0, v1);
                else *(__half2*)(Ch + cr) = __floats2half2_rn(v0, v1);
            }
}

// ---------------- Flash attention: Q hi+lo x K hi (2-product S) --------------
// Q hi @0, Q lo @26624; stage st @ 53248+st*53248: K hi @+0, V @+26624.
#define FQ 0u
#define FST(st) (53248u + (st) * 53248u)
#define FL_SMEM 159744

__device__ __forceinline__ void ldtile(uint32_t dst, const __half* __restrict__ src,
                                       long base, int tid) {
    #pragma unroll
    for (int i = 0; i < 6; i++) {
        int u = tid + i * 256;
        int r = u / 12, c = u - r * 12;
        CPA(dst + r * 208 + c * 16, src + base + (long)r * QKVC + c * 8, 16);
    }
}

#define FL_LDA(bh_, bl_, kcv) { \
    uint32_t ad = qb + ((qr + (lane & 15)) * 104 + (kcv) * 16 + (lane >> 4) * 8) * 2; \
    LDSM4(bh_, ad); \
    LDSM4(bl_, ad + 26624); }
#define FL_LDB(bh_, kcv, niv) { \
    uint32_t bd = kbase + (((niv) * 16 + (lane & 7) + ((lane >> 4) << 3)) * 104 + \
                           (kcv) * 16 + (((lane >> 3) & 1) << 3)) * 2; \
    LDSM4(bh_, bd); }
#define FL_LDV(buf, kb2v, njv) { \
    uint32_t vd = vb0 + (((kb2v) * 16 + (lane & 15)) * 104 + \
                         (njv) * 16 + ((lane >> 4) << 3)) * 2; \
    LDSM4T(buf, vd); }

__global__ __launch_bounds__(256, 1)
void flash_kernel(const __half* __restrict__ qkvh, const __half* __restrict__ qkvl,
                  __half* __restrict__ att) {
    extern __shared__ char smem[];
    uint32_t sb = smem_u32(smem);
    int tid = threadIdx.x, wid = tid >> 5, lane = tid & 31;
    int b = blockIdx.y >> 3, h = blockIdx.y & 7;
    int q0 = blockIdx.x * 128;
    int qr = wid * 16;
    const float SQ = 9.79795897113271239f;

    long baseQ = (long)(b * NN + q0) * QKVC + h * HD;
    ldtile(sb + FQ, qkvh, baseQ, tid);
    ldtile(sb + FQ + 26624, qkvl, baseQ, tid);
    CPCOMMIT();
    long baseK = (long)(b * NN) * QKVC + DIM + h * HD;
    ldtile(sb + FST(0), qkvh, baseK, tid);
    ldtile(sb + FST(0) + 26624, qkvh, baseK + DIM, tid);
    CPCOMMIT();

    float acco[12][4];
    #pragma unroll
    for (int g = 0; g < 12; g++)
        #pragma unroll
        for (int c = 0; c < 4; c++) acco[g][c] = 0.f;
    float m0 = -1e30f, m1 = -1e30f, l0 = 0.f, l1 = 0.f;

    for (int kt = 0; kt < 8; kt++) {
        int st = kt & 1;
        if (kt < 7) {
            long bk = (long)(b * NN + (kt + 1) * 128) * QKVC + DIM + h * HD;
            ldtile(sb + FST(st ^ 1), qkvh, bk, tid);
            ldtile(sb + FST(st ^ 1) + 26624, qkvh, bk + DIM, tid);
            CPCOMMIT();
            CPWAIT1();
        } else {
            CPWAIT0();
        }
        __syncthreads();

        float accs[16][4];
        #pragma unroll
        for (int g = 0; g < 16; g++)
            #pragma unroll
            for (int c = 0; c < 4; c++) accs[g][c] = 0.f;
        uint32_t qb = sb + FQ, kbase = sb + FST(st);

        uint32_t ah_c[4], al_c[4], ah_n[4], al_n[4];
        uint32_t bh_c[4], bh_n[4];
        FL_LDA(ah_c, al_c, 0);
        FL_LDB(bh_c, 0, 0);
        #pragma unroll
        for (int kc = 0; kc < 6; kc++) {
            if (kc < 5) FL_LDA(ah_n, al_n, kc + 1);
            #pragma unroll
            for (int ni = 0; ni < 8; ni++) {
                if (ni < 7) { FL_LDB(bh_n, kc, ni + 1); }
                else if (kc < 5) { FL_LDB(bh_n, kc + 1, 0); }
                MMA(accs[2 * ni], ah_c, bh_c[0], bh_c[1]);
                MMA(accs[2 * ni + 1], ah_c, bh_c[2], bh_c[3]);
                MMA(accs[2 * ni], al_c, bh_c[0], bh_c[1]);
                MMA(accs[2 * ni + 1], al_c, bh_c[2], bh_c[3]);
                CP4(bh_c, bh_n);
            }
            CP4(ah_c, ah_n);
            CP4(al_c, al_n);
        }

        float mx0 = -1e30f, mx1 = -1e30f;
        #pragma unroll
        for (int g = 0; g < 16; g++) {
            mx0 = fmaxf(mx0, fmaxf(accs[g][0], accs[g][1]));
            mx1 = fmaxf(mx1, fmaxf(accs[g][2], accs[g][3]));
        }
        mx0 = fmaxf(mx0, __shfl_xor_sync(~0u, mx0, 1));
        mx0 = fmaxf(mx0, __shfl_xor_sync(~0u, mx0, 2));
        mx1 = fmaxf(mx1, __shfl_xor_sync(~0u, mx1, 1));
        mx1 = fmaxf(mx1, __shfl_xor_sync(~0u, mx1, 2));
        float mn0 = fmaxf(m0, mx0 * SQ), mn1 = fmaxf(m1, mx1 * SQ);
        float cr0 = __expf(m0 - mn0), cr1 = __expf(m1 - mn1);
        m0 = mn0; m1 = mn1;
        float rs0 = 0.f, rs1 = 0.f;
        #pragma unroll
        for (int g = 0; g < 16; g++) {
            float p0 = __expf(fmaf(SQ, accs[g][0], -mn0));
            float p1 = __expf(fmaf(SQ, accs[g][1], -mn0));
            float p2 = __expf(fmaf(SQ, accs[g][2], -mn1));
            float p3 = __expf(fmaf(SQ, accs[g][3], -mn1));
            accs[g][0] = p0; accs[g][1] = p1; accs[g][2] = p2; accs[g][3] = p3;
            rs0 += p0 + p1; rs1 += p2 + p3;
        }
        rs0 += __shfl_xor_sync(~0u, rs0, 1);
        rs0 += __shfl_xor_sync(~0u, rs0, 2);
        rs1 += __shfl_xor_sync(~0u, rs1, 1);
        rs1 += __shfl_xor_sync(~0u, rs1, 2);
        l0 = l0 * cr0 + rs0;
        l1 = l1 * cr1 + rs1;
        #pragma unroll
        for (int g = 0; g < 12; g++) {
            acco[g][0] *= cr0; acco[g][1] *= cr0;
            acco[g][2] *= cr1; acco[g][3] *= cr1;
        }

        uint32_t vb0 = sb + FST(st) + 26624;
        uint32_t v_c[4], v_n[4];
        FL_LDV(v_c, 0, 0);
        #pragma unroll
        for (int kb2 = 0; kb2 < 8; kb2++) {
            uint32_t pa[4];
            __half2 t;
            t = __floats2half2_rn(accs[2 * kb2][0], accs[2 * kb2][1]);
            pa[0] = *(uint32_t*)&t;
            t = __floats2half2_rn(accs[2 * kb2][2], accs[2 * kb2][3]);
            pa[1] = *(uint32_t*)&t;
            t = __floats2half2_rn(accs[2 * kb2 + 1][0], accs[2 * kb2 + 1][1]);
            pa[2] = *(uint32_t*)&t;
            t = __floats2half2_rn(accs[2 * kb2 + 1][2], accs[2 * kb2 + 1][3]);
            pa[3] = *(uint32_t*)&t;
            #pragma unroll
            for (int nj = 0; nj < 6; nj++) {
                if (nj < 5) { FL_LDV(v_n, kb2, nj + 1); }
                else if (kb2 < 7) { FL_LDV(v_n, kb2 + 1, 0); }
                MMA(acco[2 * nj], pa, v_c[0], v_c[1]);
                MMA(acco[2 * nj + 1], pa, v_c[2], v_c[3]);
                CP4(v_c, v_n);
            }
        }
        __syncthreads();
    }

    float rl0 = 1.f / l0, rl1 = 1.f / l1;
    long ob = (long)(b * NN + q0 + qr + (lane >> 2)) * DIM + h * HD + (lane & 3) * 2;
    #pragma unroll
    for (int g = 0; g < 12; g++) {
        *(__half2*)(att + ob + g * 8) =
            __floats2half2_rn(acco[g][0] * rl0, acco[g][1] * rl0);
        *(__half2*)(att + ob + 8 * DIM + g * 8) =
            __floats2half2_rn(acco[g][2] * rl1, acco[g][3] * rl1);
    }
}

// ------------------------------- launch --------------------------------------
extern "C" void kernel_launch(void* const* d_in, const int* in_sizes, int n_in,
                              void* d_out, int out_size) {
    const float* x    = (const float*)d_in[0];
    const float* ln_g = (const float*)d_in[1];
    const float* ln_b = (const float*)d_in[2];
    const float* Wqkv = (const float*)d_in[3];
    const float* bqkv = (const float*)d_in[4];
    const float* W0   = (const float*)d_in[5];
    const float* b0   = (const float*)d_in[6];
    const float* W1   = (const float*)d_in[7];
    const float* b1   = (const float*)d_in[8];
    const float* W2   = (const float*)d_in[9];
    const float* b2   = (const float*)d_in[10];
    float* out = (float*)d_out;

    cudaFuncSetAttribute(hgemm3, cudaFuncAttributeMaxDynamicSharedMemorySize, 2 * STG3B);
    cudaFuncSetAttribute(hgemm1, cudaFuncAttributeMaxDynamicSharedMemorySize, SM1);
    cudaFuncSetAttribute(flash_kernel, cudaFuncAttributeMaxDynamicSharedMemorySize, FL_SMEM);

    __half *yh, *yl, *wqh, *qkvh, *qkvl, *att, *l2, *w0, *w1, *w2, *hb;
    float *z, *b1p;
    cudaGetSymbolAddress((void**)&yh, g_yh);   cudaGetSymbolAddress((void**)&yl, g_yl);
    cudaGetSymbolAddress((void**)&wqh, g_wqh);
    cudaGetSymbolAddress((void**)&qkvh, g_qkvh); cudaGetSymbolAddress((void**)&qkvl, g_qkvl);
    cudaGetSymbolAddress((void**)&att, g_att);
    cudaGetSymbolAddress((void**)&z, g_z);
    cudaGetSymbolAddress((void**)&l2, g_l2);
    cudaGetSymbolAddress((void**)&w0, g_w0);
    cudaGetSymbolAddress((void**)&w1, g_w1);
    cudaGetSymbolAddress((void**)&w2, g_w2);
    cudaGetSymbolAddress((void**)&hb, g_h);
    cudaGetSymbolAddress((void**)&b1p, g_b1p);

    split4_kernel<<<SEG0 + SEG1 + SEG2 + SEG3 + SEG4, 256>>>(
        Wqkv, wqh, W0, w0, W1, w1, W2, w2, b1, b1p);
    ln_split_kernel<<<ROWS, 256>>>(x, ln_g, ln_b, yh, yl);
    // Q,K = y @ Wqkv[:, :1536] + b  (2-product: (yh+yl)·wh, split output)
    hgemm3<<<dim3(12, 64), 256, 2 * STG3B>>>(
        yh, yl, DIM, wqh, QKVC, qkvh, qkvl, QKVC, bqkv, 24);
    // V = y @ Wqkv[:, 1536:] + b
    hgemm1<<<dim3(6, 64), 256, SM1>>>(
        yh, DIM, wqh + 1536, QKVC, nullptr, qkvh + 1536, QKVC, bqkv + 1536, nullptr,
        12, 0);
    flash_kernel<<<dim3(8, 64), 256, FL_SMEM>>>(qkvh, qkvl, att);
    // z = att @ W0 + b0 + x
    hgemm1<<<dim3(6, 64), 256, SM1>>>(
        att, DIM, w0, DIM, z, nullptr, DIM, b0, x, 12, 0);
    ln_split_kernel<<<ROWS, 256>>>(z, ln_g, ln_b, l2, nullptr);
    // h = gelu(l2 @ W1 + b1)   (N padded to 1536; padded bias = 0)
    hgemm1<<<dim3(12, 64), 256, SM1>>>(
        l2, DIM, w1, HPAD, nullptr, hb, HPAD, b1p, nullptr, 12, 1);
    // out = h @ W2 + b2 + z    (K padded to 1536 with zero rows)
    hgemm1<<<dim3(6, 64), 256, SM1>>>(
        hb, HPAD, w2, DIM, out, nullptr, DIM, b2, z, 24, 0);
}

// round 15
// speedup vs baseline: 6.7604x; 1.0090x over previous
#include <cuda_runtime.h>
#include <cuda_fp16.h>
#include <math.h>
#include <stdint.h>

#define BB 8
#define NN 1024
#define DIM 768
#define HEADS 8
#define HD 96
#define HIDDEN 1500
#define HPAD 1536
#define ROWS (BB * NN)
#define QKVC (3 * DIM)
#define PAD 64

__device__ __forceinline__ uint32_t smem_u32(const void* p) {
    uint32_t r;
    asm("{ .reg .u64 t; cvta.to.shared.u64 t, %1; cvt.u32.u64 %0, t; }" : "=r"(r) : "l"(p));
    return r;
}
#define CPA(dst, src, p) asm volatile("cp.async.cg.shared.global [%0], [%1], 16, %2;" :: "r"(dst), "l"(src), "r"(p) : "memory")
#define CPCOMMIT() asm volatile("cp.async.commit_group;" ::: "memory")
#define CPWAIT2() asm volatile("cp.async.wait_group 2;" ::: "memory")
#define CPWAIT1() asm volatile("cp.async.wait_group 1;" ::: "memory")
#define CPWAIT0() asm volatile("cp.async.wait_group 0;" ::: "memory")
#define LDSM4(r, a) asm volatile("ldmatrix.sync.aligned.m8n8.x4.shared.b16 {%0,%1,%2,%3}, [%4];" \
    : "=r"((r)[0]), "=r"((r)[1]), "=r"((r)[2]), "=r"((r)[3]) : "r"(a))
#define LDSM4T(r, a) asm volatile("ldmatrix.sync.aligned.m8n8.x4.trans.shared.b16 {%0,%1,%2,%3}, [%4];" \
    : "=r"((r)[0]), "=r"((r)[1]), "=r"((r)[2]), "=r"((r)[3]) : "r"(a))
#define MMA(c, a, b0, b1) asm volatile( \
    "mma.sync.aligned.m16n8k16.row.col.f32.f16.f16.f32 {%0,%1,%2,%3}, {%4,%5,%6,%7}, {%8,%9}, {%0,%1,%2,%3};" \
    : "+f"((c)[0]), "+f"((c)[1]), "+f"((c)[2]), "+f"((c)[3]) \
    : "r"((a)[0]), "r"((a)[1]), "r"((a)[2]), "r"((a)[3]), "r"(b0), "r"(b1))
#define CP4(d, s) { (d)[0] = (s)[0]; (d)[1] = (s)[1]; (d)[2] = (s)[2]; (d)[3] = (s)[3]; }

// ------------------------------ scratch -------------------------------------
__device__ __half g_yh[ROWS * DIM + PAD], g_yl[ROWS * DIM + PAD];
__device__ __half g_wqh[DIM * QKVC + PAD];
__device__ __half g_qkvh[ROWS * QKVC + PAD], g_qkvl[ROWS * QKVC + PAD];
__device__ __half g_att[ROWS * DIM + PAD];
__device__ float  g_z[ROWS * DIM + PAD];
__device__ __half g_l2[ROWS * DIM + PAD];
__device__ __half g_w0[DIM * DIM + PAD];
__device__ __half g_w1[DIM * HPAD + PAD];
__device__ __half g_w2[HPAD * DIM + PAD];
__device__ __half g_h[ROWS * HPAD + PAD];
__device__ float  g_b1p[HPAD];

// ---- one kernel converting all 4 weights (hi only) + padded b1 --------------
#define SEG0 6912
#define SEG1 2304
#define SEG2 4608
#define SEG3 4608
#define SEG4 6
__global__ void split4_kernel(const float* __restrict__ wq, __half* __restrict__ wqh,
                              const float* __restrict__ w0, __half* __restrict__ w0h,
                              const float* __restrict__ w1, __half* __restrict__ w1h,
                              const float* __restrict__ w2, __half* __restrict__ w2h,
                              const float* __restrict__ b1, float* __restrict__ b1p) {
    int blk = blockIdx.x;
    int t = threadIdx.x;
    if (blk < SEG0) {
        int i = blk * 256 + t;
        wqh[i] = __float2half_rn(wq[i]);
    } else if (blk < SEG0 + SEG1) {
        int i = (blk - SEG0) * 256 + t;
        w0h[i] = __float2half_rn(w0[i]);
    } else if (blk < SEG0 + SEG1 + SEG2) {
        int i = (blk - SEG0 - SEG1) * 256 + t;
        int r = i / HPAD, c = i - r * HPAD;
        w1h[i] = __float2half_rn(c < HIDDEN ? w1[(size_t)r * HIDDEN + c] : 0.f);
    } else if (blk < SEG0 + SEG1 + SEG2 + SEG3) {
        int i = (blk - SEG0 - SEG1 - SEG2) * 256 + t;
        int r = i / DIM, c = i - r * DIM;
        w2h[i] = __float2half_rn(r < HIDDEN ? w2[(size_t)r * DIM + c] : 0.f);
    } else {
        int i = (blk - SEG0 - SEG1 - SEG2 - SEG3) * 256 + t;
        b1p[i] = (i < HIDDEN) ? b1[i] : 0.f;
    }
}

__global__ void ln_split_kernel(const float* __restrict__ in,
                                const float* __restrict__ gamma,
                                const float* __restrict__ beta,
                                __half* __restrict__ oh, __half* __restrict__ ol) {
    int row = blockIdx.x, t = threadIdx.x;
    const float* px = in + (size_t)row * DIM;
    float v0 = px[t], v1 = px[t + 256], v2 = px[t + 512];
    float s = v0 + v1 + v2, sq = v0 * v0 + v1 * v1 + v2 * v2;
    __shared__ float red0[8], red1[8];
    #pragma unroll
    for (int o = 16; o; o >>= 1) {
        s += __shfl_xor_sync(~0u, s, o);
        sq += __shfl_xor_sync(~0u, sq, o);
    }
    if ((t & 31) == 0) { red0[t >> 5] = s; red1[t >> 5] = sq; }
    __syncthreads();
    if (t < 32) {
        s = (t < 8) ? red0[t] : 0.f;
        sq = (t < 8) ? red1[t] : 0.f;
        #pragma unroll
        for (int o = 4; o; o >>= 1) {
            s += __shfl_xor_sync(~0u, s, o);
            sq += __shfl_xor_sync(~0u, sq, o);
        }
        if (t == 0) { red0[0] = s; red1[0] = sq; }
    }
    __syncthreads();
    float mean = red0[0] * (1.f / DIM);
    float var = red1[0] * (1.f / DIM) - mean * mean;
    float rstd = rsqrtf(var + 1e-5f);
    size_t base = (size_t)row * DIM;
    float vv[3] = {v0, v1, v2};
    #pragma unroll
    for (int c = 0; c < 3; c++) {
        int i = t + c * 256;
        float v = (vv[c] - mean) * rstd * gamma[i] + beta[i];
        __half h = __float2half_rn(v);
        oh[base + i] = h;
        if (ol) ol[base + i] = __float2half_rn(v - __half2float(h));
    }
}

// ======== merged QKV GEMM: BK=64, 2-stage; QK tiles 2-product, V tiles 1 =====
// stage elems: A hi 128x72=9216, A lo 9216, B 64x136=8704 -> 27136 = 54272 B
#define STGQB 54272
__device__ __forceinline__ void load_stageq(uint32_t sb, int tid,
    const __half* __restrict__ Ah, const __half* __restrict__ Al,
    long aRowBase, long lda, int k0,
    const __half* __restrict__ Bh, long ldb, int col0) {
    #pragma unroll
    for (int half = 0; half < 2; half++) {
        const __half* Ab = half ? Al : Ah;
        #pragma unroll
        for (int i = 0; i < 4; i++) {
            int u = tid + i * 256;
            int row = u >> 3, c = u & 7;
            CPA(sb + (half * 9216 + row * 72 + c * 8) * 2,
                Ab + aRowBase + (long)row * lda + k0 + c * 8, 16);
        }
    }
    #pragma unroll
    for (int i = 0; i < 4; i++) {
        int u = tid + i * 256;
        int k = u >> 4, c = u & 15;
        CPA(sb + (18432 + k * 136 + c * 8) * 2,
            Bh + (long)(k0 + k) * ldb + col0 + c * 8, 16);
    }
    CPCOMMIT();
}

__global__ __launch_bounds__(256, 2)
void hgemmqkv(const __half* __restrict__ Ah, const __half* __restrict__ Al, long lda,
              const __half* __restrict__ Bh, long ldb,
              __half* __restrict__ Chi, __half* __restrict__ Clo, long ldc,
              const float* __restrict__ bias, int nkb, int nLoX) {
    extern __shared__ char smem[];
    uint32_t sbase = smem_u32(smem);
    int tid = threadIdx.x, wid = tid >> 5, lane = tid & 31;
    int wm = wid >> 1, wn = wid & 1;
    int row0 = blockIdx.y * 128, col0 = blockIdx.x * 128;
    int useLo = (blockIdx.x < nLoX);
    long aRowBase = (long)row0 * lda;

    float acc[2][8][4];
    #pragma unroll
    for (int a = 0; a < 2; a++)
        #pragma unroll
        for (int b = 0; b < 8; b++)
            #pragma unroll
            for (int c = 0; c < 4; c++) acc[a][b][c] = 0.f;

    load_stageq(sbase, tid, Ah, Al, aRowBase, lda, 0, Bh, ldb, col0);
    for (int kb = 0; kb < nkb; kb++) {
        if (kb + 1 < nkb) {
            load_stageq(sbase + ((kb + 1) & 1) * STGQB, tid, Ah, Al, aRowBase, lda,
                        (kb + 1) * 64, Bh, ldb, col0);
            CPWAIT1();
        } else {
            CPWAIT0();
        }
        __syncthreads();
        uint32_t sb = sbase + (kb & 1) * STGQB;
        #pragma unroll
        for (int kk = 0; kk < 64; kk += 16) {
            uint32_t ah[2][4], al[2][4];
            #pragma unroll
            for (int mi = 0; mi < 2; mi++) {
                uint32_t ad = sb + (((wm * 32 + mi * 16 + (lane & 15)) * 72 + kk +
                                     (lane >> 4) * 8) << 1);
                LDSM4(ah[mi], ad);
                LDSM4(al[mi], ad + 18432);
            }
            #pragma unroll
            for (int ni = 0; ni < 4; ni++) {
                uint32_t bh[4];
                int kq = kk + (lane & 15);
                int nq = wn * 64 + ni * 16 + ((lane >> 4) << 3);
                uint32_t bd = sb + 36864 + ((kq * 136 + nq) << 1);
                LDSM4T(bh, bd);
                #pragma unroll
                for (int mi = 0; mi < 2; mi++) {
                    MMA(acc[mi][2 * ni], ah[mi], bh[0], bh[1]);
                    MMA(acc[mi][2 * ni + 1], ah[mi], bh[2], bh[3]);
                }
                if (useLo) {
                    #pragma unroll
                    for (int mi = 0; mi < 2; mi++) {
                        MMA(acc[mi][2 * ni], al[mi], bh[0], bh[1]);
                        MMA(acc[mi][2 * ni + 1], al[mi], bh[2], bh[3]);
                    }
                }
            }
        }
        __syncthreads();
    }
    int row_base = row0 + wm * 32, col_base = col0 + wn * 64;
    #pragma unroll
    for (int mi = 0; mi < 2; mi++)
        #pragma unroll
        for (int g = 0; g < 8; g++)
            #pragma unroll
            for (int rh = 0; rh < 2; rh++) {
                int row = row_base + mi * 16 + rh * 8 + (lane >> 2);
                int col = col_base + g * 8 + (lane & 3) * 2;
                float v0 = acc[mi][g][rh * 2] + bias[col];
                float v1 = acc[mi][g][rh * 2 + 1] + bias[col + 1];
                long cr = (long)row * ldc + col;
                __half h0 = __float2half_rn(v0), h1 = __float2half_rn(v1);
                *(__half2*)(Chi + cr) = __halves2half2(h0, h1);
                *(__half2*)(Clo + cr) = __halves2half2(
                    __float2half_rn(v0 - __half2float(h0)),
                    __float2half_rn(v1 - __half2float(h1)));
            }
}

// ======== NP1 GEMM: BK=64, 3-stage ring, fragment double-buffering ===========
#define STG1B 35840
#define SM1 (3 * STG1B)
__device__ __forceinline__ void load_stage1(uint32_t sb, int tid,
    const __half* __restrict__ A, long aRowBase, long lda, int k0,
    const __half* __restrict__ B, long ldb, int col0) {
    #pragma unroll
    for (int i = 0; i < 4; i++) {
        int u = tid + i * 256;
        int row = u >> 3, c = u & 7;
        CPA(sb + (row * 72 + c * 8) * 2, A + aRowBase + (long)row * lda + k0 + c * 8, 16);
    }
    #pragma unroll
    for (int i = 0; i < 4; i++) {
        int u = tid + i * 256;
        int k = u >> 4, c = u & 15;
        CPA(sb + (9216 + k * 136 + c * 8) * 2, B + (long)(k0 + k) * ldb + col0 + c * 8, 16);
    }
    CPCOMMIT();
}

#define G1_LDA(buf, kkv) { \
    uint32_t ad = sb + (((wm * 32 + (lane & 15)) * 72 + (kkv) + (lane >> 4) * 8) << 1); \
    LDSM4((buf)[0], ad); \
    LDSM4((buf)[1], ad + (16 * 72 * 2)); }
#define G1_LDB(buf, kkv, niv) { \
    int kq = (kkv) + (lane & 15); \
    int nq = wn * 64 + (niv) * 16 + ((lane >> 4) << 3); \
    LDSM4T(buf, sb + ((9216 + kq * 136 + nq) << 1)); }

__global__ __launch_bounds__(256, 2)
void hgemm1(const __half* __restrict__ A, long lda,
            const __half* __restrict__ B, long ldb,
            float* __restrict__ Cf, __half* __restrict__ Ch, long ldc,
            const float* __restrict__ bias, const float* __restrict__ resid,
            int nkb, int doGelu) {
    extern __shared__ char smem[];
    uint32_t sbase = smem_u32(smem);
    int tid = threadIdx.x, wid = tid >> 5, lane = tid & 31;
    int wm = wid >> 1, wn = wid & 1;
    int row0 = blockIdx.y * 128, col0 = blockIdx.x * 128;
    long aRowBase = (long)row0 * lda;

    float acc[2][8][4];
    #pragma unroll
    for (int a = 0; a < 2; a++)
        #pragma unroll
        for (int b = 0; b < 8; b++)
            #pragma unroll
            for (int c = 0; c < 4; c++) acc[a][b][c] = 0.f;

    load_stage1(sbase, tid, A, aRowBase, lda, 0, B, ldb, col0);
    if (nkb > 1) load_stage1(sbase + STG1B, tid, A, aRowBase, lda, 64, B, ldb, col0);

    int st = 0;
    for (int kb = 0; kb < nkb; kb++) {
        if (kb + 2 < nkb) {
            int ps = (st + 2) % 3;
            load_stage1(sbase + ps * STG1B, tid, A, aRowBase, lda, (kb + 2) * 64,
                        B, ldb, col0);
        }
        int rem = nkb - kb;
        if (rem >= 3) { CPWAIT2(); } else if (rem == 2) { CPWAIT1(); } else { CPWAIT0(); }
        __syncthreads();
        uint32_t sb = sbase + st * STG1B;

        uint32_t a_cur[2][4], a_nxt[2][4], b_cur[4], b_nxt[4];
        G1_LDA(a_cur, 0);
        G1_LDB(b_cur, 0, 0);
        #pragma unroll
        for (int j = 0; j < 4; j++) {
            int kk = j * 16;
            if (j < 3) G1_LDA(a_nxt, kk + 16);
            #pragma unroll
            for (int ni = 0; ni < 4; ni++) {
                if (ni < 3) { G1_LDB(b_nxt, kk, ni + 1); }
                else if (j < 3) { G1_LDB(b_nxt, kk + 16, 0); }
                MMA(acc[0][2 * ni], a_cur[0], b_cur[0], b_cur[1]);
                MMA(acc[0][2 * ni + 1], a_cur[0], b_cur[2], b_cur[3]);
                MMA(acc[1][2 * ni], a_cur[1], b_cur[0], b_cur[1]);
                MMA(acc[1][2 * ni + 1], a_cur[1], b_cur[2], b_cur[3]);
                CP4(b_cur, b_nxt);
            }
            CP4(a_cur[0], a_nxt[0]);
            CP4(a_cur[1], a_nxt[1]);
        }
        __syncthreads();
        st++; if (st == 3) st = 0;
    }

    int row_base = row0 + wm * 32, col_base = col0 + wn * 64;
    #pragma unroll
    for (int mi = 0; mi < 2; mi++)
        #pragma unroll
        for (int g = 0; g < 8; g++)
            #pragma unroll
            for (int rh = 0; rh < 2; rh++) {
                int row = row_base + mi * 16 + rh * 8 + (lane >> 2);
                int col = col_base + g * 8 + (lane & 3) * 2;
                float v0 = acc[mi][g][rh * 2] + bias[col];
                float v1 = acc[mi][g][rh * 2 + 1] + bias[col + 1];
                if (doGelu) {
                    v0 = 0.5f * v0 * (1.f + erff(v0 * 0.70710678118654752f));
                    v1 = 0.5f * v1 * (1.f + erff(v1 * 0.70710678118654752f));
                }
                long cr = (long)row * ldc + col;
                if (resid) {
                    float2 rr = *(const float2*)(resid + cr);
                    v0 += rr.x; v1 += rr.y;
                }
                if (Cf) *(float2*)(Cf + cr) = make_float2(v0, v1);
                else *(__half2*)(Ch + cr) = __floats2half2_rn(v0, v1);
            }
}

// ---------------- Flash attention: Q hi+lo x K hi (2-product S) --------------
#define FQ 0u
#define FST(st) (53248u + (st) * 53248u)
#define FL_SMEM 159744

__device__ __forceinline__ void ldtile(uint32_t dst, const __half* __restrict__ src,
                                       long base, int tid) {
    #pragma unroll
    for (int i = 0; i < 6; i++) {
        int u = tid + i * 256;
        int r = u / 12, c = u - r * 12;
        CPA(dst + r * 208 + c * 16, src + base + (long)r * QKVC + c * 8, 16);
    }
}

#define FL_LDA(bh_, bl_, kcv) { \
    uint32_t ad = qb + ((qr + (lane & 15)) * 104 + (kcv) * 16 + (lane >> 4) * 8) * 2; \
    LDSM4(bh_, ad); \
    LDSM4(bl_, ad + 26624); }
#define FL_LDB(bh_, kcv, niv) { \
    uint32_t bd = kbase + (((niv) * 16 + (lane & 7) + ((lane >> 4) << 3)) * 104 + \
                           (kcv) * 16 + (((lane >> 3) & 1) << 3)) * 2; \
    LDSM4(bh_, bd); }
#define FL_LDV(buf, kb2v, njv) { \
    uint32_t vd = vb0 + (((kb2v) * 16 + (lane & 15)) * 104 + \
                         (njv) * 16 + ((lane >> 4) << 3)) * 2; \
    LDSM4T(buf, vd); }

__global__ __launch_bounds__(256, 1)
void flash_kernel(const __half* __restrict__ qkvh, const __half* __restrict__ qkvl,
                  __half* __restrict__ att) {
    extern __shared__ char smem[];
    uint32_t sb = smem_u32(smem);
    int tid = threadIdx.x, wid = tid >> 5, lane = tid & 31;
    int b = blockIdx.y >> 3, h = blockIdx.y & 7;
    int q0 = blockIdx.x * 128;
    int qr = wid * 16;
    const float SQ = 9.79795897113271239f;

    long baseQ = (long)(b * NN + q0) * QKVC + h * HD;
    ldtile(sb + FQ, qkvh, baseQ, tid);
    ldtile(sb + FQ + 26624, qkvl, baseQ, tid);
    CPCOMMIT();
    long baseK = (long)(b * NN) * QKVC + DIM + h * HD;
    ldtile(sb + FST(0), qkvh, baseK, tid);
    ldtile(sb + FST(0) + 26624, qkvh, baseK + DIM, tid);
    CPCOMMIT();

    float acco[12][4];
    #pragma unroll
    for (int g = 0; g < 12; g++)
        #pragma unroll
        for (int c = 0; c < 4; c++) acco[g][c] = 0.f;
    float m0 = -1e30f, m1 = -1e30f, l0 = 0.f, l1 = 0.f;

    for (int kt = 0; kt < 8; kt++) {
        int st = kt & 1;
        if (kt < 7) {
            long bk = (long)(b * NN + (kt + 1) * 128) * QKVC + DIM + h * HD;
            ldtile(sb + FST(st ^ 1), qkvh, bk, tid);
            ldtile(sb + FST(st ^ 1) + 26624, qkvh, bk + DIM, tid);
            CPCOMMIT();
            CPWAIT1();
        } else {
            CPWAIT0();
        }
        __syncthreads();

        float accs[16][4];
        #pragma unroll
        for (int g = 0; g < 16; g++)
            #pragma unroll
            for (int c = 0; c < 4; c++) accs[g][c] = 0.f;
        uint32_t qb = sb + FQ, kbase = sb + FST(st);

        uint32_t ah_c[4], al_c[4], ah_n[4], al_n[4];
        uint32_t bh_c[4], bh_n[4];
        FL_LDA(ah_c, al_c, 0);
        FL_LDB(bh_c, 0, 0);
        #pragma unroll
        for (int kc = 0; kc < 6; kc++) {
            if (kc < 5) FL_LDA(ah_n, al_n, kc + 1);
            #pragma unroll
            for (int ni = 0; ni < 8; ni++) {
                if (ni < 7) { FL_LDB(bh_n, kc, ni + 1); }
                else if (kc < 5) { FL_LDB(bh_n, kc + 1, 0); }
                MMA(accs[2 * ni], ah_c, bh_c[0], bh_c[1]);
                MMA(accs[2 * ni + 1], ah_c, bh_c[2], bh_c[3]);
                MMA(accs[2 * ni], al_c, bh_c[0], bh_c[1]);
                MMA(accs[2 * ni + 1], al_c, bh_c[2], bh_c[3]);
                CP4(bh_c, bh_n);
            }
            CP4(ah_c, ah_n);
            CP4(al_c, al_n);
        }

        float mx0 = -1e30f, mx1 = -1e30f;
        #pragma unroll
        for (int g = 0; g < 16; g++) {
            mx0 = fmaxf(mx0, fmaxf(accs[g][0], accs[g][1]));
            mx1 = fmaxf(mx1, fmaxf(accs[g][2], accs[g][3]));
        }
        mx0 = fmaxf(mx0, __shfl_xor_sync(~0u, mx0, 1));
        mx0 = fmaxf(mx0, __shfl_xor_sync(~0u, mx0, 2));
        mx1 = fmaxf(mx1, __shfl_xor_sync(~0u, mx1, 1));
        mx1 = fmaxf(mx1, __shfl_xor_sync(~0u, mx1, 2));
        float mn0 = fmaxf(m0, mx0 * SQ), mn1 = fmaxf(m1, mx1 * SQ);
        float cr0 = __expf(m0 - mn0), cr1 = __expf(m1 - mn1);
        m0 = mn0; m1 = mn1;
        float rs0 = 0.f, rs1 = 0.f;
        #pragma unroll
        for (int g = 0; g < 16; g++) {
            float p0 = __expf(fmaf(SQ, accs[g][0], -mn0));
            float p1 = __expf(fmaf(SQ, accs[g][1], -mn0));
            float p2 = __expf(fmaf(SQ, accs[g][2], -mn1));
            float p3 = __expf(fmaf(SQ, accs[g][3], -mn1));
            accs[g][0] = p0; accs[g][1] = p1; accs[g][2] = p2; accs[g][3] = p3;
            rs0 += p0 + p1; rs1 += p2 + p3;
        }
        rs0 += __shfl_xor_sync(~0u, rs0, 1);
        rs0 += __shfl_xor_sync(~0u, rs0, 2);
        rs1 += __shfl_xor_sync(~0u, rs1, 1);
        rs1 += __shfl_xor_sync(~0u, rs1, 2);
        l0 = l0 * cr0 + rs0;
        l1 = l1 * cr1 + rs1;
        #pragma unroll
        for (int g = 0; g < 12; g++) {
            acco[g][0] *= cr0; acco[g][1] *= cr0;
            acco[g][2] *= cr1; acco[g][3] *= cr1;
        }

        uint32_t vb0 = sb + FST(st) + 26624;
        uint32_t v_c[4], v_n[4];
        FL_LDV(v_c, 0, 0);
        #pragma unroll
        for (int kb2 = 0; kb2 < 8; kb2++) {
            uint32_t pa[4];
            __half2 t;
            t = __floats2half2_rn(accs[2 * kb2][0], accs[2 * kb2][1]);
            pa[0] = *(uint32_t*)&t;
            t = __floats2half2_rn(accs[2 * kb2][2], accs[2 * kb2][3]);
            pa[1] = *(uint32_t*)&t;
            t = __floats2half2_rn(accs[2 * kb2 + 1][0], accs[2 * kb2 + 1][1]);
            pa[2] = *(uint32_t*)&t;
            t = __floats2half2_rn(accs[2 * kb2 + 1][2], accs[2 * kb2 + 1][3]);
            pa[3] = *(uint32_t*)&t;
            #pragma unroll
            for (int nj = 0; nj < 6; nj++) {
                if (nj < 5) { FL_LDV(v_n, kb2, nj + 1); }
                else if (kb2 < 7) { FL_LDV(v_n, kb2 + 1, 0); }
                MMA(acco[2 * nj], pa, v_c[0], v_c[1]);
                MMA(acco[2 * nj + 1], pa, v_c[2], v_c[3]);
                CP4(v_c, v_n);
            }
        }
        __syncthreads();
    }

    float rl0 = 1.f / l0, rl1 = 1.f / l1;
    long ob = (long)(b * NN + q0 + qr + (lane >> 2)) * DIM + h * HD + (lane & 3) * 2;
    #pragma unroll
    for (int g = 0; g < 12; g++) {
        *(__half2*)(att + ob + g * 8) =
            __floats2half2_rn(acco[g][0] * rl0, acco[g][1] * rl0);
        *(__half2*)(att + ob + 8 * DIM + g * 8) =
            __floats2half2_rn(acco[g][2] * rl1, acco[g][3] * rl1);
    }
}

// ------------------------------- launch --------------------------------------
extern "C" void kernel_launch(void* const* d_in, const int* in_sizes, int n_in,
                              void* d_out, int out_size) {
    const float* x    = (const float*)d_in[0];
    const float* ln_g = (const float*)d_in[1];
    const float* ln_b = (const float*)d_in[2];
    const float* Wqkv = (const float*)d_in[3];
    const float* bqkv = (const float*)d_in[4];
    const float* W0   = (const float*)d_in[5];
    const float* b0   = (const float*)d_in[6];
    const float* W1   = (const float*)d_in[7];
    const float* b1   = (const float*)d_in[8];
    const float* W2   = (const float*)d_in[9];
    const float* b2   = (const float*)d_in[10];
    float* out = (float*)d_out;

    cudaFuncSetAttribute(hgemmqkv, cudaFuncAttributeMaxDynamicSharedMemorySize, 2 * STGQB);
    cudaFuncSetAttribute(hgemm1, cudaFuncAttributeMaxDynamicSharedMemorySize, SM1);
    cudaFuncSetAttribute(flash_kernel, cudaFuncAttributeMaxDynamicSharedMemorySize, FL_SMEM);

    __half *yh, *yl, *wqh, *qkvh, *qkvl, *att, *l2, *w0, *w1, *w2, *hb;
    float *z, *b1p;
    cudaGetSymbolAddress((void**)&yh, g_yh);   cudaGetSymbolAddress((void**)&yl, g_yl);
    cudaGetSymbolAddress((void**)&wqh, g_wqh);
    cudaGetSymbolAddress((void**)&qkvh, g_qkvh); cudaGetSymbolAddress((void**)&qkvl, g_qkvl);
    cudaGetSymbolAddress((void**)&att, g_att);
    cudaGetSymbolAddress((void**)&z, g_z);
    cudaGetSymbolAddress((void**)&l2, g_l2);
    cudaGetSymbolAddress((void**)&w0, g_w0);
    cudaGetSymbolAddress((void**)&w1, g_w1);
    cudaGetSymbolAddress((void**)&w2, g_w2);
    cudaGetSymbolAddress((void**)&hb, g_h);
    cudaGetSymbolAddress((void**)&b1p, g_b1p);

    split4_kernel<<<SEG0 + SEG1 + SEG2 + SEG3 + SEG4, 256>>>(
        Wqkv, wqh, W0, w0, W1, w1, W2, w2, b1, b1p);
    ln_split_kernel<<<ROWS, 256>>>(x, ln_g, ln_b, yh, yl);
    // QKV in ONE launch: cols [0,1536) 2-product (Q,K), cols [1536,2304) 1-product (V)
    hgemmqkv<<<dim3(18, 64), 256, 2 * STGQB>>>(
        yh, yl, DIM, wqh, QKVC, qkvh, qkvl, QKVC, bqkv, 12, 12);
    flash_kernel<<<dim3(8, 64), 256, FL_SMEM>>>(qkvh, qkvl, att);
    // z = att @ W0 + b0 + x
    hgemm1<<<dim3(6, 64), 256, SM1>>>(
        att, DIM, w0, DIM, z, nullptr, DIM, b0, x, 12, 0);
    ln_split_kernel<<<ROWS, 256>>>(z, ln_g, ln_b, l2, nullptr);
    // h = gelu(l2 @ W1 + b1)
    hgemm1<<<dim3(12, 64), 256, SM1>>>(
        l2, DIM, w1, HPAD, nullptr, hb, HPAD, b1p, nullptr, 12, 1);
    // out = h @ W2 + b2 + z
    hgemm1<<<dim3(6, 64), 256, SM1>>>(
        hb, HPAD, w2, DIM, out, nullptr, DIM, b2, z, 24, 0);
}

// round 16
// speedup vs baseline: 6.7869x; 1.0039x over previous
#include <cuda_runtime.h>
#include <cuda_fp16.h>
#include <math.h>
#include <stdint.h>

#define BB 8
#define NN 1024
#define DIM 768
#define HEADS 8
#define HD 96
#define HIDDEN 1500
#define HPAD 1536
#define ROWS (BB * NN)
#define QKVC (3 * DIM)
#define PAD 64

__device__ __forceinline__ uint32_t smem_u32(const void* p) {
    uint32_t r;
    asm("{ .reg .u64 t; cvta.to.shared.u64 t, %1; cvt.u32.u64 %0, t; }" : "=r"(r) : "l"(p));
    return r;
}
#define CPA(dst, src, p) asm volatile("cp.async.cg.shared.global [%0], [%1], 16, %2;" :: "r"(dst), "l"(src), "r"(p) : "memory")
#define CPCOMMIT() asm volatile("cp.async.commit_group;" ::: "memory")
#define CPWAIT2() asm volatile("cp.async.wait_group 2;" ::: "memory")
#define CPWAIT1() asm volatile("cp.async.wait_group 1;" ::: "memory")
#define CPWAIT0() asm volatile("cp.async.wait_group 0;" ::: "memory")
#define LDSM4(r, a) asm volatile("ldmatrix.sync.aligned.m8n8.x4.shared.b16 {%0,%1,%2,%3}, [%4];" \
    : "=r"((r)[0]), "=r"((r)[1]), "=r"((r)[2]), "=r"((r)[3]) : "r"(a))
#define LDSM4T(r, a) asm volatile("ldmatrix.sync.aligned.m8n8.x4.trans.shared.b16 {%0,%1,%2,%3}, [%4];" \
    : "=r"((r)[0]), "=r"((r)[1]), "=r"((r)[2]), "=r"((r)[3]) : "r"(a))
#define MMA(c, a, b0, b1) asm volatile( \
    "mma.sync.aligned.m16n8k16.row.col.f32.f16.f16.f32 {%0,%1,%2,%3}, {%4,%5,%6,%7}, {%8,%9}, {%0,%1,%2,%3};" \
    : "+f"((c)[0]), "+f"((c)[1]), "+f"((c)[2]), "+f"((c)[3]) \
    : "r"((a)[0]), "r"((a)[1]), "r"((a)[2]), "r"((a)[3]), "r"(b0), "r"(b1))
#define CP4(d, s) { (d)[0] = (s)[0]; (d)[1] = (s)[1]; (d)[2] = (s)[2]; (d)[3] = (s)[3]; }

// ------------------------------ scratch -------------------------------------
__device__ __half g_yh[ROWS * DIM + PAD], g_yl[ROWS * DIM + PAD];
__device__ __half g_wqh[DIM * QKVC + PAD];
__device__ __half g_qkvh[ROWS * QKVC + PAD], g_qkvl[ROWS * QKVC + PAD];
__device__ __half g_att[ROWS * DIM + PAD];
__device__ float  g_z[ROWS * DIM + PAD];
__device__ __half g_l2[ROWS * DIM + PAD];
__device__ __half g_w0[DIM * DIM + PAD];
__device__ __half g_w1[DIM * HPAD + PAD];
__device__ __half g_w2[HPAD * DIM + PAD];
__device__ __half g_h[ROWS * HPAD + PAD];
__device__ float  g_b1p[HPAD];

// ---- one kernel converting all 4 weights (hi only) + padded b1 --------------
#define SEG0 6912
#define SEG1 2304
#define SEG2 4608
#define SEG3 4608
#define SEG4 6
__global__ void split4_kernel(const float* __restrict__ wq, __half* __restrict__ wqh,
                              const float* __restrict__ w0, __half* __restrict__ w0h,
                              const float* __restrict__ w1, __half* __restrict__ w1h,
                              const float* __restrict__ w2, __half* __restrict__ w2h,
                              const float* __restrict__ b1, float* __restrict__ b1p) {
    int blk = blockIdx.x;
    int t = threadIdx.x;
    if (blk < SEG0) {
        int i = blk * 256 + t;
        wqh[i] = __float2half_rn(wq[i]);
    } else if (blk < SEG0 + SEG1) {
        int i = (blk - SEG0) * 256 + t;
        w0h[i] = __float2half_rn(w0[i]);
    } else if (blk < SEG0 + SEG1 + SEG2) {
        int i = (blk - SEG0 - SEG1) * 256 + t;
        int r = i / HPAD, c = i - r * HPAD;
        w1h[i] = __float2half_rn(c < HIDDEN ? w1[(size_t)r * HIDDEN + c] : 0.f);
    } else if (blk < SEG0 + SEG1 + SEG2 + SEG3) {
        int i = (blk - SEG0 - SEG1 - SEG2) * 256 + t;
        int r = i / DIM, c = i - r * DIM;
        w2h[i] = __float2half_rn(r < HIDDEN ? w2[(size_t)r * DIM + c] : 0.f);
    } else {
        int i = (blk - SEG0 - SEG1 - SEG2 - SEG3) * 256 + t;
        b1p[i] = (i < HIDDEN) ? b1[i] : 0.f;
    }
}

__global__ void ln_split_kernel(const float* __restrict__ in,
                                const float* __restrict__ gamma,
                                const float* __restrict__ beta,
                                __half* __restrict__ oh, __half* __restrict__ ol) {
    int row = blockIdx.x, t = threadIdx.x;
    const float* px = in + (size_t)row * DIM;
    float v0 = px[t], v1 = px[t + 256], v2 = px[t + 512];
    float s = v0 + v1 + v2, sq = v0 * v0 + v1 * v1 + v2 * v2;
    __shared__ float red0[8], red1[8];
    #pragma unroll
    for (int o = 16; o; o >>= 1) {
        s += __shfl_xor_sync(~0u, s, o);
        sq += __shfl_xor_sync(~0u, sq, o);
    }
    if ((t & 31) == 0) { red0[t >> 5] = s; red1[t >> 5] = sq; }
    __syncthreads();
    if (t < 32) {
        s = (t < 8) ? red0[t] : 0.f;
        sq = (t < 8) ? red1[t] : 0.f;
        #pragma unroll
        for (int o = 4; o; o >>= 1) {
            s += __shfl_xor_sync(~0u, s, o);
            sq += __shfl_xor_sync(~0u, sq, o);
        }
        if (t == 0) { red0[0] = s; red1[0] = sq; }
    }
    __syncthreads();
    float mean = red0[0] * (1.f / DIM);
    float var = red1[0] * (1.f / DIM) - mean * mean;
    float rstd = rsqrtf(var + 1e-5f);
    size_t base = (size_t)row * DIM;
    float vv[3] = {v0, v1, v2};
    #pragma unroll
    for (int c = 0; c < 3; c++) {
        int i = t + c * 256;
        float v = (vv[c] - mean) * rstd * gamma[i] + beta[i];
        __half h = __float2half_rn(v);
        oh[base + i] = h;
        if (ol) ol[base + i] = __float2half_rn(v - __half2float(h));
    }
}

// ======== merged QKV GEMM: BK=64, 2-stage; QK tiles 2-product, V tiles 1 =====
#define STGQB 54272
__device__ __forceinline__ void load_stageq(uint32_t sb, int tid,
    const __half* __restrict__ Ah, const __half* __restrict__ Al,
    long aRowBase, long lda, int k0,
    const __half* __restrict__ Bh, long ldb, int col0) {
    #pragma unroll
    for (int half = 0; half < 2; half++) {
        const __half* Ab = half ? Al : Ah;
        #pragma unroll
        for (int i = 0; i < 4; i++) {
            int u = tid + i * 256;
            int row = u >> 3, c = u & 7;
            CPA(sb + (half * 9216 + row * 72 + c * 8) * 2,
                Ab + aRowBase + (long)row * lda + k0 + c * 8, 16);
        }
    }
    #pragma unroll
    for (int i = 0; i < 4; i++) {
        int u = tid + i * 256;
        int k = u >> 4, c = u & 15;
        CPA(sb + (18432 + k * 136 + c * 8) * 2,
            Bh + (long)(k0 + k) * ldb + col0 + c * 8, 16);
    }
    CPCOMMIT();
}

__global__ __launch_bounds__(256, 2)
void hgemmqkv(const __half* __restrict__ Ah, const __half* __restrict__ Al, long lda,
              const __half* __restrict__ Bh, long ldb,
              __half* __restrict__ Chi, __half* __restrict__ Clo, long ldc,
              const float* __restrict__ bias, int nkb, int nLoX) {
    extern __shared__ char smem[];
    uint32_t sbase = smem_u32(smem);
    int tid = threadIdx.x, wid = tid >> 5, lane = tid & 31;
    int wm = wid >> 1, wn = wid & 1;
    int row0 = blockIdx.y * 128, col0 = blockIdx.x * 128;
    int useLo = (blockIdx.x < nLoX);
    long aRowBase = (long)row0 * lda;

    float acc[2][8][4];
    #pragma unroll
    for (int a = 0; a < 2; a++)
        #pragma unroll
        for (int b = 0; b < 8; b++)
            #pragma unroll
            for (int c = 0; c < 4; c++) acc[a][b][c] = 0.f;

    load_stageq(sbase, tid, Ah, Al, aRowBase, lda, 0, Bh, ldb, col0);
    for (int kb = 0; kb < nkb; kb++) {
        if (kb + 1 < nkb) {
            load_stageq(sbase + ((kb + 1) & 1) * STGQB, tid, Ah, Al, aRowBase, lda,
                        (kb + 1) * 64, Bh, ldb, col0);
            CPWAIT1();
        } else {
            CPWAIT0();
        }
        __syncthreads();
        uint32_t sb = sbase + (kb & 1) * STGQB;
        #pragma unroll
        for (int kk = 0; kk < 64; kk += 16) {
            uint32_t ah[2][4], al[2][4];
            #pragma unroll
            for (int mi = 0; mi < 2; mi++) {
                uint32_t ad = sb + (((wm * 32 + mi * 16 + (lane & 15)) * 72 + kk +
                                     (lane >> 4) * 8) << 1);
                LDSM4(ah[mi], ad);
                LDSM4(al[mi], ad + 18432);
            }
            #pragma unroll
            for (int ni = 0; ni < 4; ni++) {
                uint32_t bh[4];
                int kq = kk + (lane & 15);
                int nq = wn * 64 + ni * 16 + ((lane >> 4) << 3);
                uint32_t bd = sb + 36864 + ((kq * 136 + nq) << 1);
                LDSM4T(bh, bd);
                #pragma unroll
                for (int mi = 0; mi < 2; mi++) {
                    MMA(acc[mi][2 * ni], ah[mi], bh[0], bh[1]);
                    MMA(acc[mi][2 * ni + 1], ah[mi], bh[2], bh[3]);
                }
                if (useLo) {
                    #pragma unroll
                    for (int mi = 0; mi < 2; mi++) {
                        MMA(acc[mi][2 * ni], al[mi], bh[0], bh[1]);
                        MMA(acc[mi][2 * ni + 1], al[mi], bh[2], bh[3]);
                    }
                }
            }
        }
        __syncthreads();
    }
    int row_base = row0 + wm * 32, col_base = col0 + wn * 64;
    #pragma unroll
    for (int mi = 0; mi < 2; mi++)
        #pragma unroll
        for (int g = 0; g < 8; g++)
            #pragma unroll
            for (int rh = 0; rh < 2; rh++) {
                int row = row_base + mi * 16 + rh * 8 + (lane >> 2);
                int col = col_base + g * 8 + (lane & 3) * 2;
                float v0 = acc[mi][g][rh * 2] + bias[col];
                float v1 = acc[mi][g][rh * 2 + 1] + bias[col + 1];
                long cr = (long)row * ldc + col;
                __half h0 = __float2half_rn(v0), h1 = __float2half_rn(v1);
                *(__half2*)(Chi + cr) = __halves2half2(h0, h1);
                *(__half2*)(Clo + cr) = __halves2half2(
                    __float2half_rn(v0 - __half2float(h0)),
                    __float2half_rn(v1 - __half2float(h1)));
            }
}

// ======== NP1 GEMM: BK=64, 3-stage ring, fragment double-buffering ===========
#define STG1B 35840
#define SM1 (3 * STG1B)
__device__ __forceinline__ void load_stage1(uint32_t sb, int tid,
    const __half* __restrict__ A, long aRowBase, long lda, int k0,
    const __half* __restrict__ B, long ldb, int col0) {
    #pragma unroll
    for (int i = 0; i < 4; i++) {
        int u = tid + i * 256;
        int row = u >> 3, c = u & 7;
        CPA(sb + (row * 72 + c * 8) * 2, A + aRowBase + (long)row * lda + k0 + c * 8, 16);
    }
    #pragma unroll
    for (int i = 0; i < 4; i++) {
        int u = tid + i * 256;
        int k = u >> 4, c = u & 15;
        CPA(sb + (9216 + k * 136 + c * 8) * 2, B + (long)(k0 + k) * ldb + col0 + c * 8, 16);
    }
    CPCOMMIT();
}

#define G1_LDA(buf, kkv) { \
    uint32_t ad = sb + (((wm * 32 + (lane & 15)) * 72 + (kkv) + (lane >> 4) * 8) << 1); \
    LDSM4((buf)[0], ad); \
    LDSM4((buf)[1], ad + (16 * 72 * 2)); }
#define G1_LDB(buf, kkv, niv) { \
    int kq = (kkv) + (lane & 15); \
    int nq = wn * 64 + (niv) * 16 + ((lane >> 4) << 3); \
    LDSM4T(buf, sb + ((9216 + kq * 136 + nq) << 1)); }

__global__ __launch_bounds__(256, 2)
void hgemm1(const __half* __restrict__ A, long lda,
            const __half* __restrict__ B, long ldb,
            float* __restrict__ Cf, __half* __restrict__ Ch, long ldc,
            const float* __restrict__ bias, const float* __restrict__ resid,
            int nkb, int doGelu) {
    extern __shared__ char smem[];
    uint32_t sbase = smem_u32(smem);
    int tid = threadIdx.x, wid = tid >> 5, lane = tid & 31;
    int wm = wid >> 1, wn = wid & 1;
    int row0 = blockIdx.y * 128, col0 = blockIdx.x * 128;
    long aRowBase = (long)row0 * lda;

    float acc[2][8][4];
    #pragma unroll
    for (int a = 0; a < 2; a++)
        #pragma unroll
        for (int b = 0; b < 8; b++)
            #pragma unroll
            for (int c = 0; c < 4; c++) acc[a][b][c] = 0.f;

    load_stage1(sbase, tid, A, aRowBase, lda, 0, B, ldb, col0);
    if (nkb > 1) load_stage1(sbase + STG1B, tid, A, aRowBase, lda, 64, B, ldb, col0);

    int st = 0;
    for (int kb = 0; kb < nkb; kb++) {
        if (kb + 2 < nkb) {
            int ps = (st + 2) % 3;
            load_stage1(sbase + ps * STG1B, tid, A, aRowBase, lda, (kb + 2) * 64,
                        B, ldb, col0);
        }
        int rem = nkb - kb;
        if (rem >= 3) { CPWAIT2(); } else if (rem == 2) { CPWAIT1(); } else { CPWAIT0(); }
        __syncthreads();
        uint32_t sb = sbase + st * STG1B;

        uint32_t a_cur[2][4], a_nxt[2][4], b_cur[4], b_nxt[4];
        G1_LDA(a_cur, 0);
        G1_LDB(b_cur, 0, 0);
        #pragma unroll
        for (int j = 0; j < 4; j++) {
            int kk = j * 16;
            if (j < 3) G1_LDA(a_nxt, kk + 16);
            #pragma unroll
            for (int ni = 0; ni < 4; ni++) {
                if (ni < 3) { G1_LDB(b_nxt, kk, ni + 1); }
                else if (j < 3) { G1_LDB(b_nxt, kk + 16, 0); }
                MMA(acc[0][2 * ni], a_cur[0], b_cur[0], b_cur[1]);
                MMA(acc[0][2 * ni + 1], a_cur[0], b_cur[2], b_cur[3]);
                MMA(acc[1][2 * ni], a_cur[1], b_cur[0], b_cur[1]);
                MMA(acc[1][2 * ni + 1], a_cur[1], b_cur[2], b_cur[3]);
                CP4(b_cur, b_nxt);
            }
            CP4(a_cur[0], a_nxt[0]);
            CP4(a_cur[1], a_nxt[1]);
        }
        __syncthreads();
        st++; if (st == 3) st = 0;
    }

    int row_base = row0 + wm * 32, col_base = col0 + wn * 64;
    #pragma unroll
    for (int mi = 0; mi < 2; mi++)
        #pragma unroll
        for (int g = 0; g < 8; g++)
            #pragma unroll
            for (int rh = 0; rh < 2; rh++) {
                int row = row_base + mi * 16 + rh * 8 + (lane >> 2);
                int col = col_base + g * 8 + (lane & 3) * 2;
                float v0 = acc[mi][g][rh * 2] + bias[col];
                float v1 = acc[mi][g][rh * 2 + 1] + bias[col + 1];
                if (doGelu) {
                    v0 = 0.5f * v0 * (1.f + erff(v0 * 0.70710678118654752f));
                    v1 = 0.5f * v1 * (1.f + erff(v1 * 0.70710678118654752f));
                }
                long cr = (long)row * ldc + col;
                if (resid) {
                    float2 rr = *(const float2*)(resid + cr);
                    v0 += rr.x; v1 += rr.y;
                }
                if (Cf) *(float2*)(Cf + cr) = make_float2(v0, v1);
                else *(__half2*)(Ch + cr) = __floats2half2_rn(v0, v1);
            }
}

// -------- Flash attention: exp interleaved with PV MMAs (MUFU/tensor overlap)
#define FQ 0u
#define FST(st) (53248u + (st) * 53248u)
#define FL_SMEM 159744

__device__ __forceinline__ void ldtile(uint32_t dst, const __half* __restrict__ src,
                                       long base, int tid) {
    #pragma unroll
    for (int i = 0; i < 6; i++) {
        int u = tid + i * 256;
        int r = u / 12, c = u - r * 12;
        CPA(dst + r * 208 + c * 16, src + base + (long)r * QKVC + c * 8, 16);
    }
}

#define FL_LDA(bh_, bl_, kcv) { \
    uint32_t ad = qb + ((qr + (lane & 15)) * 104 + (kcv) * 16 + (lane >> 4) * 8) * 2; \
    LDSM4(bh_, ad); \
    LDSM4(bl_, ad + 26624); }
#define FL_LDB(bh_, kcv, niv) { \
    uint32_t bd = kbase + (((niv) * 16 + (lane & 7) + ((lane >> 4) << 3)) * 104 + \
                           (kcv) * 16 + (((lane >> 3) & 1) << 3)) * 2; \
    LDSM4(bh_, bd); }
#define FL_LDV(buf, kb2v, njv) { \
    uint32_t vd = vb0 + (((kb2v) * 16 + (lane & 15)) * 104 + \
                         (njv) * 16 + ((lane >> 4) << 3)) * 2; \
    LDSM4T(buf, vd); }

__global__ __launch_bounds__(256, 1)
void flash_kernel(const __half* __restrict__ qkvh, const __half* __restrict__ qkvl,
                  __half* __restrict__ att) {
    extern __shared__ char smem[];
    uint32_t sb = smem_u32(smem);
    int tid = threadIdx.x, wid = tid >> 5, lane = tid & 31;
    int b = blockIdx.y >> 3, h = blockIdx.y & 7;
    int q0 = blockIdx.x * 128;
    int qr = wid * 16;
    const float SQ = 9.79795897113271239f;

    long baseQ = (long)(b * NN + q0) * QKVC + h * HD;
    ldtile(sb + FQ, qkvh, baseQ, tid);
    ldtile(sb + FQ + 26624, qkvl, baseQ, tid);
    CPCOMMIT();
    long baseK = (long)(b * NN) * QKVC + DIM + h * HD;
    ldtile(sb + FST(0), qkvh, baseK, tid);
    ldtile(sb + FST(0) + 26624, qkvh, baseK + DIM, tid);
    CPCOMMIT();

    float acco[12][4];
    #pragma unroll
    for (int g = 0; g < 12; g++)
        #pragma unroll
        for (int c = 0; c < 4; c++) acco[g][c] = 0.f;
    float m0 = -1e30f, m1 = -1e30f, l0 = 0.f, l1 = 0.f;

    for (int kt = 0; kt < 8; kt++) {
        int st = kt & 1;
        if (kt < 7) {
            long bk = (long)(b * NN + (kt + 1) * 128) * QKVC + DIM + h * HD;
            ldtile(sb + FST(st ^ 1), qkvh, bk, tid);
            ldtile(sb + FST(st ^ 1) + 26624, qkvh, bk + DIM, tid);
            CPCOMMIT();
            CPWAIT1();
        } else {
            CPWAIT0();
        }
        __syncthreads();

        float accs[16][4];
        #pragma unroll
        for (int g = 0; g < 16; g++)
            #pragma unroll
            for (int c = 0; c < 4; c++) accs[g][c] = 0.f;
        uint32_t qb = sb + FQ, kbase = sb + FST(st);

        uint32_t ah_c[4], al_c[4], ah_n[4], al_n[4];
        uint32_t bh_c[4], bh_n[4];
        FL_LDA(ah_c, al_c, 0);
        FL_LDB(bh_c, 0, 0);
        #pragma unroll
        for (int kc = 0; kc < 6; kc++) {
            if (kc < 5) FL_LDA(ah_n, al_n, kc + 1);
            #pragma unroll
            for (int ni = 0; ni < 8; ni++) {
                if (ni < 7) { FL_LDB(bh_n, kc, ni + 1); }
                else if (kc < 5) { FL_LDB(bh_n, kc + 1, 0); }
                MMA(accs[2 * ni], ah_c, bh_c[0], bh_c[1]);
                MMA(accs[2 * ni + 1], ah_c, bh_c[2], bh_c[3]);
                MMA(accs[2 * ni], al_c, bh_c[0], bh_c[1]);
                MMA(accs[2 * ni + 1], al_c, bh_c[2], bh_c[3]);
                CP4(bh_c, bh_n);
            }
            CP4(ah_c, ah_n);
            CP4(al_c, al_n);
        }

        // ---- row max + O rescale (exp deferred into PV loop) ----
        float mx0 = -1e30f, mx1 = -1e30f;
        #pragma unroll
        for (int g = 0; g < 16; g++) {
            mx0 = fmaxf(mx0, fmaxf(accs[g][0], accs[g][1]));
            mx1 = fmaxf(mx1, fmaxf(accs[g][2], accs[g][3]));
        }
        mx0 = fmaxf(mx0, __shfl_xor_sync(~0u, mx0, 1));
        mx0 = fmaxf(mx0, __shfl_xor_sync(~0u, mx0, 2));
        mx1 = fmaxf(mx1, __shfl_xor_sync(~0u, mx1, 1));
        mx1 = fmaxf(mx1, __shfl_xor_sync(~0u, mx1, 2));
        float mn0 = fmaxf(m0, mx0 * SQ), mn1 = fmaxf(m1, mx1 * SQ);
        float cr0 = __expf(m0 - mn0), cr1 = __expf(m1 - mn1);
        m0 = mn0; m1 = mn1;
        #pragma unroll
        for (int g = 0; g < 12; g++) {
            acco[g][0] *= cr0; acco[g][1] *= cr0;
            acco[g][2] *= cr1; acco[g][3] *= cr1;
        }

        // ---- PV with per-block exp conversion (overlaps MUFU with HMMA) ----
        float rs0 = 0.f, rs1 = 0.f;
        uint32_t vb0 = sb + FST(st) + 26624;
        uint32_t v_c[4], v_n[4];
        FL_LDV(v_c, 0, 0);
        #pragma unroll
        for (int kb2 = 0; kb2 < 8; kb2++) {
            float p00 = __expf(fmaf(SQ, accs[2 * kb2][0], -mn0));
            float p01 = __expf(fmaf(SQ, accs[2 * kb2][1], -mn0));
            float p02 = __expf(fmaf(SQ, accs[2 * kb2][2], -mn1));
            float p03 = __expf(fmaf(SQ, accs[2 * kb2][3], -mn1));
            float p10 = __expf(fmaf(SQ, accs[2 * kb2 + 1][0], -mn0));
            float p11 = __expf(fmaf(SQ, accs[2 * kb2 + 1][1], -mn0));
            float p12 = __expf(fmaf(SQ, accs[2 * kb2 + 1][2], -mn1));
            float p13 = __expf(fmaf(SQ, accs[2 * kb2 + 1][3], -mn1));
            rs0 += p00 + p01 + p10 + p11;
            rs1 += p02 + p03 + p12 + p13;
            uint32_t pa[4];
            __half2 t;
            t = __floats2half2_rn(p00, p01); pa[0] = *(uint32_t*)&t;
            t = __floats2half2_rn(p02, p03); pa[1] = *(uint32_t*)&t;
            t = __floats2half2_rn(p10, p11); pa[2] = *(uint32_t*)&t;
            t = __floats2half2_rn(p12, p13); pa[3] = *(uint32_t*)&t;
            #pragma unroll
            for (int nj = 0; nj < 6; nj++) {
                if (nj < 5) { FL_LDV(v_n, kb2, nj + 1); }
                else if (kb2 < 7) { FL_LDV(v_n, kb2 + 1, 0); }
                MMA(acco[2 * nj], pa, v_c[0], v_c[1]);
                MMA(acco[2 * nj + 1], pa, v_c[2], v_c[3]);
                CP4(v_c, v_n);
            }
        }
        rs0 += __shfl_xor_sync(~0u, rs0, 1);
        rs0 += __shfl_xor_sync(~0u, rs0, 2);
        rs1 += __shfl_xor_sync(~0u, rs1, 1);
        rs1 += __shfl_xor_sync(~0u, rs1, 2);
        l0 = l0 * cr0 + rs0;
        l1 = l1 * cr1 + rs1;
        __syncthreads();
    }

    float rl0 = 1.f / l0, rl1 = 1.f / l1;
    long ob = (long)(b * NN + q0 + qr + (lane >> 2)) * DIM + h * HD + (lane & 3) * 2;
    #pragma unroll
    for (int g = 0; g < 12; g++) {
        *(__half2*)(att + ob + g * 8) =
            __floats2half2_rn(acco[g][0] * rl0, acco[g][1] * rl0);
        *(__half2*)(att + ob + 8 * DIM + g * 8) =
            __floats2half2_rn(acco[g][2] * rl1, acco[g][3] * rl1);
    }
}

// ------------------------------- launch --------------------------------------
extern "C" void kernel_launch(void* const* d_in, const int* in_sizes, int n_in,
                              void* d_out, int out_size) {
    const float* x    = (const float*)d_in[0];
    const float* ln_g = (const float*)d_in[1];
    const float* ln_b = (const float*)d_in[2];
    const float* Wqkv = (const float*)d_in[3];
    const float* bqkv = (const float*)d_in[4];
    const float* W0   = (const float*)d_in[5];
    const float* b0   = (const float*)d_in[6];
    const float* W1   = (const float*)d_in[7];
    const float* b1   = (const float*)d_in[8];
    const float* W2   = (const float*)d_in[9];
    const float* b2   = (const float*)d_in[10];
    float* out = (float*)d_out;

    cudaFuncSetAttribute(hgemmqkv, cudaFuncAttributeMaxDynamicSharedMemorySize, 2 * STGQB);
    cudaFuncSetAttribute(hgemm1, cudaFuncAttributeMaxDynamicSharedMemorySize, SM1);
    cudaFuncSetAttribute(flash_kernel, cudaFuncAttributeMaxDynamicSharedMemorySize, FL_SMEM);

    __half *yh, *yl, *wqh, *qkvh, *qkvl, *att, *l2, *w0, *w1, *w2, *hb;
    float *z, *b1p;
    cudaGetSymbolAddress((void**)&yh, g_yh);   cudaGetSymbolAddress((void**)&yl, g_yl);
    cudaGetSymbolAddress((void**)&wqh, g_wqh);
    cudaGetSymbolAddress((void**)&qkvh, g_qkvh); cudaGetSymbolAddress((void**)&qkvl, g_qkvl);
    cudaGetSymbolAddress((void**)&att, g_att);
    cudaGetSymbolAddress((void**)&z, g_z);
    cudaGetSymbolAddress((void**)&l2, g_l2);
    cudaGetSymbolAddress((void**)&w0, g_w0);
    cudaGetSymbolAddress((void**)&w1, g_w1);
    cudaGetSymbolAddress((void**)&w2, g_w2);
    cudaGetSymbolAddress((void**)&hb, g_h);
    cudaGetSymbolAddress((void**)&b1p, g_b1p);

    split4_kernel<<<SEG0 + SEG1 + SEG2 + SEG3 + SEG4, 256>>>(
        Wqkv, wqh, W0, w0, W1, w1, W2, w2, b1, b1p);
    ln_split_kernel<<<ROWS, 256>>>(x, ln_g, ln_b, yh, yl);
    // QKV in ONE launch: cols [0,1536) 2-product (Q,K), cols [1536,2304) 1-product (V)
    hgemmqkv<<<dim3(18, 64), 256, 2 * STGQB>>>(
        yh, yl, DIM, wqh, QKVC, qkvh, qkvl, QKVC, bqkv, 12, 12);
    flash_kernel<<<dim3(8, 64), 256, FL_SMEM>>>(qkvh, qkvl, att);
    // z = att @ W0 + b0 + x
    hgemm1<<<dim3(6, 64), 256, SM1>>>(
        att, DIM, w0, DIM, z, nullptr, DIM, b0, x, 12, 0);
    ln_split_kernel<<<ROWS, 256>>>(z, ln_g, ln_b, l2, nullptr);
    // h = gelu(l2 @ W1 + b1)
    hgemm1<<<dim3(12, 64), 256, SM1>>>(
        l2, DIM, w1, HPAD, nullptr, hb, HPAD, b1p, nullptr, 12, 1);
    // out = h @ W2 + b2 + z
    hgemm1<<<dim3(6, 64), 256, SM1>>>(
        hb, HPAD, w2, DIM, out, nullptr, DIM, b2, z, 24, 0);
}

// round 17
// speedup vs baseline: 6.8635x; 1.0113x over previous
#include <cuda_runtime.h>
#include <cuda_fp16.h>
#include <math.h>
#include <stdint.h>

#define BB 8
#define NN 1024
#define DIM 768
#define HEADS 8
#define HD 96
#define HIDDEN 1500
#define HPAD 1536
#define ROWS (BB * NN)
#define QKVC (3 * DIM)
#define PAD 64

__device__ __forceinline__ uint32_t smem_u32(const void* p) {
    uint32_t r;
    asm("{ .reg .u64 t; cvta.to.shared.u64 t, %1; cvt.u32.u64 %0, t; }" : "=r"(r) : "l"(p));
    return r;
}
#define CPA(dst, src, p) asm volatile("cp.async.cg.shared.global [%0], [%1], 16, %2;" :: "r"(dst), "l"(src), "r"(p) : "memory")
#define CPCOMMIT() asm volatile("cp.async.commit_group;" ::: "memory")
#define CPWAIT2() asm volatile("cp.async.wait_group 2;" ::: "memory")
#define CPWAIT1() asm volatile("cp.async.wait_group 1;" ::: "memory")
#define CPWAIT0() asm volatile("cp.async.wait_group 0;" ::: "memory")
#define LDSM4(r, a) asm volatile("ldmatrix.sync.aligned.m8n8.x4.shared.b16 {%0,%1,%2,%3}, [%4];" \
    : "=r"((r)[0]), "=r"((r)[1]), "=r"((r)[2]), "=r"((r)[3]) : "r"(a))
#define LDSM4T(r, a) asm volatile("ldmatrix.sync.aligned.m8n8.x4.trans.shared.b16 {%0,%1,%2,%3}, [%4];" \
    : "=r"((r)[0]), "=r"((r)[1]), "=r"((r)[2]), "=r"((r)[3]) : "r"(a))
#define MMA(c, a, b0, b1) asm volatile( \
    "mma.sync.aligned.m16n8k16.row.col.f32.f16.f16.f32 {%0,%1,%2,%3}, {%4,%5,%6,%7}, {%8,%9}, {%0,%1,%2,%3};" \
    : "+f"((c)[0]), "+f"((c)[1]), "+f"((c)[2]), "+f"((c)[3]) \
    : "r"((a)[0]), "r"((a)[1]), "r"((a)[2]), "r"((a)[3]), "r"(b0), "r"(b1))
#define CP4(d, s) { (d)[0] = (s)[0]; (d)[1] = (s)[1]; (d)[2] = (s)[2]; (d)[3] = (s)[3]; }

// ------------------------------ scratch -------------------------------------
__device__ __half g_yh[ROWS * DIM + PAD], g_yl[ROWS * DIM + PAD];
__device__ __half g_wqh[DIM * QKVC + PAD];
__device__ __half g_qkvh[ROWS * QKVC + PAD], g_qkvl[ROWS * QKVC + PAD];
__device__ __half g_att[ROWS * DIM + PAD];
__device__ float  g_z[ROWS * DIM + PAD];
__device__ __half g_l2[ROWS * DIM + PAD];
__device__ __half g_w0[DIM * DIM + PAD];
__device__ __half g_w1[DIM * HPAD + PAD];
__device__ __half g_w2[HPAD * DIM + PAD];
__device__ __half g_h[ROWS * HPAD + PAD];
__device__ float  g_b1p[HPAD];

// ---- one kernel converting all 4 weights (hi only) + padded b1 --------------
#define SEG0 6912
#define SEG1 2304
#define SEG2 4608
#define SEG3 4608
#define SEG4 6
__global__ void split4_kernel(const float* __restrict__ wq, __half* __restrict__ wqh,
                              const float* __restrict__ w0, __half* __restrict__ w0h,
                              const float* __restrict__ w1, __half* __restrict__ w1h,
                              const float* __restrict__ w2, __half* __restrict__ w2h,
                              const float* __restrict__ b1, float* __restrict__ b1p) {
    int blk = blockIdx.x;
    int t = threadIdx.x;
    if (blk < SEG0) {
        int i = blk * 256 + t;
        wqh[i] = __float2half_rn(wq[i]);
    } else if (blk < SEG0 + SEG1) {
        int i = (blk - SEG0) * 256 + t;
        w0h[i] = __float2half_rn(w0[i]);
    } else if (blk < SEG0 + SEG1 + SEG2) {
        int i = (blk - SEG0 - SEG1) * 256 + t;
        int r = i / HPAD, c = i - r * HPAD;
        w1h[i] = __float2half_rn(c < HIDDEN ? w1[(size_t)r * HIDDEN + c] : 0.f);
    } else if (blk < SEG0 + SEG1 + SEG2 + SEG3) {
        int i = (blk - SEG0 - SEG1 - SEG2) * 256 + t;
        int r = i / DIM, c = i - r * DIM;
        w2h[i] = __float2half_rn(r < HIDDEN ? w2[(size_t)r * DIM + c] : 0.f);
    } else {
        int i = (blk - SEG0 - SEG1 - SEG2 - SEG3) * 256 + t;
        b1p[i] = (i < HIDDEN) ? b1[i] : 0.f;
    }
}

__global__ void ln_split_kernel(const float* __restrict__ in,
                                const float* __restrict__ gamma,
                                const float* __restrict__ beta,
                                __half* __restrict__ oh, __half* __restrict__ ol) {
    int row = blockIdx.x, t = threadIdx.x;
    const float* px = in + (size_t)row * DIM;
    float v0 = px[t], v1 = px[t + 256], v2 = px[t + 512];
    float s = v0 + v1 + v2, sq = v0 * v0 + v1 * v1 + v2 * v2;
    __shared__ float red0[8], red1[8];
    #pragma unroll
    for (int o = 16; o; o >>= 1) {
        s += __shfl_xor_sync(~0u, s, o);
        sq += __shfl_xor_sync(~0u, sq, o);
    }
    if ((t & 31) == 0) { red0[t >> 5] = s; red1[t >> 5] = sq; }
    __syncthreads();
    if (t < 32) {
        s = (t < 8) ? red0[t] : 0.f;
        sq = (t < 8) ? red1[t] : 0.f;
        #pragma unroll
        for (int o = 4; o; o >>= 1) {
            s += __shfl_xor_sync(~0u, s, o);
            sq += __shfl_xor_sync(~0u, sq, o);
        }
        if (t == 0) { red0[0] = s; red1[0] = sq; }
    }
    __syncthreads();
    float mean = red0[0] * (1.f / DIM);
    float var = red1[0] * (1.f / DIM) - mean * mean;
    float rstd = rsqrtf(var + 1e-5f);
    size_t base = (size_t)row * DIM;
    float vv[3] = {v0, v1, v2};
    #pragma unroll
    for (int c = 0; c < 3; c++) {
        int i = t + c * 256;
        float v = (vv[c] - mean) * rstd * gamma[i] + beta[i];
        __half h = __float2half_rn(v);
        oh[base + i] = h;
        if (ol) ol[base + i] = __float2half_rn(v - __half2float(h));
    }
}

// ======== merged QKV GEMM: BK=64, 2-stage; QK tiles 2-product, V tiles 1 =====
#define STGQB 54272
__device__ __forceinline__ void load_stageq(uint32_t sb, int tid,
    const __half* __restrict__ Ah, const __half* __restrict__ Al,
    long aRowBase, long lda, int k0,
    const __half* __restrict__ Bh, long ldb, int col0) {
    #pragma unroll
    for (int half = 0; half < 2; half++) {
        const __half* Ab = half ? Al : Ah;
        #pragma unroll
        for (int i = 0; i < 4; i++) {
            int u = tid + i * 256;
            int row = u >> 3, c = u & 7;
            CPA(sb + (half * 9216 + row * 72 + c * 8) * 2,
                Ab + aRowBase + (long)row * lda + k0 + c * 8, 16);
        }
    }
    #pragma unroll
    for (int i = 0; i < 4; i++) {
        int u = tid + i * 256;
        int k = u >> 4, c = u & 15;
        CPA(sb + (18432 + k * 136 + c * 8) * 2,
            Bh + (long)(k0 + k) * ldb + col0 + c * 8, 16);
    }
    CPCOMMIT();
}

__global__ __launch_bounds__(256, 2)
void hgemmqkv(const __half* __restrict__ Ah, const __half* __restrict__ Al, long lda,
              const __half* __restrict__ Bh, long ldb,
              __half* __restrict__ Chi, __half* __restrict__ Clo, long ldc,
              const float* __restrict__ bias, int nkb, int nLoX) {
    extern __shared__ char smem[];
    uint32_t sbase = smem_u32(smem);
    int tid = threadIdx.x, wid = tid >> 5, lane = tid & 31;
    int wm = wid >> 1, wn = wid & 1;
    int row0 = blockIdx.y * 128, col0 = blockIdx.x * 128;
    int useLo = (blockIdx.x < nLoX);
    long aRowBase = (long)row0 * lda;

    float acc[2][8][4];
    #pragma unroll
    for (int a = 0; a < 2; a++)
        #pragma unroll
        for (int b = 0; b < 8; b++)
            #pragma unroll
            for (int c = 0; c < 4; c++) acc[a][b][c] = 0.f;

    load_stageq(sbase, tid, Ah, Al, aRowBase, lda, 0, Bh, ldb, col0);
    for (int kb = 0; kb < nkb; kb++) {
        if (kb + 1 < nkb) {
            load_stageq(sbase + ((kb + 1) & 1) * STGQB, tid, Ah, Al, aRowBase, lda,
                        (kb + 1) * 64, Bh, ldb, col0);
            CPWAIT1();
        } else {
            CPWAIT0();
        }
        __syncthreads();
        uint32_t sb = sbase + (kb & 1) * STGQB;
        #pragma unroll
        for (int kk = 0; kk < 64; kk += 16) {
            uint32_t ah[2][4], al[2][4];
            #pragma unroll
            for (int mi = 0; mi < 2; mi++) {
                uint32_t ad = sb + (((wm * 32 + mi * 16 + (lane & 15)) * 72 + kk +
                                     (lane >> 4) * 8) << 1);
                LDSM4(ah[mi], ad);
                LDSM4(al[mi], ad + 18432);
            }
            #pragma unroll
            for (int ni = 0; ni < 4; ni++) {
                uint32_t bh[4];
                int kq = kk + (lane & 15);
                int nq = wn * 64 + ni * 16 + ((lane >> 4) << 3);
                uint32_t bd = sb + 36864 + ((kq * 136 + nq) << 1);
                LDSM4T(bh, bd);
                #pragma unroll
                for (int mi = 0; mi < 2; mi++) {
                    MMA(acc[mi][2 * ni], ah[mi], bh[0], bh[1]);
                    MMA(acc[mi][2 * ni + 1], ah[mi], bh[2], bh[3]);
                }
                if (useLo) {
                    #pragma unroll
                    for (int mi = 0; mi < 2; mi++) {
                        MMA(acc[mi][2 * ni], al[mi], bh[0], bh[1]);
                        MMA(acc[mi][2 * ni + 1], al[mi], bh[2], bh[3]);
                    }
                }
            }
        }
        __syncthreads();
    }
    int row_base = row0 + wm * 32, col_base = col0 + wn * 64;
    #pragma unroll
    for (int mi = 0; mi < 2; mi++)
        #pragma unroll
        for (int g = 0; g < 8; g++)
            #pragma unroll
            for (int rh = 0; rh < 2; rh++) {
                int row = row_base + mi * 16 + rh * 8 + (lane >> 2);
                int col = col_base + g * 8 + (lane & 3) * 2;
                float v0 = acc[mi][g][rh * 2] + bias[col];
                float v1 = acc[mi][g][rh * 2 + 1] + bias[col + 1];
                long cr = (long)row * ldc + col;
                __half h0 = __float2half_rn(v0), h1 = __float2half_rn(v1);
                *(__half2*)(Chi + cr) = __halves2half2(h0, h1);
                *(__half2*)(Clo + cr) = __halves2half2(
                    __float2half_rn(v0 - __half2float(h0)),
                    __float2half_rn(v1 - __half2float(h1)));
            }
}

// ======== NP1 GEMM: BK=64, 3-stage ring, fragment double-buffering ===========
#define STG1B 35840
#define SM1 (3 * STG1B)
__device__ __forceinline__ void load_stage1(uint32_t sb, int tid,
    const __half* __restrict__ A, long aRowBase, long lda, int k0,
    const __half* __restrict__ B, long ldb, int col0) {
    #pragma unroll
    for (int i = 0; i < 4; i++) {
        int u = tid + i * 256;
        int row = u >> 3, c = u & 7;
        CPA(sb + (row * 72 + c * 8) * 2, A + aRowBase + (long)row * lda + k0 + c * 8, 16);
    }
    #pragma unroll
    for (int i = 0; i < 4; i++) {
        int u = tid + i * 256;
        int k = u >> 4, c = u & 15;
        CPA(sb + (9216 + k * 136 + c * 8) * 2, B + (long)(k0 + k) * ldb + col0 + c * 8, 16);
    }
    CPCOMMIT();
}

#define G1_LDA(buf, kkv) { \
    uint32_t ad = sb + (((wm * 32 + (lane & 15)) * 72 + (kkv) + (lane >> 4) * 8) << 1); \
    LDSM4((buf)[0], ad); \
    LDSM4((buf)[1], ad + (16 * 72 * 2)); }
#define G1_LDB(buf, kkv, niv) { \
    int kq = (kkv) + (lane & 15); \
    int nq = wn * 64 + (niv) * 16 + ((lane >> 4) << 3); \
    LDSM4T(buf, sb + ((9216 + kq * 136 + nq) << 1)); }

__global__ __launch_bounds__(256, 2)
void hgemm1(const __half* __restrict__ A, long lda,
            const __half* __restrict__ B, long ldb,
            float* __restrict__ Cf, __half* __restrict__ Ch, long ldc,
            const float* __restrict__ bias, const float* __restrict__ resid,
            int nkb, int doGelu) {
    extern __shared__ char smem[];
    uint32_t sbase = smem_u32(smem);
    int tid = threadIdx.x, wid = tid >> 5, lane = tid & 31;
    int wm = wid >> 1, wn = wid & 1;
    int row0 = blockIdx.y * 128, col0 = blockIdx.x * 128;
    long aRowBase = (long)row0 * lda;

    float acc[2][8][4];
    #pragma unroll
    for (int a = 0; a < 2; a++)
        #pragma unroll
        for (int b = 0; b < 8; b++)
            #pragma unroll
            for (int c = 0; c < 4; c++) acc[a][b][c] = 0.f;

    load_stage1(sbase, tid, A, aRowBase, lda, 0, B, ldb, col0);
    if (nkb > 1) load_stage1(sbase + STG1B, tid, A, aRowBase, lda, 64, B, ldb, col0);

    int st = 0;
    for (int kb = 0; kb < nkb; kb++) {
        if (kb + 2 < nkb) {
            int ps = (st + 2) % 3;
            load_stage1(sbase + ps * STG1B, tid, A, aRowBase, lda, (kb + 2) * 64,
                        B, ldb, col0);
        }
        int rem = nkb - kb;
        if (rem >= 3) { CPWAIT2(); } else if (rem == 2) { CPWAIT1(); } else { CPWAIT0(); }
        __syncthreads();
        uint32_t sb = sbase + st * STG1B;

        uint32_t a_cur[2][4], a_nxt[2][4], b_cur[4], b_nxt[4];
        G1_LDA(a_cur, 0);
        G1_LDB(b_cur, 0, 0);
        #pragma unroll
        for (int j = 0; j < 4; j++) {
            int kk = j * 16;
            if (j < 3) G1_LDA(a_nxt, kk + 16);
            #pragma unroll
            for (int ni = 0; ni < 4; ni++) {
                if (ni < 3) { G1_LDB(b_nxt, kk, ni + 1); }
                else if (j < 3) { G1_LDB(b_nxt, kk + 16, 0); }
                MMA(acc[0][2 * ni], a_cur[0], b_cur[0], b_cur[1]);
                MMA(acc[0][2 * ni + 1], a_cur[0], b_cur[2], b_cur[3]);
                MMA(acc[1][2 * ni], a_cur[1], b_cur[0], b_cur[1]);
                MMA(acc[1][2 * ni + 1], a_cur[1], b_cur[2], b_cur[3]);
                CP4(b_cur, b_nxt);
            }
            CP4(a_cur[0], a_nxt[0]);
            CP4(a_cur[1], a_nxt[1]);
        }
        __syncthreads();
        st++; if (st == 3) st = 0;
    }

    int row_base = row0 + wm * 32, col_base = col0 + wn * 64;
    #pragma unroll
    for (int mi = 0; mi < 2; mi++)
        #pragma unroll
        for (int g = 0; g < 8; g++)
            #pragma unroll
            for (int rh = 0; rh < 2; rh++) {
                int row = row_base + mi * 16 + rh * 8 + (lane >> 2);
                int col = col_base + g * 8 + (lane & 3) * 2;
                float v0 = acc[mi][g][rh * 2] + bias[col];
                float v1 = acc[mi][g][rh * 2 + 1] + bias[col + 1];
                if (doGelu) {
                    v0 = 0.5f * v0 * (1.f + erff(v0 * 0.70710678118654752f));
                    v1 = 0.5f * v1 * (1.f + erff(v1 * 0.70710678118654752f));
                }
                long cr = (long)row * ldc + col;
                if (resid) {
                    float2 rr = *(const float2*)(resid + cr);
                    v0 += rr.x; v1 += rr.y;
                }
                if (Cf) *(float2*)(Cf + cr) = make_float2(v0, v1);
                else *(__half2*)(Ch + cr) = __floats2half2_rn(v0, v1);
            }
}

// ---- Flash v3: k-tile 64, 2 CTAs/SM (smem 104 KB, regs <=128) ---------------
// Q hi @0, Q lo @26624 B; stage st @ 53248+st*26624: K @+0, V @+13312. stride 104.
#define FQ 0u
#define FST(st) (53248u + (st) * 26624u)
#define FL_SMEM 106496

__device__ __forceinline__ void ldtile128(uint32_t dst, const __half* __restrict__ src,
                                          long base, int tid) {
    #pragma unroll
    for (int i = 0; i < 6; i++) {
        int u = tid + i * 256;
        int r = u / 12, c = u - r * 12;
        CPA(dst + r * 208 + c * 16, src + base + (long)r * QKVC + c * 8, 16);
    }
}
__device__ __forceinline__ void ldtile64(uint32_t dst, const __half* __restrict__ src,
                                         long base, int tid) {
    #pragma unroll
    for (int i = 0; i < 3; i++) {
        int u = tid + i * 256;
        int r = u / 12, c = u - r * 12;
        CPA(dst + r * 208 + c * 16, src + base + (long)r * QKVC + c * 8, 16);
    }
}

__global__ __launch_bounds__(256, 2)
void flash_kernel(const __half* __restrict__ qkvh, const __half* __restrict__ qkvl,
                  __half* __restrict__ att) {
    extern __shared__ char smem[];
    uint32_t sb = smem_u32(smem);
    int tid = threadIdx.x, wid = tid >> 5, lane = tid & 31;
    int b = blockIdx.y >> 3, h = blockIdx.y & 7;
    int q0 = blockIdx.x * 128;
    int qr = wid * 16;
    const float SQ = 9.79795897113271239f;

    long baseQ = (long)(b * NN + q0) * QKVC + h * HD;
    ldtile128(sb + FQ, qkvh, baseQ, tid);
    ldtile128(sb + FQ + 26624, qkvl, baseQ, tid);
    CPCOMMIT();
    long baseK = (long)(b * NN) * QKVC + DIM + h * HD;
    ldtile64(sb + FST(0), qkvh, baseK, tid);
    ldtile64(sb + FST(0) + 13312, qkvh, baseK + DIM, tid);
    CPCOMMIT();

    float acco[12][4];
    #pragma unroll
    for (int g = 0; g < 12; g++)
        #pragma unroll
        for (int c = 0; c < 4; c++) acco[g][c] = 0.f;
    float m0 = -1e30f, m1 = -1e30f, l0 = 0.f, l1 = 0.f;

    for (int kt = 0; kt < 16; kt++) {
        int st = kt & 1;
        if (kt < 15) {
            long bk = (long)(b * NN + (kt + 1) * 64) * QKVC + DIM + h * HD;
            ldtile64(sb + FST(st ^ 1), qkvh, bk, tid);
            ldtile64(sb + FST(st ^ 1) + 13312, qkvh, bk + DIM, tid);
            CPCOMMIT();
            CPWAIT1();
        } else {
            CPWAIT0();
        }
        __syncthreads();

        float accs[8][4];
        #pragma unroll
        for (int g = 0; g < 8; g++)
            #pragma unroll
            for (int c = 0; c < 4; c++) accs[g][c] = 0.f;
        uint32_t qb = sb + FQ, kbase = sb + FST(st);

        #pragma unroll
        for (int kc = 0; kc < 6; kc++) {
            uint32_t ah[4], al[4];
            uint32_t ad = qb + ((qr + (lane & 15)) * 104 + kc * 16 + (lane >> 4) * 8) * 2;
            LDSM4(ah, ad);
            LDSM4(al, ad + 26624);
            #pragma unroll
            for (int ni = 0; ni < 4; ni++) {
                uint32_t bh[4];
                uint32_t bd = kbase + ((ni * 16 + (lane & 7) + ((lane >> 4) << 3)) * 104 +
                                       kc * 16 + (((lane >> 3) & 1) << 3)) * 2;
                LDSM4(bh, bd);
                MMA(accs[2 * ni], ah, bh[0], bh[1]);
                MMA(accs[2 * ni + 1], ah, bh[2], bh[3]);
                MMA(accs[2 * ni], al, bh[0], bh[1]);
                MMA(accs[2 * ni + 1], al, bh[2], bh[3]);
            }
        }

        float mx0 = -1e30f, mx1 = -1e30f;
        #pragma unroll
        for (int g = 0; g < 8; g++) {
            mx0 = fmaxf(mx0, fmaxf(accs[g][0], accs[g][1]));
            mx1 = fmaxf(mx1, fmaxf(accs[g][2], accs[g][3]));
        }
        mx0 = fmaxf(mx0, __shfl_xor_sync(~0u, mx0, 1));
        mx0 = fmaxf(mx0, __shfl_xor_sync(~0u, mx0, 2));
        mx1 = fmaxf(mx1, __shfl_xor_sync(~0u, mx1, 1));
        mx1 = fmaxf(mx1, __shfl_xor_sync(~0u, mx1, 2));
        float mn0 = fmaxf(m0, mx0 * SQ), mn1 = fmaxf(m1, mx1 * SQ);
        float cr0 = __expf(m0 - mn0), cr1 = __expf(m1 - mn1);
        m0 = mn0; m1 = mn1;
        #pragma unroll
        for (int g = 0; g < 12; g++) {
            acco[g][0] *= cr0; acco[g][1] *= cr0;
            acco[g][2] *= cr1; acco[g][3] *= cr1;
        }

        float rs0 = 0.f, rs1 = 0.f;
        uint32_t vb0 = kbase + 13312;
        #pragma unroll
        for (int kb2 = 0; kb2 < 4; kb2++) {
            float p00 = __expf(fmaf(SQ, accs[2 * kb2][0], -mn0));
            float p01 = __expf(fmaf(SQ, accs[2 * kb2][1], -mn0));
            float p02 = __expf(fmaf(SQ, accs[2 * kb2][2], -mn1));
            float p03 = __expf(fmaf(SQ, accs[2 * kb2][3], -mn1));
            float p10 = __expf(fmaf(SQ, accs[2 * kb2 + 1][0], -mn0));
            float p11 = __expf(fmaf(SQ, accs[2 * kb2 + 1][1], -mn0));
            float p12 = __expf(fmaf(SQ, accs[2 * kb2 + 1][2], -mn1));
            float p13 = __expf(fmaf(SQ, accs[2 * kb2 + 1][3], -mn1));
            rs0 += p00 + p01 + p10 + p11;
            rs1 += p02 + p03 + p12 + p13;
            uint32_t pa[4];
            __half2 t;
            t = __floats2half2_rn(p00, p01); pa[0] = *(uint32_t*)&t;
            t = __floats2half2_rn(p02, p03); pa[1] = *(uint32_t*)&t;
            t = __floats2half2_rn(p10, p11); pa[2] = *(uint32_t*)&t;
            t = __floats2half2_rn(p12, p13); pa[3] = *(uint32_t*)&t;
            #pragma unroll
            for (int nj = 0; nj < 6; nj++) {
                uint32_t vb[4];
                uint32_t vd = vb0 + ((kb2 * 16 + (lane & 15)) * 104 +
                                     nj * 16 + ((lane >> 4) << 3)) * 2;
                LDSM4T(vb, vd);
                MMA(acco[2 * nj], pa, vb[0], vb[1]);
                MMA(acco[2 * nj + 1], pa, vb[2], vb[3]);
            }
        }
        rs0 += __shfl_xor_sync(~0u, rs0, 1);
        rs0 += __shfl_xor_sync(~0u, rs0, 2);
        rs1 += __shfl_xor_sync(~0u, rs1, 1);
        rs1 += __shfl_xor_sync(~0u, rs1, 2);
        l0 = l0 * cr0 + rs0;
        l1 = l1 * cr1 + rs1;
        __syncthreads();
    }

    float rl0 = 1.f / l0, rl1 = 1.f / l1;
    long ob = (long)(b * NN + q0 + qr + (lane >> 2)) * DIM + h * HD + (lane & 3) * 2;
    #pragma unroll
    for (int g = 0; g < 12; g++) {
        *(__half2*)(att + ob + g * 8) =
            __floats2half2_rn(acco[g][0] * rl0, acco[g][1] * rl0);
        *(__half2*)(att + ob + 8 * DIM + g * 8) =
            __floats2half2_rn(acco[g][2] * rl1, acco[g][3] * rl1);
    }
}

// ------------------------------- launch --------------------------------------
extern "C" void kernel_launch(void* const* d_in, const int* in_sizes, int n_in,
                              void* d_out, int out_size) {
    const float* x    = (const float*)d_in[0];
    const float* ln_g = (const float*)d_in[1];
    const float* ln_b = (const float*)d_in[2];
    const float* Wqkv = (const float*)d_in[3];
    const float* bqkv = (const float*)d_in[4];
    const float* W0   = (const float*)d_in[5];
    const float* b0   = (const float*)d_in[6];
    const float* W1   = (const float*)d_in[7];
    const float* b1   = (const float*)d_in[8];
    const float* W2   = (const float*)d_in[9];
    const float* b2   = (const float*)d_in[10];
    float* out = (float*)d_out;

    cudaFuncSetAttribute(hgemmqkv, cudaFuncAttributeMaxDynamicSharedMemorySize, 2 * STGQB);
    cudaFuncSetAttribute(hgemm1, cudaFuncAttributeMaxDynamicSharedMemorySize, SM1);
    cudaFuncSetAttribute(flash_kernel, cudaFuncAttributeMaxDynamicSharedMemorySize, FL_SMEM);

    __half *yh, *yl, *wqh, *qkvh, *qkvl, *att, *l2, *w0, *w1, *w2, *hb;
    float *z, *b1p;
    cudaGetSymbolAddress((void**)&yh, g_yh);   cudaGetSymbolAddress((void**)&yl, g_yl);
    cudaGetSymbolAddress((void**)&wqh, g_wqh);
    cudaGetSymbolAddress((void**)&qkvh, g_qkvh); cudaGetSymbolAddress((void**)&qkvl, g_qkvl);
    cudaGetSymbolAddress((void**)&att, g_att);
    cudaGetSymbolAddress((void**)&z, g_z);
    cudaGetSymbolAddress((void**)&l2, g_l2);
    cudaGetSymbolAddress((void**)&w0, g_w0);
    cudaGetSymbolAddress((void**)&w1, g_w1);
    cudaGetSymbolAddress((void**)&w2, g_w2);
    cudaGetSymbolAddress((void**)&hb, g_h);
    cudaGetSymbolAddress((void**)&b1p, g_b1p);

    split4_kernel<<<SEG0 + SEG1 + SEG2 + SEG3 + SEG4, 256>>>(
        Wqkv, wqh, W0, w0, W1, w1, W2, w2, b1, b1p);
    ln_split_kernel<<<ROWS, 256>>>(x, ln_g, ln_b, yh, yl);
    // QKV in ONE launch: cols [0,1536) 2-product (Q,K), cols [1536,2304) 1-product (V)
    hgemmqkv<<<dim3(18, 64), 256, 2 * STGQB>>>(
        yh, yl, DIM, wqh, QKVC, qkvh, qkvl, QKVC, bqkv, 12, 12);
    flash_kernel<<<dim3(8, 64), 256, FL_SMEM>>>(qkvh, qkvl, att);
    // z = att @ W0 + b0 + x
    hgemm1<<<dim3(6, 64), 256, SM1>>>(
        att, DIM, w0, DIM, z, nullptr, DIM, b0, x, 12, 0);
    ln_split_kernel<<<ROWS, 256>>>(z, ln_g, ln_b, l2, nullptr);
    // h = gelu(l2 @ W1 + b1)
    hgemm1<<<dim3(12, 64), 256, SM1>>>(
        l2, DIM, w1, HPAD, nullptr, hb, HPAD, b1p, nullptr, 12, 1);
    // out = h @ W2 + b2 + z
    hgemm1<<<dim3(6, 64), 256, SM1>>>(
        hb, HPAD, w2, DIM, out, nullptr, DIM, b2, z, 24, 0);
}